// round 7
// baseline (speedup 1.0000x reference)
#include <cuda_runtime.h>
#include <cuda_bf16.h>
#include <math.h>
#include <stdint.h>

// Problem constants
#define BB 2
#define TT 1024
#define DD 1024
#define HH 16
#define LL 6
#define DHH 64
#define DFFF 2048
#define MROWS (BB*TT)   // 2048
#define D3 (3*DD)

// ---------------- scratch (device globals) ----------------------------------
__device__ float g_x[MROWS * DD];                                   // residual
__device__ __nv_bfloat16 g_h_hi[MROWS*DD],    g_h_lo[MROWS*DD];     // LN out
__device__ __nv_bfloat16 g_qkv_hi[MROWS*D3],  g_qkv_lo[MROWS*D3];   // qkv
__device__ __nv_bfloat16 g_o_hi[MROWS*DD],    g_o_lo[MROWS*DD];     // attn out
__device__ __nv_bfloat16 g_a_hi[MROWS*DFFF],  g_a_lo[MROWS*DFFF];   // gelu out
__device__ __nv_bfloat16 g_WqkvT_hi[LL*D3*DD],   g_WqkvT_lo[LL*D3*DD];
__device__ __nv_bfloat16 g_WoutT_hi[LL*DD*DD],   g_WoutT_lo[LL*DD*DD];
__device__ __nv_bfloat16 g_W1T_hi [LL*DFFF*DD],  g_W1T_lo [LL*DFFF*DD];
__device__ __nv_bfloat16 g_W2T_hi [LL*DD*DFFF],  g_W2T_lo [LL*DD*DFFF];

// ================= helpers =================
__device__ __forceinline__ uint32_t smem_u32(const void* p){
    uint32_t a;
    asm("{ .reg .u64 t; cvta.to.shared.u64 t, %1; cvt.u32.u64 %0, t; }"
        : "=r"(a) : "l"(p));
    return a;
}
__device__ __forceinline__ void ldsm_x4(uint32_t a, uint32_t& r0, uint32_t& r1,
                                        uint32_t& r2, uint32_t& r3){
    asm volatile("ldmatrix.sync.aligned.m8n8.x4.shared.b16 {%0,%1,%2,%3}, [%4];"
                 : "=r"(r0), "=r"(r1), "=r"(r2), "=r"(r3) : "r"(a));
}
__device__ __forceinline__ void ldsm_x2(uint32_t a, uint32_t& r0, uint32_t& r1){
    asm volatile("ldmatrix.sync.aligned.m8n8.x2.shared.b16 {%0,%1}, [%2];"
                 : "=r"(r0), "=r"(r1) : "r"(a));
}
__device__ __forceinline__ void ldsm_x2t(uint32_t a, uint32_t& r0, uint32_t& r1){
    asm volatile("ldmatrix.sync.aligned.m8n8.x2.trans.shared.b16 {%0,%1}, [%2];"
                 : "=r"(r0), "=r"(r1) : "r"(a));
}
__device__ __forceinline__ void mma_bf16(float* c, const uint32_t* a,
                                         const uint32_t* b){
    asm volatile(
        "mma.sync.aligned.m16n8k16.row.col.f32.bf16.bf16.f32 "
        "{%0,%1,%2,%3}, {%4,%5,%6,%7}, {%8,%9}, {%0,%1,%2,%3};"
        : "+f"(c[0]), "+f"(c[1]), "+f"(c[2]), "+f"(c[3])
        : "r"(a[0]), "r"(a[1]), "r"(a[2]), "r"(a[3]), "r"(b[0]), "r"(b[1]));
}
__device__ __forceinline__ void cp16(uint32_t dst, const void* src){
    asm volatile("cp.async.cg.shared.global [%0], [%1], 16;"
                 :: "r"(dst), "l"(src));
}
#define CP_COMMIT() asm volatile("cp.async.commit_group;" ::: "memory")
#define CP_WAIT1()  asm volatile("cp.async.wait_group 1;" ::: "memory")
#define CP_WAIT0()  asm volatile("cp.async.wait_group 0;" ::: "memory")

__device__ __forceinline__ uint32_t pack_bf2(float lo_val, float hi_val){
    __nv_bfloat162 t = __floats2bfloat162_rn(lo_val, hi_val);
    return *(uint32_t*)&t;
}
__device__ __forceinline__ void split_bf(float v, float& hi_f, float& lo_f){
    __nv_bfloat16 h = __float2bfloat16(v);
    hi_f = __bfloat162float(h);
    lo_f = v - hi_f;
}

// ---------------- embedding -------------------------------------------------
__global__ void embed_kernel(const int* __restrict__ ids,
                             const float* __restrict__ tok,
                             const float* __restrict__ pos,
                             float* __restrict__ x)
{
    int idx = blockIdx.x * blockDim.x + threadIdx.x;
    if (idx >= MROWS * DD) return;
    int d  = idx & (DD - 1);
    int bt = idx / DD;
    int t  = bt & (TT - 1);
    x[idx] = tok[(size_t)ids[bt] * DD + d] + pos[t * DD + d];
}

// ---------------- weight transpose + bf16 hi/lo split (batched over L) ------
__global__ void twk(const float* __restrict__ W,
                    __nv_bfloat16* __restrict__ hi,
                    __nv_bfloat16* __restrict__ lo, int K, int N)
{
    __shared__ float t[32][33];
    size_t loff = (size_t)blockIdx.z * K * N;
    const float* Wl = W + loff;
    __nv_bfloat16* hil = hi + loff;
    __nv_bfloat16* lol = lo + loff;

    int n0 = blockIdx.x * 32, k0 = blockIdx.y * 32;
    int tx = threadIdx.x, ty = threadIdx.y;   // 32 x 8
    #pragma unroll
    for (int i = 0; i < 32; i += 8)
        t[ty + i][tx] = Wl[(size_t)(k0 + ty + i) * N + n0 + tx];
    __syncthreads();
    #pragma unroll
    for (int i = 0; i < 32; i += 8) {
        float v = t[tx][ty + i];
        __nv_bfloat16 h = __float2bfloat16(v);
        size_t o = (size_t)(n0 + ty + i) * K + k0 + tx;
        hil[o] = h;
        lol[o] = __float2bfloat16(v - __bfloat162float(h));
    }
}

// ---------------- layernorm (biased var, eps 1e-5) --------------------------
template<bool BF>
__global__ void ln_kernel(const float* __restrict__ x,
                          const float* __restrict__ s,
                          const float* __restrict__ b,
                          float* __restrict__ y,
                          __nv_bfloat16* __restrict__ yhi,
                          __nv_bfloat16* __restrict__ ylo)
{
    int row = blockIdx.x;
    const float* xr = x + (size_t)row * DD;

    float sum = 0.f, sq = 0.f;
    int c4 = threadIdx.x;
    float4 v = ((const float4*)xr)[c4];
    sum = v.x + v.y + v.z + v.w;
    sq  = v.x*v.x + v.y*v.y + v.z*v.z + v.w*v.w;

    __shared__ float rs[8], rq[8];
    for (int o = 16; o > 0; o >>= 1) {
        sum += __shfl_xor_sync(0xffffffffu, sum, o);
        sq  += __shfl_xor_sync(0xffffffffu, sq,  o);
    }
    int wid = threadIdx.x >> 5;
    if ((threadIdx.x & 31) == 0) { rs[wid] = sum; rq[wid] = sq; }
    __syncthreads();
    if (threadIdx.x < 8) { sum = rs[threadIdx.x]; sq = rq[threadIdx.x]; }
    else                 { sum = 0.f; sq = 0.f; }
    if (threadIdx.x < 32) {
        for (int o = 4; o > 0; o >>= 1) {
            sum += __shfl_xor_sync(0xffffffffu, sum, o);
            sq  += __shfl_xor_sync(0xffffffffu, sq,  o);
        }
    }
    __shared__ float s_mean, s_inv;
    if (threadIdx.x == 0) {
        float mean = sum * (1.f / DD);
        float var  = sq * (1.f / DD) - mean * mean;
        s_mean = mean;
        s_inv  = rsqrtf(var + 1e-5f);
    }
    __syncthreads();
    float mean = s_mean, inv = s_inv;

    float4 sv = ((const float4*)s)[c4];
    float4 bv = ((const float4*)b)[c4];
    float ov[4];
    ov[0] = (v.x - mean) * inv * sv.x + bv.x;
    ov[1] = (v.y - mean) * inv * sv.y + bv.y;
    ov[2] = (v.z - mean) * inv * sv.z + bv.z;
    ov[3] = (v.w - mean) * inv * sv.w + bv.w;
    if (BF) {
        size_t base = (size_t)row * DD + c4 * 4;
        #pragma unroll
        for (int j = 0; j < 4; j += 2) {
            float h0, l0, h1, l1;
            split_bf(ov[j],     h0, l0);
            split_bf(ov[j + 1], h1, l1);
            *(uint32_t*)&yhi[base + j] = pack_bf2(h0, h1);
            *(uint32_t*)&ylo[base + j] = pack_bf2(l0, l1);
        }
    } else {
        float4 o4 = make_float4(ov[0], ov[1], ov[2], ov[3]);
        ((float4*)(y + (size_t)row * DD))[c4] = o4;
    }
}

// ================= mma.sync bf16 GEMM (512 threads, 16 warps) ================
// C[M,N] = epi( A @ B^T ), A=[M,K] hi/lo bf16, B=[N,K] hi/lo bf16
// EPI: 1 = X + acc -> fp32, 2 = GELU -> bf16 hi/lo, 3 = bf16 hi/lo
// 128x128 CTA tile, warp grid 4x4, warp tile 32x32.
#define TPITCH 80
#define TILE_B (128 * TPITCH)
#define STAGE_B (4 * TILE_B)
#define GSM_TOTAL (2 * STAGE_B)

__device__ __forceinline__ void fill_cp512(uint32_t dst, const __nv_bfloat16* g,
                                           int K, int tid)
{
    // 128 rows x 4 16B-chunks = 512 chunks, one per thread
    int r = tid >> 2, c = tid & 3;
    cp16(dst + r * TPITCH + c * 16,
         (const char*)g + (size_t)r * K * 2 + c * 16);
}

template<int EPI>
__global__ __launch_bounds__(512, 1) void gemm_mma(
    const __nv_bfloat16* __restrict__ Ahi, const __nv_bfloat16* __restrict__ Alo,
    const __nv_bfloat16* __restrict__ Bhi, const __nv_bfloat16* __restrict__ Blo,
    const float* __restrict__ X, float* __restrict__ C,
    __nv_bfloat16* __restrict__ Chi, __nv_bfloat16* __restrict__ Clo,
    int M, int N, int K)
{
    extern __shared__ char sm[];
    uint32_t sb = smem_u32(sm);
    int tid  = threadIdx.x;
    int lane = tid & 31, w = tid >> 5;
    int wm = (w >> 2) * 32, wn = (w & 3) * 32;
    int m0 = blockIdx.y * 128, n0 = blockIdx.x * 128;

    const __nv_bfloat16* pAhi = Ahi + (size_t)m0 * K;
    const __nv_bfloat16* pAlo = Alo + (size_t)m0 * K;
    const __nv_bfloat16* pBhi = Bhi + (size_t)n0 * K;
    const __nv_bfloat16* pBlo = Blo + (size_t)n0 * K;

    float acc[2][4][4] = {};
    int S = K >> 5;

    fill_cp512(sb,              pAhi, K, tid);
    fill_cp512(sb + TILE_B,     pAlo, K, tid);
    fill_cp512(sb + 2 * TILE_B, pBhi, K, tid);
    fill_cp512(sb + 3 * TILE_B, pBlo, K, tid);
    CP_COMMIT();

    // ldmatrix lane addressing (within-tile)
    uint32_t aRowOff = (uint32_t)(wm + (lane & 15)) * TPITCH;
    uint32_t aColSel = (uint32_t)(lane >> 4);                 // 0/1 chunk
    // B x4 over nt-pair: lanes 0-15 -> first n8 tile (k halves), 16-31 -> second
    uint32_t bRowOff = (uint32_t)(wn + ((lane >> 4) << 3) + (lane & 7)) * TPITCH;
    uint32_t bColSel = (uint32_t)((lane >> 3) & 1);

    for (int s = 0; s < S; s++) {
        uint32_t buf = sb + (s & 1) * STAGE_B;
        if (s + 1 < S) {
            uint32_t nbuf = sb + ((s + 1) & 1) * STAGE_B;
            int k0 = (s + 1) << 5;
            fill_cp512(nbuf,              pAhi + k0, K, tid);
            fill_cp512(nbuf + TILE_B,     pAlo + k0, K, tid);
            fill_cp512(nbuf + 2 * TILE_B, pBhi + k0, K, tid);
            fill_cp512(nbuf + 3 * TILE_B, pBlo + k0, K, tid);
            CP_COMMIT();
            CP_WAIT1();
        } else {
            CP_WAIT0();
        }
        __syncthreads();

        #pragma unroll
        for (int k16 = 0; k16 < 2; k16++) {
            uint32_t ah[2][4], al[2][4];
            #pragma unroll
            for (int mt = 0; mt < 2; mt++) {
                uint32_t off = aRowOff + (uint32_t)(mt * 16) * TPITCH +
                               (aColSel + k16 * 2) * 16;
                ldsm_x4(buf + off, ah[mt][0], ah[mt][1], ah[mt][2], ah[mt][3]);
                ldsm_x4(buf + TILE_B + off, al[mt][0], al[mt][1], al[mt][2], al[mt][3]);
            }
            uint32_t bh[4][2], bl[4][2];
            #pragma unroll
            for (int np = 0; np < 2; np++) {
                uint32_t off = bRowOff + (uint32_t)(np * 16) * TPITCH +
                               (bColSel + k16 * 2) * 16;
                ldsm_x4(buf + 2 * TILE_B + off,
                        bh[2*np][0], bh[2*np][1], bh[2*np+1][0], bh[2*np+1][1]);
                ldsm_x4(buf + 3 * TILE_B + off,
                        bl[2*np][0], bl[2*np][1], bl[2*np+1][0], bl[2*np+1][1]);
            }
            #pragma unroll
            for (int mt = 0; mt < 2; mt++)
                #pragma unroll
                for (int nt = 0; nt < 4; nt++) {
                    mma_bf16(acc[mt][nt], ah[mt], bh[nt]);
                    mma_bf16(acc[mt][nt], al[mt], bh[nt]);
                    mma_bf16(acc[mt][nt], ah[mt], bl[nt]);
                }
        }
        __syncthreads();
    }

    #pragma unroll
    for (int mt = 0; mt < 2; mt++) {
        #pragma unroll
        for (int nt = 0; nt < 4; nt++) {
            float* cc = acc[mt][nt];
            int gr = m0 + wm + mt * 16 + (lane >> 2);
            int gc = n0 + wn + nt * 8 + (lane & 3) * 2;
            #pragma unroll
            for (int half = 0; half < 2; half++) {
                size_t base = (size_t)(gr + half * 8) * N + gc;
                float v0 = cc[half * 2], v1 = cc[half * 2 + 1];
                if (EPI == 1) {
                    C[base]     = v0 + X[base];
                    C[base + 1] = v1 + X[base + 1];
                } else {
                    if (EPI == 2) {
                        v0 = 0.5f * v0 * (1.f + erff(v0 * 0.70710678118654752f));
                        v1 = 0.5f * v1 * (1.f + erff(v1 * 0.70710678118654752f));
                    }
                    float h0, l0, h1, l1;
                    split_bf(v0, h0, l0);
                    split_bf(v1, h1, l1);
                    *(uint32_t*)&Chi[base] = pack_bf2(h0, h1);
                    *(uint32_t*)&Clo[base] = pack_bf2(l0, l1);
                }
            }
        }
    }
}

// ================= tensor-core flash attention ==============================
// grid (16 qtiles, 32 bh), 128 threads; warp w owns q rows [w*16, w*16+16)
#define APITCH 144
#define ATILE (64 * APITCH)            // 9216 B per 64x64 bf16 tile
#define ASTAGE (4 * ATILE)             // Khi,Klo,Vhi,Vlo
#define ATTN_SMEM (2 * ATILE + 2 * ASTAGE)  // Q hi/lo + 2 stages = 92160

__device__ __forceinline__ void attn_fill(uint32_t dst,
                                          const __nv_bfloat16* ghi,
                                          const __nv_bfloat16* glo, int tid)
{
    #pragma unroll
    for (int i = 0; i < 8; i++) {
        int ch = tid + (i << 7);
        int r = (ch & 511) >> 3, c = ch & 7;
        const __nv_bfloat16* src = (ch < 512) ? ghi : glo;
        uint32_t d = dst + ((ch < 512) ? 0 : ATILE) + r * APITCH + c * 16;
        cp16(d, (const char*)src + (size_t)r * D3 * 2 + c * 16);
    }
}

__global__ __launch_bounds__(128) void attn_mma(
    const __nv_bfloat16* __restrict__ qkv_hi,
    const __nv_bfloat16* __restrict__ qkv_lo,
    __nv_bfloat16* __restrict__ o_hi,
    __nv_bfloat16* __restrict__ o_lo)
{
    extern __shared__ char sm[];
    uint32_t sb = smem_u32(sm);
    int qt = blockIdx.x, bh = blockIdx.y;
    int b = bh >> 4, h = bh & 15;
    int tid = threadIdx.x, lane = tid & 31, w = tid >> 5;

    size_t qrow = (size_t)(b * TT + qt * 64);
    const __nv_bfloat16* gq_hi = qkv_hi + qrow * D3 + h * DHH;
    const __nv_bfloat16* gq_lo = qkv_lo + qrow * D3 + h * DHH;

    uint32_t sQ = sb;
    uint32_t sS0 = sb + 2 * ATILE;

    attn_fill(sQ, gq_hi, gq_lo, tid);
    {
        const __nv_bfloat16* gk_hi = qkv_hi + (size_t)(b * TT) * D3 + DD + h * DHH;
        const __nv_bfloat16* gk_lo = qkv_lo + (size_t)(b * TT) * D3 + DD + h * DHH;
        attn_fill(sS0,             gk_hi, gk_lo, tid);
        attn_fill(sS0 + 2 * ATILE, gk_hi + DD, gk_lo + DD, tid);
    }
    CP_COMMIT();
    CP_WAIT0();
    __syncthreads();

    uint32_t qh[4][4], ql[4][4];
    {
        uint32_t rowoff = (uint32_t)(w * 16 + (lane & 15)) * APITCH;
        uint32_t coloff = (uint32_t)(lane >> 4) * 16;
        #pragma unroll
        for (int kb = 0; kb < 4; kb++) {
            uint32_t off = rowoff + kb * 32 + coloff;
            ldsm_x4(sQ + off,         qh[kb][0], qh[kb][1], qh[kb][2], qh[kb][3]);
            ldsm_x4(sQ + ATILE + off, ql[kb][0], ql[kb][1], ql[kb][2], ql[kb][3]);
        }
    }

    float oacc[8][4] = {};
    float mrow[2] = {-1e30f, -1e30f};
    float lrow[2] = {0.f, 0.f};

    int r0loc = w * 16 + (lane >> 2);
    int r0g = qt * 64 + r0loc;
    int cql = (lane & 3) * 2;

    for (int jt = 0; jt <= qt; jt++) {
        uint32_t buf = sS0 + (jt & 1) * ASTAGE;
        if (jt + 1 <= qt) {
            uint32_t nbuf = sS0 + ((jt + 1) & 1) * ASTAGE;
            size_t krow = (size_t)(b * TT + (jt + 1) * 64);
            const __nv_bfloat16* gk_hi = qkv_hi + krow * D3 + DD + h * DHH;
            const __nv_bfloat16* gk_lo = qkv_lo + krow * D3 + DD + h * DHH;
            attn_fill(nbuf,             gk_hi, gk_lo, tid);
            attn_fill(nbuf + 2 * ATILE, gk_hi + DD, gk_lo + DD, tid);
            CP_COMMIT();
        }

        float s[8][4] = {};
        #pragma unroll
        for (int kb = 0; kb < 4; kb++) {
            uint32_t kcol = (uint32_t)(((lane >> 3) & 1) * 8 + kb * 16) * 2;
            #pragma unroll
            for (int nt = 0; nt < 8; nt++) {
                uint32_t off = (uint32_t)(nt * 8 + (lane & 7)) * APITCH + kcol;
                uint32_t kh0, kh1, kl0, kl1;
                ldsm_x2(buf + off, kh0, kh1);
                ldsm_x2(buf + ATILE + off, kl0, kl1);
                uint32_t bhK[2] = {kh0, kh1}, blK[2] = {kl0, kl1};
                mma_bf16(s[nt], qh[kb], bhK);
                mma_bf16(s[nt], ql[kb], bhK);
                mma_bf16(s[nt], qh[kb], blK);
            }
        }

        bool diag = (jt == qt);
        #pragma unroll
        for (int nt = 0; nt < 8; nt++) {
            int colb = jt * 64 + nt * 8 + cql;
            #pragma unroll
            for (int q = 0; q < 4; q++) {
                float v = s[nt][q] * 0.125f;
                if (diag) {
                    int col = colb + (q & 1);
                    int row = r0g + (q >> 1) * 8;
                    if (col > row) v = -1e30f;
                }
                s[nt][q] = v;
            }
        }

        float mx0 = -1e30f, mx1 = -1e30f;
        #pragma unroll
        for (int nt = 0; nt < 8; nt++) {
            mx0 = fmaxf(mx0, fmaxf(s[nt][0], s[nt][1]));
            mx1 = fmaxf(mx1, fmaxf(s[nt][2], s[nt][3]));
        }
        mx0 = fmaxf(mx0, __shfl_xor_sync(0xffffffffu, mx0, 1));
        mx0 = fmaxf(mx0, __shfl_xor_sync(0xffffffffu, mx0, 2));
        mx1 = fmaxf(mx1, __shfl_xor_sync(0xffffffffu, mx1, 1));
        mx1 = fmaxf(mx1, __shfl_xor_sync(0xffffffffu, mx1, 2));
        float mn0 = fmaxf(mrow[0], mx0), mn1 = fmaxf(mrow[1], mx1);
        float sum0 = 0.f, sum1 = 0.f;
        #pragma unroll
        for (int nt = 0; nt < 8; nt++) {
            s[nt][0] = __expf(s[nt][0] - mn0);
            s[nt][1] = __expf(s[nt][1] - mn0);
            s[nt][2] = __expf(s[nt][2] - mn1);
            s[nt][3] = __expf(s[nt][3] - mn1);
            sum0 += s[nt][0] + s[nt][1];
            sum1 += s[nt][2] + s[nt][3];
        }
        sum0 += __shfl_xor_sync(0xffffffffu, sum0, 1);
        sum0 += __shfl_xor_sync(0xffffffffu, sum0, 2);
        sum1 += __shfl_xor_sync(0xffffffffu, sum1, 1);
        sum1 += __shfl_xor_sync(0xffffffffu, sum1, 2);
        float a0 = __expf(mrow[0] - mn0), a1 = __expf(mrow[1] - mn1);
        lrow[0] = lrow[0] * a0 + sum0;
        lrow[1] = lrow[1] * a1 + sum1;
        mrow[0] = mn0; mrow[1] = mn1;
        #pragma unroll
        for (int nt = 0; nt < 8; nt++) {
            oacc[nt][0] *= a0; oacc[nt][1] *= a0;
            oacc[nt][2] *= a1; oacc[nt][3] *= a1;
        }

        uint32_t vbase = buf + 2 * ATILE;
        #pragma unroll
        for (int kb = 0; kb < 4; kb++) {
            uint32_t ph[4], pl[4];
            {
                float h0, l0, h1, l1;
                split_bf(s[2*kb][0], h0, l0); split_bf(s[2*kb][1], h1, l1);
                ph[0] = pack_bf2(h0, h1); pl[0] = pack_bf2(l0, l1);
                split_bf(s[2*kb][2], h0, l0); split_bf(s[2*kb][3], h1, l1);
                ph[1] = pack_bf2(h0, h1); pl[1] = pack_bf2(l0, l1);
                split_bf(s[2*kb+1][0], h0, l0); split_bf(s[2*kb+1][1], h1, l1);
                ph[2] = pack_bf2(h0, h1); pl[2] = pack_bf2(l0, l1);
                split_bf(s[2*kb+1][2], h0, l0); split_bf(s[2*kb+1][3], h1, l1);
                ph[3] = pack_bf2(h0, h1); pl[3] = pack_bf2(l0, l1);
            }
            uint32_t vrow = (uint32_t)(kb * 16 + (lane & 15)) * APITCH;
            #pragma unroll
            for (int nt = 0; nt < 8; nt++) {
                uint32_t off = vrow + nt * 16;
                uint32_t vh0, vh1, vl0, vl1;
                ldsm_x2t(vbase + off, vh0, vh1);
                ldsm_x2t(vbase + ATILE + off, vl0, vl1);
                uint32_t bhV[2] = {vh0, vh1}, blV[2] = {vl0, vl1};
                mma_bf16(oacc[nt], ph, bhV);
                mma_bf16(oacc[nt], pl, bhV);
                mma_bf16(oacc[nt], ph, blV);
            }
        }

        CP_WAIT0();
        __syncthreads();
    }

    float li0 = 1.f / lrow[0], li1 = 1.f / lrow[1];
    size_t orow0 = (size_t)(b * TT + r0g) * DD + h * DHH;
    #pragma unroll
    for (int nt = 0; nt < 8; nt++) {
        int gc = nt * 8 + cql;
        float v0 = oacc[nt][0] * li0, v1 = oacc[nt][1] * li0;
        float v2 = oacc[nt][2] * li1, v3 = oacc[nt][3] * li1;
        float h0, l0, h1, l1;
        split_bf(v0, h0, l0); split_bf(v1, h1, l1);
        *(uint32_t*)&o_hi[orow0 + gc] = pack_bf2(h0, h1);
        *(uint32_t*)&o_lo[orow0 + gc] = pack_bf2(l0, l1);
        split_bf(v2, h0, l0); split_bf(v3, h1, l1);
        *(uint32_t*)&o_hi[orow0 + 8 * DD + gc] = pack_bf2(h0, h1);
        *(uint32_t*)&o_lo[orow0 + 8 * DD + gc] = pack_bf2(l0, l1);
    }
}

// ---------------- launcher ---------------------------------------------------
extern "C" void kernel_launch(void* const* d_in, const int* in_sizes, int n_in,
                              void* d_out, int out_size)
{
    const int*   ids  = (const int*)  d_in[0];
    const float* tok  = (const float*)d_in[1];
    const float* pos  = (const float*)d_in[2];
    const float* ln1s = (const float*)d_in[3];
    const float* ln1b = (const float*)d_in[4];
    const float* Wqkv = (const float*)d_in[5];
    const float* Wout = (const float*)d_in[6];
    const float* ln2s = (const float*)d_in[7];
    const float* ln2b = (const float*)d_in[8];
    const float* W1   = (const float*)d_in[9];
    const float* W2   = (const float*)d_in[10];
    const float* lnfs = (const float*)d_in[11];
    const float* lnfb = (const float*)d_in[12];
    float* out = (float*)d_out;

    float *x;
    __nv_bfloat16 *h_hi, *h_lo, *qkv_hi, *qkv_lo, *o_hi, *o_lo, *a_hi, *a_lo;
    __nv_bfloat16 *wqT_hi, *wqT_lo, *woT_hi, *woT_lo, *w1T_hi, *w1T_lo, *w2T_hi, *w2T_lo;
    cudaGetSymbolAddress((void**)&x,      g_x);
    cudaGetSymbolAddress((void**)&h_hi,   g_h_hi);
    cudaGetSymbolAddress((void**)&h_lo,   g_h_lo);
    cudaGetSymbolAddress((void**)&qkv_hi, g_qkv_hi);
    cudaGetSymbolAddress((void**)&qkv_lo, g_qkv_lo);
    cudaGetSymbolAddress((void**)&o_hi,   g_o_hi);
    cudaGetSymbolAddress((void**)&o_lo,   g_o_lo);
    cudaGetSymbolAddress((void**)&a_hi,   g_a_hi);
    cudaGetSymbolAddress((void**)&a_lo,   g_a_lo);
    cudaGetSymbolAddress((void**)&wqT_hi, g_WqkvT_hi);
    cudaGetSymbolAddress((void**)&wqT_lo, g_WqkvT_lo);
    cudaGetSymbolAddress((void**)&woT_hi, g_WoutT_hi);
    cudaGetSymbolAddress((void**)&woT_lo, g_WoutT_lo);
    cudaGetSymbolAddress((void**)&w1T_hi, g_W1T_hi);
    cudaGetSymbolAddress((void**)&w1T_lo, g_W1T_lo);
    cudaGetSymbolAddress((void**)&w2T_hi, g_W2T_hi);
    cudaGetSymbolAddress((void**)&w2T_lo, g_W2T_lo);

    cudaFuncSetAttribute(attn_mma,
                         cudaFuncAttributeMaxDynamicSharedMemorySize, ATTN_SMEM);
    cudaFuncSetAttribute(gemm_mma<1>,
                         cudaFuncAttributeMaxDynamicSharedMemorySize, GSM_TOTAL);
    cudaFuncSetAttribute(gemm_mma<2>,
                         cudaFuncAttributeMaxDynamicSharedMemorySize, GSM_TOTAL);
    cudaFuncSetAttribute(gemm_mma<3>,
                         cudaFuncAttributeMaxDynamicSharedMemorySize, GSM_TOTAL);

    // weight transpose + bf16 split, batched over all layers (4 launches)
    dim3 tb(32, 8);
    twk<<<dim3(D3 / 32, DD / 32, LL), tb>>>(Wqkv, wqT_hi, wqT_lo, DD, D3);
    twk<<<dim3(DD / 32, DD / 32, LL), tb>>>(Wout, woT_hi, woT_lo, DD, DD);
    twk<<<dim3(DFFF / 32, DD / 32, LL), tb>>>(W1, w1T_hi, w1T_lo, DD, DFFF);
    twk<<<dim3(DD / 32, DFFF / 32, LL), tb>>>(W2, w2T_hi, w2T_lo, DFFF, DD);

    embed_kernel<<<(MROWS * DD + 255) / 256, 256>>>(ids, tok, pos, x);

    for (int l = 0; l < LL; l++) {
        ln_kernel<true><<<MROWS, 256>>>(x, ln1s + (size_t)l * DD, ln1b + (size_t)l * DD,
                                        nullptr, h_hi, h_lo);
        gemm_mma<3><<<dim3(D3 / 128, MROWS / 128), 512, GSM_TOTAL>>>(
            h_hi, h_lo,
            wqT_hi + (size_t)l * D3 * DD, wqT_lo + (size_t)l * D3 * DD,
            nullptr, nullptr, qkv_hi, qkv_lo, MROWS, D3, DD);
        attn_mma<<<dim3(TT / 64, BB * HH), 128, ATTN_SMEM>>>(qkv_hi, qkv_lo, o_hi, o_lo);
        gemm_mma<1><<<dim3(DD / 128, MROWS / 128), 512, GSM_TOTAL>>>(
            o_hi, o_lo,
            woT_hi + (size_t)l * DD * DD, woT_lo + (size_t)l * DD * DD,
            x, x, nullptr, nullptr, MROWS, DD, DD);
        ln_kernel<true><<<MROWS, 256>>>(x, ln2s + (size_t)l * DD, ln2b + (size_t)l * DD,
                                        nullptr, h_hi, h_lo);
        gemm_mma<2><<<dim3(DFFF / 128, MROWS / 128), 512, GSM_TOTAL>>>(
            h_hi, h_lo,
            w1T_hi + (size_t)l * DFFF * DD, w1T_lo + (size_t)l * DFFF * DD,
            nullptr, nullptr, a_hi, a_lo, MROWS, DFFF, DD);
        gemm_mma<1><<<dim3(DD / 128, MROWS / 128), 512, GSM_TOTAL>>>(
            a_hi, a_lo,
            w2T_hi + (size_t)l * DD * DFFF, w2T_lo + (size_t)l * DD * DFFF,
            x, x, nullptr, nullptr, MROWS, DD, DFFF);
    }

    ln_kernel<false><<<MROWS, 256>>>(x, lnfs, lnfb, out, nullptr, nullptr);
}

// round 8
// speedup vs baseline: 1.2814x; 1.2814x over previous
#include <cuda_runtime.h>
#include <cuda_fp16.h>
#include <math.h>
#include <stdint.h>

// Problem constants
#define BB 2
#define TT 1024
#define DD 1024
#define HH 16
#define LL 6
#define DHH 64
#define DFFF 2048
#define MROWS (BB*TT)   // 2048
#define D3 (3*DD)

// ---------------- scratch (device globals) ----------------------------------
__device__ float g_x[MROWS * DD];                              // residual
__device__ __half g_h_hi[MROWS*DD],    g_h_lo[MROWS*DD];       // LN out
__device__ __half g_qkv_hi[MROWS*D3],  g_qkv_lo[MROWS*D3];     // qkv
__device__ __half g_o_hi[MROWS*DD],    g_o_lo[MROWS*DD];       // attn out
__device__ __half g_a_hi[MROWS*DFFF],  g_a_lo[MROWS*DFFF];     // gelu out
// transposed [N,K] fp16 weights (hi only - B side of GEMMs)
__device__ __half g_WqkvT[LL*D3*DD];
__device__ __half g_WoutT[LL*DD*DD];
__device__ __half g_W1T [LL*DFFF*DD];
__device__ __half g_W2T [LL*DD*DFFF];

// ================= helpers =================
__device__ __forceinline__ uint32_t smem_u32(const void* p){
    uint32_t a;
    asm("{ .reg .u64 t; cvta.to.shared.u64 t, %1; cvt.u32.u64 %0, t; }"
        : "=r"(a) : "l"(p));
    return a;
}
__device__ __forceinline__ void ldsm_x4(uint32_t a, uint32_t& r0, uint32_t& r1,
                                        uint32_t& r2, uint32_t& r3){
    asm volatile("ldmatrix.sync.aligned.m8n8.x4.shared.b16 {%0,%1,%2,%3}, [%4];"
                 : "=r"(r0), "=r"(r1), "=r"(r2), "=r"(r3) : "r"(a));
}
__device__ __forceinline__ void ldsm_x2(uint32_t a, uint32_t& r0, uint32_t& r1){
    asm volatile("ldmatrix.sync.aligned.m8n8.x2.shared.b16 {%0,%1}, [%2];"
                 : "=r"(r0), "=r"(r1) : "r"(a));
}
__device__ __forceinline__ void ldsm_x2t(uint32_t a, uint32_t& r0, uint32_t& r1){
    asm volatile("ldmatrix.sync.aligned.m8n8.x2.trans.shared.b16 {%0,%1}, [%2];"
                 : "=r"(r0), "=r"(r1) : "r"(a));
}
__device__ __forceinline__ void mma_f16(float* c, const uint32_t* a,
                                        const uint32_t* b){
    asm volatile(
        "mma.sync.aligned.m16n8k16.row.col.f32.f16.f16.f32 "
        "{%0,%1,%2,%3}, {%4,%5,%6,%7}, {%8,%9}, {%0,%1,%2,%3};"
        : "+f"(c[0]), "+f"(c[1]), "+f"(c[2]), "+f"(c[3])
        : "r"(a[0]), "r"(a[1]), "r"(a[2]), "r"(a[3]), "r"(b[0]), "r"(b[1]));
}
__device__ __forceinline__ void cp16(uint32_t dst, const void* src){
    asm volatile("cp.async.cg.shared.global [%0], [%1], 16;"
                 :: "r"(dst), "l"(src));
}
#define CP_COMMIT() asm volatile("cp.async.commit_group;" ::: "memory")
#define CP_WAIT1()  asm volatile("cp.async.wait_group 1;" ::: "memory")
#define CP_WAIT0()  asm volatile("cp.async.wait_group 0;" ::: "memory")

__device__ __forceinline__ uint32_t pack_h2(float lo_val, float hi_val){
    __half2 t = __floats2half2_rn(lo_val, hi_val);
    return *(uint32_t*)&t;
}
__device__ __forceinline__ void split_h(float v, float& hi_f, float& lo_f){
    __half h = __float2half_rn(v);
    hi_f = __half2float(h);
    lo_f = v - hi_f;
}

// ---------------- embedding -------------------------------------------------
__global__ void embed_kernel(const int* __restrict__ ids,
                             const float* __restrict__ tok,
                             const float* __restrict__ pos,
                             float* __restrict__ x)
{
    int idx = blockIdx.x * blockDim.x + threadIdx.x;
    if (idx >= MROWS * DD) return;
    int d  = idx & (DD - 1);
    int bt = idx / DD;
    int t  = bt & (TT - 1);
    x[idx] = tok[(size_t)ids[bt] * DD + d] + pos[t * DD + d];
}

// ---------------- weight transpose + fp16 convert (batched over L) ----------
__global__ void twk(const float* __restrict__ W,
                    __half* __restrict__ hi, int K, int N)
{
    __shared__ float t[32][33];
    size_t loff = (size_t)blockIdx.z * K * N;
    const float* Wl = W + loff;
    __half* hil = hi + loff;

    int n0 = blockIdx.x * 32, k0 = blockIdx.y * 32;
    int tx = threadIdx.x, ty = threadIdx.y;   // 32 x 8
    #pragma unroll
    for (int i = 0; i < 32; i += 8)
        t[ty + i][tx] = Wl[(size_t)(k0 + ty + i) * N + n0 + tx];
    __syncthreads();
    #pragma unroll
    for (int i = 0; i < 32; i += 8) {
        float v = t[tx][ty + i];
        hil[(size_t)(n0 + ty + i) * K + k0 + tx] = __float2half_rn(v);
    }
}

// ---------------- layernorm (biased var, eps 1e-5) --------------------------
template<bool HF>
__global__ void ln_kernel(const float* __restrict__ x,
                          const float* __restrict__ s,
                          const float* __restrict__ b,
                          float* __restrict__ y,
                          __half* __restrict__ yhi,
                          __half* __restrict__ ylo)
{
    int row = blockIdx.x;
    const float* xr = x + (size_t)row * DD;

    float sum = 0.f, sq = 0.f;
    int c4 = threadIdx.x;
    float4 v = ((const float4*)xr)[c4];
    sum = v.x + v.y + v.z + v.w;
    sq  = v.x*v.x + v.y*v.y + v.z*v.z + v.w*v.w;

    __shared__ float rs[8], rq[8];
    for (int o = 16; o > 0; o >>= 1) {
        sum += __shfl_xor_sync(0xffffffffu, sum, o);
        sq  += __shfl_xor_sync(0xffffffffu, sq,  o);
    }
    int wid = threadIdx.x >> 5;
    if ((threadIdx.x & 31) == 0) { rs[wid] = sum; rq[wid] = sq; }
    __syncthreads();
    if (threadIdx.x < 8) { sum = rs[threadIdx.x]; sq = rq[threadIdx.x]; }
    else                 { sum = 0.f; sq = 0.f; }
    if (threadIdx.x < 32) {
        for (int o = 4; o > 0; o >>= 1) {
            sum += __shfl_xor_sync(0xffffffffu, sum, o);
            sq  += __shfl_xor_sync(0xffffffffu, sq,  o);
        }
    }
    __shared__ float s_mean, s_inv;
    if (threadIdx.x == 0) {
        float mean = sum * (1.f / DD);
        float var  = sq * (1.f / DD) - mean * mean;
        s_mean = mean;
        s_inv  = rsqrtf(var + 1e-5f);
    }
    __syncthreads();
    float mean = s_mean, inv = s_inv;

    float4 sv = ((const float4*)s)[c4];
    float4 bv = ((const float4*)b)[c4];
    float ov[4];
    ov[0] = (v.x - mean) * inv * sv.x + bv.x;
    ov[1] = (v.y - mean) * inv * sv.y + bv.y;
    ov[2] = (v.z - mean) * inv * sv.z + bv.z;
    ov[3] = (v.w - mean) * inv * sv.w + bv.w;
    if (HF) {
        size_t base = (size_t)row * DD + c4 * 4;
        #pragma unroll
        for (int j = 0; j < 4; j += 2) {
            float h0, l0, h1, l1;
            split_h(ov[j],     h0, l0);
            split_h(ov[j + 1], h1, l1);
            *(uint32_t*)&yhi[base + j] = pack_h2(h0, h1);
            *(uint32_t*)&ylo[base + j] = pack_h2(l0, l1);
        }
    } else {
        float4 o4 = make_float4(ov[0], ov[1], ov[2], ov[3]);
        ((float4*)(y + (size_t)row * DD))[c4] = o4;
    }
}

// ================= mma.sync fp16 GEMM (256 threads, 8 warps) =================
// C[M,N] = epi( A @ B^T ), A=[M,K] hi/lo fp16, B=[N,K] fp16 (hi only)
// 2-term: Ah*B + Al*B. EPI: 1 = X+acc fp32, 2 = GELU -> fp16 hi/lo, 3 = fp16 hi/lo
#define TPITCH 80
#define TILE_B (128 * TPITCH)
#define STAGE_B (3 * TILE_B)         // Ahi, Alo, B
#define GSM_TOTAL (2 * STAGE_B)      // 61440

__device__ __forceinline__ void fill_cp(uint32_t dst, const __half* g,
                                        int K, int tid)
{
    // 128 rows x 4 16B-chunks = 512 chunks, 256 threads -> 2 each
    #pragma unroll
    for (int i = 0; i < 2; i++) {
        int ch = tid + (i << 8);
        int r = ch >> 2, c = ch & 3;
        cp16(dst + r * TPITCH + c * 16,
             (const char*)g + (size_t)r * K * 2 + c * 16);
    }
}

template<int EPI>
__global__ __launch_bounds__(256, 1) void gemm_mma(
    const __half* __restrict__ Ahi, const __half* __restrict__ Alo,
    const __half* __restrict__ B,
    const float* __restrict__ X, float* __restrict__ C,
    __half* __restrict__ Chi, __half* __restrict__ Clo,
    int M, int N, int K)
{
    extern __shared__ char sm[];
    uint32_t sb = smem_u32(sm);
    int tid  = threadIdx.x;
    int lane = tid & 31, w = tid >> 5;
    int wm = (w >> 2) * 64, wn = (w & 3) * 32;
    int m0 = blockIdx.y * 128, n0 = blockIdx.x * 128;

    const __half* pAhi = Ahi + (size_t)m0 * K;
    const __half* pAlo = Alo + (size_t)m0 * K;
    const __half* pB   = B   + (size_t)n0 * K;

    float acc[4][4][4] = {};
    int S = K >> 5;

    fill_cp(sb,              pAhi, K, tid);
    fill_cp(sb + TILE_B,     pAlo, K, tid);
    fill_cp(sb + 2 * TILE_B, pB,   K, tid);
    CP_COMMIT();

    int aRow = wm + (lane & 15);
    int aCol = (lane >> 4);
    int bRow = wn + (lane & 7);
    int bCol = ((lane >> 3) & 1);

    for (int s = 0; s < S; s++) {
        uint32_t buf = sb + (s & 1) * STAGE_B;
        if (s + 1 < S) {
            uint32_t nbuf = sb + ((s + 1) & 1) * STAGE_B;
            int k0 = (s + 1) << 5;
            fill_cp(nbuf,              pAhi + k0, K, tid);
            fill_cp(nbuf + TILE_B,     pAlo + k0, K, tid);
            fill_cp(nbuf + 2 * TILE_B, pB + k0,   K, tid);
            CP_COMMIT();
            CP_WAIT1();
        } else {
            CP_WAIT0();
        }
        __syncthreads();

        #pragma unroll
        for (int k16 = 0; k16 < 2; k16++) {
            uint32_t ah[4][4], al[4][4];
            #pragma unroll
            for (int mt = 0; mt < 4; mt++) {
                uint32_t off = (uint32_t)(aRow + mt * 16) * TPITCH +
                               (uint32_t)(aCol + k16 * 2) * 16;
                ldsm_x4(buf + off, ah[mt][0], ah[mt][1], ah[mt][2], ah[mt][3]);
                ldsm_x4(buf + TILE_B + off, al[mt][0], al[mt][1], al[mt][2], al[mt][3]);
            }
            uint32_t bh[4][2];
            #pragma unroll
            for (int nt = 0; nt < 4; nt++) {
                uint32_t off = (uint32_t)(bRow + nt * 8) * TPITCH +
                               (uint32_t)(bCol + k16 * 2) * 16;
                ldsm_x2(buf + 2 * TILE_B + off, bh[nt][0], bh[nt][1]);
            }
            #pragma unroll
            for (int mt = 0; mt < 4; mt++)
                #pragma unroll
                for (int nt = 0; nt < 4; nt++) {
                    mma_f16(acc[mt][nt], ah[mt], bh[nt]);
                    mma_f16(acc[mt][nt], al[mt], bh[nt]);
                }
        }
        __syncthreads();
    }

    #pragma unroll
    for (int mt = 0; mt < 4; mt++) {
        #pragma unroll
        for (int nt = 0; nt < 4; nt++) {
            float* cc = acc[mt][nt];
            int gr = m0 + wm + mt * 16 + (lane >> 2);
            int gc = n0 + wn + nt * 8 + (lane & 3) * 2;
            #pragma unroll
            for (int half = 0; half < 2; half++) {
                size_t base = (size_t)(gr + half * 8) * N + gc;
                float v0 = cc[half * 2], v1 = cc[half * 2 + 1];
                if (EPI == 1) {
                    C[base]     = v0 + X[base];
                    C[base + 1] = v1 + X[base + 1];
                } else {
                    if (EPI == 2) {
                        v0 = 0.5f * v0 * (1.f + erff(v0 * 0.70710678118654752f));
                        v1 = 0.5f * v1 * (1.f + erff(v1 * 0.70710678118654752f));
                    }
                    float h0, l0, h1, l1;
                    split_h(v0, h0, l0);
                    split_h(v1, h1, l1);
                    *(uint32_t*)&Chi[base] = pack_h2(h0, h1);
                    *(uint32_t*)&Clo[base] = pack_h2(l0, l1);
                }
            }
        }
    }
}

// ================= tensor-core flash attention (fp16, 3-term) ===============
// grid (16 qtiles, 32 bh), 128 threads; warp w owns q rows [w*16, w*16+16)
#define APITCH 144
#define ATILE (64 * APITCH)            // 9216 B per 64x64 fp16 tile
#define ASTAGE (4 * ATILE)             // Khi,Klo,Vhi,Vlo
#define ATTN_SMEM (2 * ATILE + 2 * ASTAGE)  // Q hi/lo + 2 stages = 92160

__device__ __forceinline__ void attn_fill(uint32_t dst,
                                          const __half* ghi,
                                          const __half* glo, int tid)
{
    #pragma unroll
    for (int i = 0; i < 8; i++) {
        int ch = tid + (i << 7);
        int r = (ch & 511) >> 3, c = ch & 7;
        const __half* src = (ch < 512) ? ghi : glo;
        uint32_t d = dst + ((ch < 512) ? 0 : ATILE) + r * APITCH + c * 16;
        cp16(d, (const char*)src + (size_t)r * D3 * 2 + c * 16);
    }
}

__global__ __launch_bounds__(128) void attn_mma(
    const __half* __restrict__ qkv_hi,
    const __half* __restrict__ qkv_lo,
    __half* __restrict__ o_hi,
    __half* __restrict__ o_lo)
{
    extern __shared__ char sm[];
    uint32_t sb = smem_u32(sm);
    int qt = blockIdx.x, bh = blockIdx.y;
    int b = bh >> 4, h = bh & 15;
    int tid = threadIdx.x, lane = tid & 31, w = tid >> 5;

    size_t qrow = (size_t)(b * TT + qt * 64);
    const __half* gq_hi = qkv_hi + qrow * D3 + h * DHH;
    const __half* gq_lo = qkv_lo + qrow * D3 + h * DHH;

    uint32_t sQ = sb;
    uint32_t sS0 = sb + 2 * ATILE;

    attn_fill(sQ, gq_hi, gq_lo, tid);
    {
        const __half* gk_hi = qkv_hi + (size_t)(b * TT) * D3 + DD + h * DHH;
        const __half* gk_lo = qkv_lo + (size_t)(b * TT) * D3 + DD + h * DHH;
        attn_fill(sS0,             gk_hi, gk_lo, tid);
        attn_fill(sS0 + 2 * ATILE, gk_hi + DD, gk_lo + DD, tid);
    }
    CP_COMMIT();
    CP_WAIT0();
    __syncthreads();

    uint32_t qh[4][4], ql[4][4];
    {
        uint32_t rowoff = (uint32_t)(w * 16 + (lane & 15)) * APITCH;
        uint32_t coloff = (uint32_t)(lane >> 4) * 16;
        #pragma unroll
        for (int kb = 0; kb < 4; kb++) {
            uint32_t off = rowoff + kb * 32 + coloff;
            ldsm_x4(sQ + off,         qh[kb][0], qh[kb][1], qh[kb][2], qh[kb][3]);
            ldsm_x4(sQ + ATILE + off, ql[kb][0], ql[kb][1], ql[kb][2], ql[kb][3]);
        }
    }

    float oacc[8][4] = {};
    float mrow[2] = {-1e30f, -1e30f};
    float lrow[2] = {0.f, 0.f};

    int r0loc = w * 16 + (lane >> 2);
    int r0g = qt * 64 + r0loc;
    int cql = (lane & 3) * 2;

    for (int jt = 0; jt <= qt; jt++) {
        uint32_t buf = sS0 + (jt & 1) * ASTAGE;
        if (jt + 1 <= qt) {
            uint32_t nbuf = sS0 + ((jt + 1) & 1) * ASTAGE;
            size_t krow = (size_t)(b * TT + (jt + 1) * 64);
            const __half* gk_hi = qkv_hi + krow * D3 + DD + h * DHH;
            const __half* gk_lo = qkv_lo + krow * D3 + DD + h * DHH;
            attn_fill(nbuf,             gk_hi, gk_lo, tid);
            attn_fill(nbuf + 2 * ATILE, gk_hi + DD, gk_lo + DD, tid);
            CP_COMMIT();
        }

        float s[8][4] = {};
        #pragma unroll
        for (int kb = 0; kb < 4; kb++) {
            uint32_t kcol = (uint32_t)(((lane >> 3) & 1) * 8 + kb * 16) * 2;
            #pragma unroll
            for (int nt = 0; nt < 8; nt++) {
                uint32_t off = (uint32_t)(nt * 8 + (lane & 7)) * APITCH + kcol;
                uint32_t kh0, kh1, kl0, kl1;
                ldsm_x2(buf + off, kh0, kh1);
                ldsm_x2(buf + ATILE + off, kl0, kl1);
                uint32_t bhK[2] = {kh0, kh1}, blK[2] = {kl0, kl1};
                mma_f16(s[nt], qh[kb], bhK);
                mma_f16(s[nt], ql[kb], bhK);
                mma_f16(s[nt], qh[kb], blK);
            }
        }

        bool diag = (jt == qt);
        #pragma unroll
        for (int nt = 0; nt < 8; nt++) {
            int colb = jt * 64 + nt * 8 + cql;
            #pragma unroll
            for (int q = 0; q < 4; q++) {
                float v = s[nt][q] * 0.125f;
                if (diag) {
                    int col = colb + (q & 1);
                    int row = r0g + (q >> 1) * 8;
                    if (col > row) v = -1e30f;
                }
                s[nt][q] = v;
            }
        }

        float mx0 = -1e30f, mx1 = -1e30f;
        #pragma unroll
        for (int nt = 0; nt < 8; nt++) {
            mx0 = fmaxf(mx0, fmaxf(s[nt][0], s[nt][1]));
            mx1 = fmaxf(mx1, fmaxf(s[nt][2], s[nt][3]));
        }
        mx0 = fmaxf(mx0, __shfl_xor_sync(0xffffffffu, mx0, 1));
        mx0 = fmaxf(mx0, __shfl_xor_sync(0xffffffffu, mx0, 2));
        mx1 = fmaxf(mx1, __shfl_xor_sync(0xffffffffu, mx1, 1));
        mx1 = fmaxf(mx1, __shfl_xor_sync(0xffffffffu, mx1, 2));
        float mn0 = fmaxf(mrow[0], mx0), mn1 = fmaxf(mrow[1], mx1);
        float sum0 = 0.f, sum1 = 0.f;
        #pragma unroll
        for (int nt = 0; nt < 8; nt++) {
            s[nt][0] = __expf(s[nt][0] - mn0);
            s[nt][1] = __expf(s[nt][1] - mn0);
            s[nt][2] = __expf(s[nt][2] - mn1);
            s[nt][3] = __expf(s[nt][3] - mn1);
            sum0 += s[nt][0] + s[nt][1];
            sum1 += s[nt][2] + s[nt][3];
        }
        sum0 += __shfl_xor_sync(0xffffffffu, sum0, 1);
        sum0 += __shfl_xor_sync(0xffffffffu, sum0, 2);
        sum1 += __shfl_xor_sync(0xffffffffu, sum1, 1);
        sum1 += __shfl_xor_sync(0xffffffffu, sum1, 2);
        float a0 = __expf(mrow[0] - mn0), a1 = __expf(mrow[1] - mn1);
        lrow[0] = lrow[0] * a0 + sum0;
        lrow[1] = lrow[1] * a1 + sum1;
        mrow[0] = mn0; mrow[1] = mn1;
        #pragma unroll
        for (int nt = 0; nt < 8; nt++) {
            oacc[nt][0] *= a0; oacc[nt][1] *= a0;
            oacc[nt][2] *= a1; oacc[nt][3] *= a1;
        }

        uint32_t vbase = buf + 2 * ATILE;
        #pragma unroll
        for (int kb = 0; kb < 4; kb++) {
            uint32_t ph[4], pl[4];
            {
                float h0, l0, h1, l1;
                split_h(s[2*kb][0], h0, l0); split_h(s[2*kb][1], h1, l1);
                ph[0] = pack_h2(h0, h1); pl[0] = pack_h2(l0, l1);
                split_h(s[2*kb][2], h0, l0); split_h(s[2*kb][3], h1, l1);
                ph[1] = pack_h2(h0, h1); pl[1] = pack_h2(l0, l1);
                split_h(s[2*kb+1][0], h0, l0); split_h(s[2*kb+1][1], h1, l1);
                ph[2] = pack_h2(h0, h1); pl[2] = pack_h2(l0, l1);
                split_h(s[2*kb+1][2], h0, l0); split_h(s[2*kb+1][3], h1, l1);
                ph[3] = pack_h2(h0, h1); pl[3] = pack_h2(l0, l1);
            }
            uint32_t vrow = (uint32_t)(kb * 16 + (lane & 15)) * APITCH;
            #pragma unroll
            for (int nt = 0; nt < 8; nt++) {
                uint32_t off = vrow + nt * 16;
                uint32_t vh0, vh1, vl0, vl1;
                ldsm_x2t(vbase + off, vh0, vh1);
                ldsm_x2t(vbase + ATILE + off, vl0, vl1);
                uint32_t bhV[2] = {vh0, vh1}, blV[2] = {vl0, vl1};
                mma_f16(oacc[nt], ph, bhV);
                mma_f16(oacc[nt], pl, bhV);
                mma_f16(oacc[nt], ph, blV);
            }
        }

        CP_WAIT0();
        __syncthreads();
    }

    float li0 = 1.f / lrow[0], li1 = 1.f / lrow[1];
    size_t orow0 = (size_t)(b * TT + r0g) * DD + h * DHH;
    #pragma unroll
    for (int nt = 0; nt < 8; nt++) {
        int gc = nt * 8 + cql;
        float v0 = oacc[nt][0] * li0, v1 = oacc[nt][1] * li0;
        float v2 = oacc[nt][2] * li1, v3 = oacc[nt][3] * li1;
        float h0, l0, h1, l1;
        split_h(v0, h0, l0); split_h(v1, h1, l1);
        *(uint32_t*)&o_hi[orow0 + gc] = pack_h2(h0, h1);
        *(uint32_t*)&o_lo[orow0 + gc] = pack_h2(l0, l1);
        split_h(v2, h0, l0); split_h(v3, h1, l1);
        *(uint32_t*)&o_hi[orow0 + 8 * DD + gc] = pack_h2(h0, h1);
        *(uint32_t*)&o_lo[orow0 + 8 * DD + gc] = pack_h2(l0, l1);
    }
}

// ---------------- launcher ---------------------------------------------------
extern "C" void kernel_launch(void* const* d_in, const int* in_sizes, int n_in,
                              void* d_out, int out_size)
{
    const int*   ids  = (const int*)  d_in[0];
    const float* tok  = (const float*)d_in[1];
    const float* pos  = (const float*)d_in[2];
    const float* ln1s = (const float*)d_in[3];
    const float* ln1b = (const float*)d_in[4];
    const float* Wqkv = (const float*)d_in[5];
    const float* Wout = (const float*)d_in[6];
    const float* ln2s = (const float*)d_in[7];
    const float* ln2b = (const float*)d_in[8];
    const float* W1   = (const float*)d_in[9];
    const float* W2   = (const float*)d_in[10];
    const float* lnfs = (const float*)d_in[11];
    const float* lnfb = (const float*)d_in[12];
    float* out = (float*)d_out;

    float *x;
    __half *h_hi, *h_lo, *qkv_hi, *qkv_lo, *o_hi, *o_lo, *a_hi, *a_lo;
    __half *wqT, *woT, *w1T, *w2T;
    cudaGetSymbolAddress((void**)&x,      g_x);
    cudaGetSymbolAddress((void**)&h_hi,   g_h_hi);
    cudaGetSymbolAddress((void**)&h_lo,   g_h_lo);
    cudaGetSymbolAddress((void**)&qkv_hi, g_qkv_hi);
    cudaGetSymbolAddress((void**)&qkv_lo, g_qkv_lo);
    cudaGetSymbolAddress((void**)&o_hi,   g_o_hi);
    cudaGetSymbolAddress((void**)&o_lo,   g_o_lo);
    cudaGetSymbolAddress((void**)&a_hi,   g_a_hi);
    cudaGetSymbolAddress((void**)&a_lo,   g_a_lo);
    cudaGetSymbolAddress((void**)&wqT,    g_WqkvT);
    cudaGetSymbolAddress((void**)&woT,    g_WoutT);
    cudaGetSymbolAddress((void**)&w1T,    g_W1T);
    cudaGetSymbolAddress((void**)&w2T,    g_W2T);

    cudaFuncSetAttribute(attn_mma,
                         cudaFuncAttributeMaxDynamicSharedMemorySize, ATTN_SMEM);
    cudaFuncSetAttribute(gemm_mma<1>,
                         cudaFuncAttributeMaxDynamicSharedMemorySize, GSM_TOTAL);
    cudaFuncSetAttribute(gemm_mma<2>,
                         cudaFuncAttributeMaxDynamicSharedMemorySize, GSM_TOTAL);
    cudaFuncSetAttribute(gemm_mma<3>,
                         cudaFuncAttributeMaxDynamicSharedMemorySize, GSM_TOTAL);

    // weight transpose + fp16 convert, batched over all layers (4 launches)
    dim3 tb(32, 8);
    twk<<<dim3(D3 / 32, DD / 32, LL), tb>>>(Wqkv, wqT, DD, D3);
    twk<<<dim3(DD / 32, DD / 32, LL), tb>>>(Wout, woT, DD, DD);
    twk<<<dim3(DFFF / 32, DD / 32, LL), tb>>>(W1, w1T, DD, DFFF);
    twk<<<dim3(DD / 32, DFFF / 32, LL), tb>>>(W2, w2T, DFFF, DD);

    embed_kernel<<<(MROWS * DD + 255) / 256, 256>>>(ids, tok, pos, x);

    for (int l = 0; l < LL; l++) {
        ln_kernel<true><<<MROWS, 256>>>(x, ln1s + (size_t)l * DD, ln1b + (size_t)l * DD,
                                        nullptr, h_hi, h_lo);
        gemm_mma<3><<<dim3(D3 / 128, MROWS / 128), 256, GSM_TOTAL>>>(
            h_hi, h_lo, wqT + (size_t)l * D3 * DD,
            nullptr, nullptr, qkv_hi, qkv_lo, MROWS, D3, DD);
        attn_mma<<<dim3(TT / 64, BB * HH), 128, ATTN_SMEM>>>(qkv_hi, qkv_lo, o_hi, o_lo);
        gemm_mma<1><<<dim3(DD / 128, MROWS / 128), 256, GSM_TOTAL>>>(
            o_hi, o_lo, woT + (size_t)l * DD * DD,
            x, x, nullptr, nullptr, MROWS, DD, DD);
        ln_kernel<true><<<MROWS, 256>>>(x, ln2s + (size_t)l * DD, ln2b + (size_t)l * DD,
                                        nullptr, h_hi, h_lo);
        gemm_mma<2><<<dim3(DFFF / 128, MROWS / 128), 256, GSM_TOTAL>>>(
            h_hi, h_lo, w1T + (size_t)l * DFFF * DD,
            nullptr, nullptr, a_hi, a_lo, MROWS, DFFF, DD);
        gemm_mma<1><<<dim3(DD / 128, MROWS / 128), 256, GSM_TOTAL>>>(
            a_hi, a_lo, w2T + (size_t)l * DD * DFFF,
            x, x, nullptr, nullptr, MROWS, DD, DFFF);
    }

    ln_kernel<false><<<MROWS, 256>>>(x, lnfs, lnfb, out, nullptr, nullptr);
}

// round 9
// speedup vs baseline: 1.4237x; 1.1110x over previous
#include <cuda_runtime.h>
#include <cuda_fp16.h>
#include <math.h>
#include <stdint.h>

// Problem constants
#define BB 2
#define TT 1024
#define DD 1024
#define HH 16
#define LL 6
#define DHH 64
#define DFFF 2048
#define MROWS (BB*TT)   // 2048
#define D3 (3*DD)

// ---------------- scratch (device globals) ----------------------------------
__device__ float g_x[MROWS * DD];                              // residual
__device__ __half g_h_hi[MROWS*DD],    g_h_lo[MROWS*DD];       // LN out
__device__ __half g_qkv_hi[MROWS*D3],  g_qkv_lo[MROWS*D3];     // qkv
__device__ __half g_o_hi[MROWS*DD],    g_o_lo[MROWS*DD];       // attn out
__device__ __half g_a_hi[MROWS*DFFF],  g_a_lo[MROWS*DFFF];     // gelu out
// transposed [N,K] fp16 weights
__device__ __half g_WqkvT[LL*D3*DD];
__device__ __half g_WoutT[LL*DD*DD];
__device__ __half g_W1T [LL*DFFF*DD];
__device__ __half g_W2T [LL*DD*DFFF];

// ================= helpers =================
__device__ __forceinline__ uint32_t smem_u32(const void* p){
    uint32_t a;
    asm("{ .reg .u64 t; cvta.to.shared.u64 t, %1; cvt.u32.u64 %0, t; }"
        : "=r"(a) : "l"(p));
    return a;
}
__device__ __forceinline__ void ldsm_x4(uint32_t a, uint32_t& r0, uint32_t& r1,
                                        uint32_t& r2, uint32_t& r3){
    asm volatile("ldmatrix.sync.aligned.m8n8.x4.shared.b16 {%0,%1,%2,%3}, [%4];"
                 : "=r"(r0), "=r"(r1), "=r"(r2), "=r"(r3) : "r"(a));
}
__device__ __forceinline__ void ldsm_x2(uint32_t a, uint32_t& r0, uint32_t& r1){
    asm volatile("ldmatrix.sync.aligned.m8n8.x2.shared.b16 {%0,%1}, [%2];"
                 : "=r"(r0), "=r"(r1) : "r"(a));
}
__device__ __forceinline__ void ldsm_x2t(uint32_t a, uint32_t& r0, uint32_t& r1){
    asm volatile("ldmatrix.sync.aligned.m8n8.x2.trans.shared.b16 {%0,%1}, [%2];"
                 : "=r"(r0), "=r"(r1) : "r"(a));
}
__device__ __forceinline__ void mma_f16(float* c, const uint32_t* a,
                                        const uint32_t* b){
    asm volatile(
        "mma.sync.aligned.m16n8k16.row.col.f32.f16.f16.f32 "
        "{%0,%1,%2,%3}, {%4,%5,%6,%7}, {%8,%9}, {%0,%1,%2,%3};"
        : "+f"(c[0]), "+f"(c[1]), "+f"(c[2]), "+f"(c[3])
        : "r"(a[0]), "r"(a[1]), "r"(a[2]), "r"(a[3]), "r"(b[0]), "r"(b[1]));
}
__device__ __forceinline__ void cp16(uint32_t dst, const void* src){
    asm volatile("cp.async.cg.shared.global [%0], [%1], 16;"
                 :: "r"(dst), "l"(src));
}
#define CP_COMMIT() asm volatile("cp.async.commit_group;" ::: "memory")
#define CP_WAIT1()  asm volatile("cp.async.wait_group 1;" ::: "memory")
#define CP_WAIT0()  asm volatile("cp.async.wait_group 0;" ::: "memory")

__device__ __forceinline__ uint32_t pack_h2(float lo_val, float hi_val){
    __half2 t = __floats2half2_rn(lo_val, hi_val);
    return *(uint32_t*)&t;
}
__device__ __forceinline__ void split_h(float v, float& hi_f, float& lo_f){
    __half h = __float2half_rn(v);
    hi_f = __half2float(h);
    lo_f = v - hi_f;
}

// ---------------- embedding -------------------------------------------------
__global__ void embed_kernel(const int* __restrict__ ids,
                             const float* __restrict__ tok,
                             const float* __restrict__ pos,
                             float* __restrict__ x)
{
    int idx = blockIdx.x * blockDim.x + threadIdx.x;
    if (idx >= MROWS * DD) return;
    int d  = idx & (DD - 1);
    int bt = idx / DD;
    int t  = bt & (TT - 1);
    x[idx] = tok[(size_t)ids[bt] * DD + d] + pos[t * DD + d];
}

// ---------------- weight transpose + fp16 convert (batched over L) ----------
__global__ void twk(const float* __restrict__ W,
                    __half* __restrict__ hi, int K, int N)
{
    __shared__ float t[32][33];
    size_t loff = (size_t)blockIdx.z * K * N;
    const float* Wl = W + loff;
    __half* hil = hi + loff;

    int n0 = blockIdx.x * 32, k0 = blockIdx.y * 32;
    int tx = threadIdx.x, ty = threadIdx.y;   // 32 x 8
    #pragma unroll
    for (int i = 0; i < 32; i += 8)
        t[ty + i][tx] = Wl[(size_t)(k0 + ty + i) * N + n0 + tx];
    __syncthreads();
    #pragma unroll
    for (int i = 0; i < 32; i += 8) {
        float v = t[tx][ty + i];
        hil[(size_t)(n0 + ty + i) * K + k0 + tx] = __float2half_rn(v);
    }
}

// ---------------- layernorm: warp-per-row, no barriers ----------------------
// block 256 = 8 warps = 8 rows; grid MROWS/8
template<bool HF>
__global__ __launch_bounds__(256) void ln_kernel(
    const float* __restrict__ x,
    const float* __restrict__ s,
    const float* __restrict__ b,
    float* __restrict__ y,
    __half* __restrict__ yhi,
    __half* __restrict__ ylo)
{
    int lane = threadIdx.x & 31;
    int row  = (blockIdx.x << 3) + (threadIdx.x >> 5);
    const float* xr = x + (size_t)row * DD;

    float4 v[8];
    float sum = 0.f, sq = 0.f;
    #pragma unroll
    for (int i = 0; i < 8; i++) {
        v[i] = ((const float4*)xr)[i * 32 + lane];
        sum += v[i].x + v[i].y + v[i].z + v[i].w;
        sq  += v[i].x*v[i].x + v[i].y*v[i].y + v[i].z*v[i].z + v[i].w*v[i].w;
    }
    #pragma unroll
    for (int o = 16; o > 0; o >>= 1) {
        sum += __shfl_xor_sync(0xffffffffu, sum, o);
        sq  += __shfl_xor_sync(0xffffffffu, sq,  o);
    }
    float mean = sum * (1.f / DD);
    float inv  = rsqrtf(sq * (1.f / DD) - mean * mean + 1e-5f);

    #pragma unroll
    for (int i = 0; i < 8; i++) {
        int c4 = i * 32 + lane;
        float4 sv = ((const float4*)s)[c4];
        float4 bv = ((const float4*)b)[c4];
        float o0 = (v[i].x - mean) * inv * sv.x + bv.x;
        float o1 = (v[i].y - mean) * inv * sv.y + bv.y;
        float o2 = (v[i].z - mean) * inv * sv.z + bv.z;
        float o3 = (v[i].w - mean) * inv * sv.w + bv.w;
        if (HF) {
            size_t base = (size_t)row * DD + c4 * 4;
            float h0, l0, h1, l1;
            split_h(o0, h0, l0); split_h(o1, h1, l1);
            *(uint32_t*)&yhi[base]     = pack_h2(h0, h1);
            *(uint32_t*)&ylo[base]     = pack_h2(l0, l1);
            split_h(o2, h0, l0); split_h(o3, h1, l1);
            *(uint32_t*)&yhi[base + 2] = pack_h2(h0, h1);
            *(uint32_t*)&ylo[base + 2] = pack_h2(l0, l1);
        } else {
            ((float4*)(y + (size_t)row * DD))[c4] = make_float4(o0, o1, o2, o3);
        }
    }
}

// ================= mma.sync fp16 GEMM (256 threads, 8 warps) =================
#define TPITCH 80
#define TILE_B (128 * TPITCH)
#define STAGE_B (3 * TILE_B)         // Ahi, Alo, B
#define GSM_TOTAL (2 * STAGE_B)      // 61440

__device__ __forceinline__ void fill_cp(uint32_t dst, const __half* g,
                                        int K, int tid)
{
    #pragma unroll
    for (int i = 0; i < 2; i++) {
        int ch = tid + (i << 8);
        int r = ch >> 2, c = ch & 3;
        cp16(dst + r * TPITCH + c * 16,
             (const char*)g + (size_t)r * K * 2 + c * 16);
    }
}

template<int EPI>
__global__ __launch_bounds__(256, 1) void gemm_mma(
    const __half* __restrict__ Ahi, const __half* __restrict__ Alo,
    const __half* __restrict__ B,
    const float* __restrict__ X, float* __restrict__ C,
    __half* __restrict__ Chi, __half* __restrict__ Clo,
    int M, int N, int K)
{
    extern __shared__ char sm[];
    uint32_t sb = smem_u32(sm);
    int tid  = threadIdx.x;
    int lane = tid & 31, w = tid >> 5;
    int wm = (w >> 2) * 64, wn = (w & 3) * 32;
    int m0 = blockIdx.y * 128, n0 = blockIdx.x * 128;

    const __half* pAhi = Ahi + (size_t)m0 * K;
    const __half* pAlo = Alo + (size_t)m0 * K;
    const __half* pB   = B   + (size_t)n0 * K;

    float acc[4][4][4] = {};
    int S = K >> 5;

    fill_cp(sb,              pAhi, K, tid);
    fill_cp(sb + TILE_B,     pAlo, K, tid);
    fill_cp(sb + 2 * TILE_B, pB,   K, tid);
    CP_COMMIT();

    int aRow = wm + (lane & 15);
    int aCol = (lane >> 4);
    int bRow = wn + (lane & 7);
    int bCol = ((lane >> 3) & 1);

    for (int s = 0; s < S; s++) {
        uint32_t buf = sb + (s & 1) * STAGE_B;
        if (s + 1 < S) {
            uint32_t nbuf = sb + ((s + 1) & 1) * STAGE_B;
            int k0 = (s + 1) << 5;
            fill_cp(nbuf,              pAhi + k0, K, tid);
            fill_cp(nbuf + TILE_B,     pAlo + k0, K, tid);
            fill_cp(nbuf + 2 * TILE_B, pB + k0,   K, tid);
            CP_COMMIT();
            CP_WAIT1();
        } else {
            CP_WAIT0();
        }
        __syncthreads();

        #pragma unroll
        for (int k16 = 0; k16 < 2; k16++) {
            uint32_t ah[4][4], al[4][4];
            #pragma unroll
            for (int mt = 0; mt < 4; mt++) {
                uint32_t off = (uint32_t)(aRow + mt * 16) * TPITCH +
                               (uint32_t)(aCol + k16 * 2) * 16;
                ldsm_x4(buf + off, ah[mt][0], ah[mt][1], ah[mt][2], ah[mt][3]);
                ldsm_x4(buf + TILE_B + off, al[mt][0], al[mt][1], al[mt][2], al[mt][3]);
            }
            uint32_t bh[4][2];
            #pragma unroll
            for (int nt = 0; nt < 4; nt++) {
                uint32_t off = (uint32_t)(bRow + nt * 8) * TPITCH +
                               (uint32_t)(bCol + k16 * 2) * 16;
                ldsm_x2(buf + 2 * TILE_B + off, bh[nt][0], bh[nt][1]);
            }
            #pragma unroll
            for (int mt = 0; mt < 4; mt++)
                #pragma unroll
                for (int nt = 0; nt < 4; nt++) {
                    mma_f16(acc[mt][nt], ah[mt], bh[nt]);
                    mma_f16(acc[mt][nt], al[mt], bh[nt]);
                }
        }
        __syncthreads();
    }

    #pragma unroll
    for (int mt = 0; mt < 4; mt++) {
        #pragma unroll
        for (int nt = 0; nt < 4; nt++) {
            float* cc = acc[mt][nt];
            int gr = m0 + wm + mt * 16 + (lane >> 2);
            int gc = n0 + wn + nt * 8 + (lane & 3) * 2;
            #pragma unroll
            for (int half = 0; half < 2; half++) {
                size_t base = (size_t)(gr + half * 8) * N + gc;
                float v0 = cc[half * 2], v1 = cc[half * 2 + 1];
                if (EPI == 1) {
                    C[base]     = v0 + X[base];
                    C[base + 1] = v1 + X[base + 1];
                } else {
                    if (EPI == 2) {
                        v0 = 0.5f * v0 * (1.f + erff(v0 * 0.70710678118654752f));
                        v1 = 0.5f * v1 * (1.f + erff(v1 * 0.70710678118654752f));
                    }
                    float h0, l0, h1, l1;
                    split_h(v0, h0, l0);
                    split_h(v1, h1, l1);
                    *(uint32_t*)&Chi[base] = pack_h2(h0, h1);
                    *(uint32_t*)&Clo[base] = pack_h2(l0, l1);
                }
            }
        }
    }
}

// ================= tensor-core flash attention (fp16, 3-term) ===============
// grid (8 pairs, 32 bh), 128 threads; CTA p handles q-tiles p and 15-p
// (balanced: total jt-iterations = (p+1) + (16-p) = 17 per CTA)
#define APITCH 144
#define ATILE (64 * APITCH)            // 9216 B per 64x64 fp16 tile
#define ASTAGE (4 * ATILE)             // Khi,Klo,Vhi,Vlo
#define ATTN_SMEM (2 * ATILE + 2 * ASTAGE)  // Q hi/lo + 2 stages = 92160

__device__ __forceinline__ void attn_fill(uint32_t dst,
                                          const __half* ghi,
                                          const __half* glo, int tid)
{
    #pragma unroll
    for (int i = 0; i < 8; i++) {
        int ch = tid + (i << 7);
        int r = (ch & 511) >> 3, c = ch & 7;
        const __half* src = (ch < 512) ? ghi : glo;
        uint32_t d = dst + ((ch < 512) ? 0 : ATILE) + r * APITCH + c * 16;
        cp16(d, (const char*)src + (size_t)r * D3 * 2 + c * 16);
    }
}

__global__ __launch_bounds__(128) void attn_mma(
    const __half* __restrict__ qkv_hi,
    const __half* __restrict__ qkv_lo,
    __half* __restrict__ o_hi,
    __half* __restrict__ o_lo)
{
    extern __shared__ char sm[];
    uint32_t sb = smem_u32(sm);
    int p = blockIdx.x, bh = blockIdx.y;
    int b = bh >> 4, h = bh & 15;
    int tid = threadIdx.x, lane = tid & 31, w = tid >> 5;

    uint32_t sQ = sb;
    uint32_t sS0 = sb + 2 * ATILE;

    for (int sub = 0; sub < 2; sub++) {
        int qt = sub ? (15 - p) : p;

        size_t qrow = (size_t)(b * TT + qt * 64);
        const __half* gq_hi = qkv_hi + qrow * D3 + h * DHH;
        const __half* gq_lo = qkv_lo + qrow * D3 + h * DHH;

        // prologue: Q + stage 0 (K/V tile jt=0)
        attn_fill(sQ, gq_hi, gq_lo, tid);
        {
            const __half* gk_hi = qkv_hi + (size_t)(b * TT) * D3 + DD + h * DHH;
            const __half* gk_lo = qkv_lo + (size_t)(b * TT) * D3 + DD + h * DHH;
            attn_fill(sS0,             gk_hi, gk_lo, tid);
            attn_fill(sS0 + 2 * ATILE, gk_hi + DD, gk_lo + DD, tid);
        }
        CP_COMMIT();
        CP_WAIT0();
        __syncthreads();

        uint32_t qh[4][4], ql[4][4];
        {
            uint32_t rowoff = (uint32_t)(w * 16 + (lane & 15)) * APITCH;
            uint32_t coloff = (uint32_t)(lane >> 4) * 16;
            #pragma unroll
            for (int kb = 0; kb < 4; kb++) {
                uint32_t off = rowoff + kb * 32 + coloff;
                ldsm_x4(sQ + off,         qh[kb][0], qh[kb][1], qh[kb][2], qh[kb][3]);
                ldsm_x4(sQ + ATILE + off, ql[kb][0], ql[kb][1], ql[kb][2], ql[kb][3]);
            }
        }

        float oacc[8][4] = {};
        float mrow[2] = {-1e30f, -1e30f};
        float lrow[2] = {0.f, 0.f};

        int r0loc = w * 16 + (lane >> 2);
        int r0g = qt * 64 + r0loc;
        int cql = (lane & 3) * 2;

        for (int jt = 0; jt <= qt; jt++) {
            uint32_t buf = sS0 + (jt & 1) * ASTAGE;
            if (jt + 1 <= qt) {
                uint32_t nbuf = sS0 + ((jt + 1) & 1) * ASTAGE;
                size_t krow = (size_t)(b * TT + (jt + 1) * 64);
                const __half* gk_hi = qkv_hi + krow * D3 + DD + h * DHH;
                const __half* gk_lo = qkv_lo + krow * D3 + DD + h * DHH;
                attn_fill(nbuf,             gk_hi, gk_lo, tid);
                attn_fill(nbuf + 2 * ATILE, gk_hi + DD, gk_lo + DD, tid);
                CP_COMMIT();
            }

            float s[8][4] = {};
            #pragma unroll
            for (int kb = 0; kb < 4; kb++) {
                uint32_t kcol = (uint32_t)(((lane >> 3) & 1) * 8 + kb * 16) * 2;
                #pragma unroll
                for (int nt = 0; nt < 8; nt++) {
                    uint32_t off = (uint32_t)(nt * 8 + (lane & 7)) * APITCH + kcol;
                    uint32_t kh0, kh1, kl0, kl1;
                    ldsm_x2(buf + off, kh0, kh1);
                    ldsm_x2(buf + ATILE + off, kl0, kl1);
                    uint32_t bhK[2] = {kh0, kh1}, blK[2] = {kl0, kl1};
                    mma_f16(s[nt], qh[kb], bhK);
                    mma_f16(s[nt], ql[kb], bhK);
                    mma_f16(s[nt], qh[kb], blK);
                }
            }

            bool diag = (jt == qt);
            #pragma unroll
            for (int nt = 0; nt < 8; nt++) {
                int colb = jt * 64 + nt * 8 + cql;
                #pragma unroll
                for (int q = 0; q < 4; q++) {
                    float v = s[nt][q] * 0.125f;
                    if (diag) {
                        int col = colb + (q & 1);
                        int row = r0g + (q >> 1) * 8;
                        if (col > row) v = -1e30f;
                    }
                    s[nt][q] = v;
                }
            }

            float mx0 = -1e30f, mx1 = -1e30f;
            #pragma unroll
            for (int nt = 0; nt < 8; nt++) {
                mx0 = fmaxf(mx0, fmaxf(s[nt][0], s[nt][1]));
                mx1 = fmaxf(mx1, fmaxf(s[nt][2], s[nt][3]));
            }
            mx0 = fmaxf(mx0, __shfl_xor_sync(0xffffffffu, mx0, 1));
            mx0 = fmaxf(mx0, __shfl_xor_sync(0xffffffffu, mx0, 2));
            mx1 = fmaxf(mx1, __shfl_xor_sync(0xffffffffu, mx1, 1));
            mx1 = fmaxf(mx1, __shfl_xor_sync(0xffffffffu, mx1, 2));
            float mn0 = fmaxf(mrow[0], mx0), mn1 = fmaxf(mrow[1], mx1);
            float sum0 = 0.f, sum1 = 0.f;
            #pragma unroll
            for (int nt = 0; nt < 8; nt++) {
                s[nt][0] = __expf(s[nt][0] - mn0);
                s[nt][1] = __expf(s[nt][1] - mn0);
                s[nt][2] = __expf(s[nt][2] - mn1);
                s[nt][3] = __expf(s[nt][3] - mn1);
                sum0 += s[nt][0] + s[nt][1];
                sum1 += s[nt][2] + s[nt][3];
            }
            sum0 += __shfl_xor_sync(0xffffffffu, sum0, 1);
            sum0 += __shfl_xor_sync(0xffffffffu, sum0, 2);
            sum1 += __shfl_xor_sync(0xffffffffu, sum1, 1);
            sum1 += __shfl_xor_sync(0xffffffffu, sum1, 2);
            float a0 = __expf(mrow[0] - mn0), a1 = __expf(mrow[1] - mn1);
            lrow[0] = lrow[0] * a0 + sum0;
            lrow[1] = lrow[1] * a1 + sum1;
            mrow[0] = mn0; mrow[1] = mn1;
            #pragma unroll
            for (int nt = 0; nt < 8; nt++) {
                oacc[nt][0] *= a0; oacc[nt][1] *= a0;
                oacc[nt][2] *= a1; oacc[nt][3] *= a1;
            }

            uint32_t vbase = buf + 2 * ATILE;
            #pragma unroll
            for (int kb = 0; kb < 4; kb++) {
                uint32_t ph[4], pl[4];
                {
                    float h0, l0, h1, l1;
                    split_h(s[2*kb][0], h0, l0); split_h(s[2*kb][1], h1, l1);
                    ph[0] = pack_h2(h0, h1); pl[0] = pack_h2(l0, l1);
                    split_h(s[2*kb][2], h0, l0); split_h(s[2*kb][3], h1, l1);
                    ph[1] = pack_h2(h0, h1); pl[1] = pack_h2(l0, l1);
                    split_h(s[2*kb+1][0], h0, l0); split_h(s[2*kb+1][1], h1, l1);
                    ph[2] = pack_h2(h0, h1); pl[2] = pack_h2(l0, l1);
                    split_h(s[2*kb+1][2], h0, l0); split_h(s[2*kb+1][3], h1, l1);
                    ph[3] = pack_h2(h0, h1); pl[3] = pack_h2(l0, l1);
                }
                uint32_t vrow = (uint32_t)(kb * 16 + (lane & 15)) * APITCH;
                #pragma unroll
                for (int nt = 0; nt < 8; nt++) {
                    uint32_t off = vrow + nt * 16;
                    uint32_t vh0, vh1, vl0, vl1;
                    ldsm_x2t(vbase + off, vh0, vh1);
                    ldsm_x2t(vbase + ATILE + off, vl0, vl1);
                    uint32_t bhV[2] = {vh0, vh1}, blV[2] = {vl0, vl1};
                    mma_f16(oacc[nt], ph, bhV);
                    mma_f16(oacc[nt], pl, bhV);
                    mma_f16(oacc[nt], ph, blV);
                }
            }

            CP_WAIT0();
            __syncthreads();
        }

        // epilogue for this q-tile
        float li0 = 1.f / lrow[0], li1 = 1.f / lrow[1];
        size_t orow0 = (size_t)(b * TT + r0g) * DD + h * DHH;
        #pragma unroll
        for (int nt = 0; nt < 8; nt++) {
            int gc = nt * 8 + cql;
            float v0 = oacc[nt][0] * li0, v1 = oacc[nt][1] * li0;
            float v2 = oacc[nt][2] * li1, v3 = oacc[nt][3] * li1;
            float h0, l0, h1, l1;
            split_h(v0, h0, l0); split_h(v1, h1, l1);
            *(uint32_t*)&o_hi[orow0 + gc] = pack_h2(h0, h1);
            *(uint32_t*)&o_lo[orow0 + gc] = pack_h2(l0, l1);
            split_h(v2, h0, l0); split_h(v3, h1, l1);
            *(uint32_t*)&o_hi[orow0 + 8 * DD + gc] = pack_h2(h0, h1);
            *(uint32_t*)&o_lo[orow0 + 8 * DD + gc] = pack_h2(l0, l1);
        }
    }
}

// ---------------- launcher ---------------------------------------------------
extern "C" void kernel_launch(void* const* d_in, const int* in_sizes, int n_in,
                              void* d_out, int out_size)
{
    const int*   ids  = (const int*)  d_in[0];
    const float* tok  = (const float*)d_in[1];
    const float* pos  = (const float*)d_in[2];
    const float* ln1s = (const float*)d_in[3];
    const float* ln1b = (const float*)d_in[4];
    const float* Wqkv = (const float*)d_in[5];
    const float* Wout = (const float*)d_in[6];
    const float* ln2s = (const float*)d_in[7];
    const float* ln2b = (const float*)d_in[8];
    const float* W1   = (const float*)d_in[9];
    const float* W2   = (const float*)d_in[10];
    const float* lnfs = (const float*)d_in[11];
    const float* lnfb = (const float*)d_in[12];
    float* out = (float*)d_out;

    float *x;
    __half *h_hi, *h_lo, *qkv_hi, *qkv_lo, *o_hi, *o_lo, *a_hi, *a_lo;
    __half *wqT, *woT, *w1T, *w2T;
    cudaGetSymbolAddress((void**)&x,      g_x);
    cudaGetSymbolAddress((void**)&h_hi,   g_h_hi);
    cudaGetSymbolAddress((void**)&h_lo,   g_h_lo);
    cudaGetSymbolAddress((void**)&qkv_hi, g_qkv_hi);
    cudaGetSymbolAddress((void**)&qkv_lo, g_qkv_lo);
    cudaGetSymbolAddress((void**)&o_hi,   g_o_hi);
    cudaGetSymbolAddress((void**)&o_lo,   g_o_lo);
    cudaGetSymbolAddress((void**)&a_hi,   g_a_hi);
    cudaGetSymbolAddress((void**)&a_lo,   g_a_lo);
    cudaGetSymbolAddress((void**)&wqT,    g_WqkvT);
    cudaGetSymbolAddress((void**)&woT,    g_WoutT);
    cudaGetSymbolAddress((void**)&w1T,    g_W1T);
    cudaGetSymbolAddress((void**)&w2T,    g_W2T);

    cudaFuncSetAttribute(attn_mma,
                         cudaFuncAttributeMaxDynamicSharedMemorySize, ATTN_SMEM);
    cudaFuncSetAttribute(gemm_mma<1>,
                         cudaFuncAttributeMaxDynamicSharedMemorySize, GSM_TOTAL);
    cudaFuncSetAttribute(gemm_mma<2>,
                         cudaFuncAttributeMaxDynamicSharedMemorySize, GSM_TOTAL);
    cudaFuncSetAttribute(gemm_mma<3>,
                         cudaFuncAttributeMaxDynamicSharedMemorySize, GSM_TOTAL);

    // weight transpose + fp16 convert, batched over all layers (4 launches)
    dim3 tb(32, 8);
    twk<<<dim3(D3 / 32, DD / 32, LL), tb>>>(Wqkv, wqT, DD, D3);
    twk<<<dim3(DD / 32, DD / 32, LL), tb>>>(Wout, woT, DD, DD);
    twk<<<dim3(DFFF / 32, DD / 32, LL), tb>>>(W1, w1T, DD, DFFF);
    twk<<<dim3(DD / 32, DFFF / 32, LL), tb>>>(W2, w2T, DFFF, DD);

    embed_kernel<<<(MROWS * DD + 255) / 256, 256>>>(ids, tok, pos, x);

    for (int l = 0; l < LL; l++) {
        ln_kernel<true><<<MROWS / 8, 256>>>(x, ln1s + (size_t)l * DD,
                                            ln1b + (size_t)l * DD,
                                            nullptr, h_hi, h_lo);
        gemm_mma<3><<<dim3(D3 / 128, MROWS / 128), 256, GSM_TOTAL>>>(
            h_hi, h_lo, wqT + (size_t)l * D3 * DD,
            nullptr, nullptr, qkv_hi, qkv_lo, MROWS, D3, DD);
        attn_mma<<<dim3(TT / 128, BB * HH), 128, ATTN_SMEM>>>(qkv_hi, qkv_lo, o_hi, o_lo);
        gemm_mma<1><<<dim3(DD / 128, MROWS / 128), 256, GSM_TOTAL>>>(
            o_hi, o_lo, woT + (size_t)l * DD * DD,
            x, x, nullptr, nullptr, MROWS, DD, DD);
        ln_kernel<true><<<MROWS / 8, 256>>>(x, ln2s + (size_t)l * DD,
                                            ln2b + (size_t)l * DD,
                                            nullptr, h_hi, h_lo);
        gemm_mma<2><<<dim3(DFFF / 128, MROWS / 128), 256, GSM_TOTAL>>>(
            h_hi, h_lo, w1T + (size_t)l * DFFF * DD,
            nullptr, nullptr, a_hi, a_lo, MROWS, DFFF, DD);
        gemm_mma<1><<<dim3(DD / 128, MROWS / 128), 256, GSM_TOTAL>>>(
            a_hi, a_lo, w2T + (size_t)l * DD * DFFF,
            x, x, nullptr, nullptr, MROWS, DD, DFFF);
    }

    ln_kernel<false><<<MROWS / 8, 256>>>(x, lnfs, lnfb, out, nullptr, nullptr);
}

// round 10
// speedup vs baseline: 1.6292x; 1.1443x over previous
#include <cuda_runtime.h>
#include <cuda_fp16.h>
#include <math.h>
#include <stdint.h>

// Problem constants
#define BB 2
#define TT 1024
#define DD 1024
#define HH 16
#define LL 6
#define DHH 64
#define DFFF 2048
#define MROWS (BB*TT)   // 2048
#define D3 (3*DD)

// ---------------- scratch (device globals) ----------------------------------
__device__ float g_x[MROWS * DD];                              // residual
__device__ __half g_h_hi[MROWS*DD],    g_h_lo[MROWS*DD];       // LN out
__device__ __half g_qkv_hi[MROWS*D3],  g_qkv_lo[MROWS*D3];     // qkv
__device__ __half g_o_hi[MROWS*DD],    g_o_lo[MROWS*DD];       // attn out
__device__ __half g_a_hi[MROWS*DFFF],  g_a_lo[MROWS*DFFF];     // gelu out
// transposed [N,K] fp16 weights
__device__ __half g_WqkvT[LL*D3*DD];
__device__ __half g_WoutT[LL*DD*DD];
__device__ __half g_W1T [LL*DFFF*DD];
__device__ __half g_W2T [LL*DD*DFFF];

// ================= helpers =================
__device__ __forceinline__ uint32_t smem_u32(const void* p){
    uint32_t a;
    asm("{ .reg .u64 t; cvta.to.shared.u64 t, %1; cvt.u32.u64 %0, t; }"
        : "=r"(a) : "l"(p));
    return a;
}
__device__ __forceinline__ void ldsm_x4(uint32_t a, uint32_t& r0, uint32_t& r1,
                                        uint32_t& r2, uint32_t& r3){
    asm volatile("ldmatrix.sync.aligned.m8n8.x4.shared.b16 {%0,%1,%2,%3}, [%4];"
                 : "=r"(r0), "=r"(r1), "=r"(r2), "=r"(r3) : "r"(a));
}
__device__ __forceinline__ void ldsm_x2(uint32_t a, uint32_t& r0, uint32_t& r1){
    asm volatile("ldmatrix.sync.aligned.m8n8.x2.shared.b16 {%0,%1}, [%2];"
                 : "=r"(r0), "=r"(r1) : "r"(a));
}
__device__ __forceinline__ void ldsm_x2t(uint32_t a, uint32_t& r0, uint32_t& r1){
    asm volatile("ldmatrix.sync.aligned.m8n8.x2.trans.shared.b16 {%0,%1}, [%2];"
                 : "=r"(r0), "=r"(r1) : "r"(a));
}
__device__ __forceinline__ void mma_f16(float* c, const uint32_t* a,
                                        const uint32_t* b){
    asm volatile(
        "mma.sync.aligned.m16n8k16.row.col.f32.f16.f16.f32 "
        "{%0,%1,%2,%3}, {%4,%5,%6,%7}, {%8,%9}, {%0,%1,%2,%3};"
        : "+f"(c[0]), "+f"(c[1]), "+f"(c[2]), "+f"(c[3])
        : "r"(a[0]), "r"(a[1]), "r"(a[2]), "r"(a[3]), "r"(b[0]), "r"(b[1]));
}
__device__ __forceinline__ void cp16(uint32_t dst, const void* src){
    asm volatile("cp.async.cg.shared.global [%0], [%1], 16;"
                 :: "r"(dst), "l"(src));
}
#define CP_COMMIT() asm volatile("cp.async.commit_group;" ::: "memory")
#define CP_WAIT1()  asm volatile("cp.async.wait_group 1;" ::: "memory")
#define CP_WAIT0()  asm volatile("cp.async.wait_group 0;" ::: "memory")

__device__ __forceinline__ uint32_t pack_h2(float lo_val, float hi_val){
    __half2 t = __floats2half2_rn(lo_val, hi_val);
    return *(uint32_t*)&t;
}
__device__ __forceinline__ void split_h(float v, float& hi_f, float& lo_f){
    __half h = __float2half_rn(v);
    hi_f = __half2float(h);
    lo_f = v - hi_f;
}

// ---------------- weight transpose + fp16 convert (batched over L) ----------
__global__ void twk(const float* __restrict__ W,
                    __half* __restrict__ hi, int K, int N)
{
    __shared__ float t[32][33];
    size_t loff = (size_t)blockIdx.z * K * N;
    const float* Wl = W + loff;
    __half* hil = hi + loff;

    int n0 = blockIdx.x * 32, k0 = blockIdx.y * 32;
    int tx = threadIdx.x, ty = threadIdx.y;   // 32 x 8
    #pragma unroll
    for (int i = 0; i < 32; i += 8)
        t[ty + i][tx] = Wl[(size_t)(k0 + ty + i) * N + n0 + tx];
    __syncthreads();
    #pragma unroll
    for (int i = 0; i < 32; i += 8) {
        float v = t[tx][ty + i];
        hil[(size_t)(n0 + ty + i) * K + k0 + tx] = __float2half_rn(v);
    }
}

// ---------------- fused embedding + layer-0 LN1 (warp-per-row) --------------
__global__ __launch_bounds__(256) void embed_ln_kernel(
    const int* __restrict__ ids,
    const float* __restrict__ tok,
    const float* __restrict__ pos,
    const float* __restrict__ s,
    const float* __restrict__ b,
    float* __restrict__ x,
    __half* __restrict__ yhi,
    __half* __restrict__ ylo)
{
    int lane = threadIdx.x & 31;
    int row  = (blockIdx.x << 3) + (threadIdx.x >> 5);
    int t    = row & (TT - 1);
    const float4* tok4 = (const float4*)(tok + (size_t)ids[row] * DD);
    const float4* pos4 = (const float4*)(pos + (size_t)t * DD);

    float4 v[8];
    float sum = 0.f, sq = 0.f;
    #pragma unroll
    for (int i = 0; i < 8; i++) {
        float4 a = tok4[i * 32 + lane];
        float4 p = pos4[i * 32 + lane];
        v[i] = make_float4(a.x + p.x, a.y + p.y, a.z + p.z, a.w + p.w);
        sum += v[i].x + v[i].y + v[i].z + v[i].w;
        sq  += v[i].x*v[i].x + v[i].y*v[i].y + v[i].z*v[i].z + v[i].w*v[i].w;
        ((float4*)(x + (size_t)row * DD))[i * 32 + lane] = v[i];
    }
    #pragma unroll
    for (int o = 16; o > 0; o >>= 1) {
        sum += __shfl_xor_sync(0xffffffffu, sum, o);
        sq  += __shfl_xor_sync(0xffffffffu, sq,  o);
    }
    float mean = sum * (1.f / DD);
    float inv  = rsqrtf(sq * (1.f / DD) - mean * mean + 1e-5f);

    #pragma unroll
    for (int i = 0; i < 8; i++) {
        int c4 = i * 32 + lane;
        float4 sv = ((const float4*)s)[c4];
        float4 bv = ((const float4*)b)[c4];
        float o0 = (v[i].x - mean) * inv * sv.x + bv.x;
        float o1 = (v[i].y - mean) * inv * sv.y + bv.y;
        float o2 = (v[i].z - mean) * inv * sv.z + bv.z;
        float o3 = (v[i].w - mean) * inv * sv.w + bv.w;
        size_t base = (size_t)row * DD + c4 * 4;
        float h0, l0, h1, l1;
        split_h(o0, h0, l0); split_h(o1, h1, l1);
        *(uint32_t*)&yhi[base]     = pack_h2(h0, h1);
        *(uint32_t*)&ylo[base]     = pack_h2(l0, l1);
        split_h(o2, h0, l0); split_h(o3, h1, l1);
        *(uint32_t*)&yhi[base + 2] = pack_h2(h0, h1);
        *(uint32_t*)&ylo[base + 2] = pack_h2(l0, l1);
    }
}

// ---------------- layernorm: warp-per-row, no barriers ----------------------
template<bool HF>
__global__ __launch_bounds__(256) void ln_kernel(
    const float* __restrict__ x,
    const float* __restrict__ s,
    const float* __restrict__ b,
    float* __restrict__ y,
    __half* __restrict__ yhi,
    __half* __restrict__ ylo)
{
    int lane = threadIdx.x & 31;
    int row  = (blockIdx.x << 3) + (threadIdx.x >> 5);
    const float* xr = x + (size_t)row * DD;

    float4 v[8];
    float sum = 0.f, sq = 0.f;
    #pragma unroll
    for (int i = 0; i < 8; i++) {
        v[i] = ((const float4*)xr)[i * 32 + lane];
        sum += v[i].x + v[i].y + v[i].z + v[i].w;
        sq  += v[i].x*v[i].x + v[i].y*v[i].y + v[i].z*v[i].z + v[i].w*v[i].w;
    }
    #pragma unroll
    for (int o = 16; o > 0; o >>= 1) {
        sum += __shfl_xor_sync(0xffffffffu, sum, o);
        sq  += __shfl_xor_sync(0xffffffffu, sq,  o);
    }
    float mean = sum * (1.f / DD);
    float inv  = rsqrtf(sq * (1.f / DD) - mean * mean + 1e-5f);

    #pragma unroll
    for (int i = 0; i < 8; i++) {
        int c4 = i * 32 + lane;
        float4 sv = ((const float4*)s)[c4];
        float4 bv = ((const float4*)b)[c4];
        float o0 = (v[i].x - mean) * inv * sv.x + bv.x;
        float o1 = (v[i].y - mean) * inv * sv.y + bv.y;
        float o2 = (v[i].z - mean) * inv * sv.z + bv.z;
        float o3 = (v[i].w - mean) * inv * sv.w + bv.w;
        if (HF) {
            size_t base = (size_t)row * DD + c4 * 4;
            float h0, l0, h1, l1;
            split_h(o0, h0, l0); split_h(o1, h1, l1);
            *(uint32_t*)&yhi[base]     = pack_h2(h0, h1);
            *(uint32_t*)&ylo[base]     = pack_h2(l0, l1);
            split_h(o2, h0, l0); split_h(o3, h1, l1);
            *(uint32_t*)&yhi[base + 2] = pack_h2(h0, h1);
            *(uint32_t*)&ylo[base + 2] = pack_h2(l0, l1);
        } else {
            ((float4*)(y + (size_t)row * DD))[c4] = make_float4(o0, o1, o2, o3);
        }
    }
}

// ================= mma.sync fp16 GEMM (256 threads, 8 warps) =================
// K-step 64, 3-stage cp.async ring, ONE barrier per stage.
// smem tile: 128 rows x 64 halves (128 B data), pitch 144 B.
#define GP 144
#define GTILE (128 * GP)              // 18432
#define STAGE_B (3 * GTILE)           // 55296 (Ahi, Alo, B)
#define GSM_TOTAL (3 * STAGE_B)       // 165888

__device__ __forceinline__ void fill_cp(uint32_t dst, const __half* g,
                                        int K, int tid)
{
    // 128 rows x 8 16B-chunks = 1024 chunks, 256 threads -> 4 each
    #pragma unroll
    for (int i = 0; i < 4; i++) {
        int ch = tid + (i << 8);
        int r = ch >> 3, c = ch & 7;
        cp16(dst + r * GP + c * 16,
             (const char*)g + (size_t)r * K * 2 + c * 16);
    }
}

template<int EPI>
__global__ __launch_bounds__(256, 1) void gemm_mma(
    const __half* __restrict__ Ahi, const __half* __restrict__ Alo,
    const __half* __restrict__ B,
    const float* __restrict__ X, float* __restrict__ C,
    __half* __restrict__ Chi, __half* __restrict__ Clo,
    int M, int N, int K)
{
    extern __shared__ char sm[];
    uint32_t sb = smem_u32(sm);
    int tid  = threadIdx.x;
    int lane = tid & 31, w = tid >> 5;
    int wm = (w >> 2) * 64, wn = (w & 3) * 32;
    int m0 = blockIdx.y * 128, n0 = blockIdx.x * 128;

    const __half* pAhi = Ahi + (size_t)m0 * K;
    const __half* pAlo = Alo + (size_t)m0 * K;
    const __half* pB   = B   + (size_t)n0 * K;

    float acc[4][4][4] = {};
    int S = K >> 6;

    // prologue: stages 0, 1
    fill_cp(sb,             pAhi, K, tid);
    fill_cp(sb + GTILE,     pAlo, K, tid);
    fill_cp(sb + 2 * GTILE, pB,   K, tid);
    CP_COMMIT();
    fill_cp(sb + STAGE_B,             pAhi + 64, K, tid);
    fill_cp(sb + STAGE_B + GTILE,     pAlo + 64, K, tid);
    fill_cp(sb + STAGE_B + 2 * GTILE, pB + 64,   K, tid);
    CP_COMMIT();

    int aRow = wm + (lane & 15);
    int aSel = (lane >> 4);
    int bRow = wn + (lane & 7);
    int bSel = ((lane >> 3) & 1);

    for (int s = 0; s < S; s++) {
        if (s < S - 1) { CP_WAIT1(); } else { CP_WAIT0(); }
        __syncthreads();

        // prefetch stage s+2 into ring slot (s+2)%3 (overwrites slot of s-1,
        // which every thread finished before this barrier)
        if (s + 2 < S) {
            uint32_t nbuf = sb + ((s + 2) % 3) * STAGE_B;
            int k0 = (s + 2) << 6;
            fill_cp(nbuf,             pAhi + k0, K, tid);
            fill_cp(nbuf + GTILE,     pAlo + k0, K, tid);
            fill_cp(nbuf + 2 * GTILE, pB + k0,   K, tid);
            CP_COMMIT();
        }

        uint32_t buf = sb + (s % 3) * STAGE_B;
        #pragma unroll
        for (int k16 = 0; k16 < 4; k16++) {
            uint32_t ah[4][4], al[4][4];
            #pragma unroll
            for (int mt = 0; mt < 4; mt++) {
                uint32_t off = (uint32_t)(aRow + mt * 16) * GP +
                               (uint32_t)(k16 * 2 + aSel) * 16;
                ldsm_x4(buf + off, ah[mt][0], ah[mt][1], ah[mt][2], ah[mt][3]);
                ldsm_x4(buf + GTILE + off, al[mt][0], al[mt][1], al[mt][2], al[mt][3]);
            }
            uint32_t bh[4][2];
            #pragma unroll
            for (int nt = 0; nt < 4; nt++) {
                uint32_t off = (uint32_t)(bRow + nt * 8) * GP +
                               (uint32_t)(k16 * 2 + bSel) * 16;
                ldsm_x2(buf + 2 * GTILE + off, bh[nt][0], bh[nt][1]);
            }
            #pragma unroll
            for (int mt = 0; mt < 4; mt++)
                #pragma unroll
                for (int nt = 0; nt < 4; nt++) {
                    mma_f16(acc[mt][nt], ah[mt], bh[nt]);
                    mma_f16(acc[mt][nt], al[mt], bh[nt]);
                }
        }
    }

    #pragma unroll
    for (int mt = 0; mt < 4; mt++) {
        #pragma unroll
        for (int nt = 0; nt < 4; nt++) {
            float* cc = acc[mt][nt];
            int gr = m0 + wm + mt * 16 + (lane >> 2);
            int gc = n0 + wn + nt * 8 + (lane & 3) * 2;
            #pragma unroll
            for (int half = 0; half < 2; half++) {
                size_t base = (size_t)(gr + half * 8) * N + gc;
                float v0 = cc[half * 2], v1 = cc[half * 2 + 1];
                if (EPI == 1) {
                    C[base]     = v0 + X[base];
                    C[base + 1] = v1 + X[base + 1];
                } else {
                    if (EPI == 2) {
                        v0 = 0.5f * v0 * (1.f + erff(v0 * 0.70710678118654752f));
                        v1 = 0.5f * v1 * (1.f + erff(v1 * 0.70710678118654752f));
                    }
                    float h0, l0, h1, l1;
                    split_h(v0, h0, l0);
                    split_h(v1, h1, l1);
                    *(uint32_t*)&Chi[base] = pack_h2(h0, h1);
                    *(uint32_t*)&Clo[base] = pack_h2(l0, l1);
                }
            }
        }
    }
}

// ================= tensor-core flash attention (fp16, 3-term) ===============
// grid (8 pairs, 32 bh), 128 threads; CTA p handles q-tiles p and 15-p
#define APITCH 144
#define ATILE (64 * APITCH)
#define ASTAGE (4 * ATILE)
#define ATTN_SMEM (2 * ATILE + 2 * ASTAGE)  // 92160

__device__ __forceinline__ void attn_fill(uint32_t dst,
                                          const __half* ghi,
                                          const __half* glo, int tid)
{
    #pragma unroll
    for (int i = 0; i < 8; i++) {
        int ch = tid + (i << 7);
        int r = (ch & 511) >> 3, c = ch & 7;
        const __half* src = (ch < 512) ? ghi : glo;
        uint32_t d = dst + ((ch < 512) ? 0 : ATILE) + r * APITCH + c * 16;
        cp16(d, (const char*)src + (size_t)r * D3 * 2 + c * 16);
    }
}

__global__ __launch_bounds__(128) void attn_mma(
    const __half* __restrict__ qkv_hi,
    const __half* __restrict__ qkv_lo,
    __half* __restrict__ o_hi,
    __half* __restrict__ o_lo)
{
    extern __shared__ char sm[];
    uint32_t sb = smem_u32(sm);
    int p = blockIdx.x, bh = blockIdx.y;
    int b = bh >> 4, h = bh & 15;
    int tid = threadIdx.x, lane = tid & 31, w = tid >> 5;

    uint32_t sQ = sb;
    uint32_t sS0 = sb + 2 * ATILE;

    for (int sub = 0; sub < 2; sub++) {
        int qt = sub ? (15 - p) : p;

        size_t qrow = (size_t)(b * TT + qt * 64);
        const __half* gq_hi = qkv_hi + qrow * D3 + h * DHH;
        const __half* gq_lo = qkv_lo + qrow * D3 + h * DHH;

        attn_fill(sQ, gq_hi, gq_lo, tid);
        {
            const __half* gk_hi = qkv_hi + (size_t)(b * TT) * D3 + DD + h * DHH;
            const __half* gk_lo = qkv_lo + (size_t)(b * TT) * D3 + DD + h * DHH;
            attn_fill(sS0,             gk_hi, gk_lo, tid);
            attn_fill(sS0 + 2 * ATILE, gk_hi + DD, gk_lo + DD, tid);
        }
        CP_COMMIT();
        CP_WAIT0();
        __syncthreads();

        uint32_t qh[4][4], ql[4][4];
        {
            uint32_t rowoff = (uint32_t)(w * 16 + (lane & 15)) * APITCH;
            uint32_t coloff = (uint32_t)(lane >> 4) * 16;
            #pragma unroll
            for (int kb = 0; kb < 4; kb++) {
                uint32_t off = rowoff + kb * 32 + coloff;
                ldsm_x4(sQ + off,         qh[kb][0], qh[kb][1], qh[kb][2], qh[kb][3]);
                ldsm_x4(sQ + ATILE + off, ql[kb][0], ql[kb][1], ql[kb][2], ql[kb][3]);
            }
        }

        float oacc[8][4] = {};
        float mrow[2] = {-1e30f, -1e30f};
        float lrow[2] = {0.f, 0.f};

        int r0loc = w * 16 + (lane >> 2);
        int r0g = qt * 64 + r0loc;
        int cql = (lane & 3) * 2;

        for (int jt = 0; jt <= qt; jt++) {
            uint32_t buf = sS0 + (jt & 1) * ASTAGE;
            if (jt + 1 <= qt) {
                uint32_t nbuf = sS0 + ((jt + 1) & 1) * ASTAGE;
                size_t krow = (size_t)(b * TT + (jt + 1) * 64);
                const __half* gk_hi = qkv_hi + krow * D3 + DD + h * DHH;
                const __half* gk_lo = qkv_lo + krow * D3 + DD + h * DHH;
                attn_fill(nbuf,             gk_hi, gk_lo, tid);
                attn_fill(nbuf + 2 * ATILE, gk_hi + DD, gk_lo + DD, tid);
                CP_COMMIT();
            }

            float s[8][4] = {};
            #pragma unroll
            for (int kb = 0; kb < 4; kb++) {
                uint32_t kcol = (uint32_t)(((lane >> 3) & 1) * 8 + kb * 16) * 2;
                #pragma unroll
                for (int nt = 0; nt < 8; nt++) {
                    uint32_t off = (uint32_t)(nt * 8 + (lane & 7)) * APITCH + kcol;
                    uint32_t kh0, kh1, kl0, kl1;
                    ldsm_x2(buf + off, kh0, kh1);
                    ldsm_x2(buf + ATILE + off, kl0, kl1);
                    uint32_t bhK[2] = {kh0, kh1}, blK[2] = {kl0, kl1};
                    mma_f16(s[nt], qh[kb], bhK);
                    mma_f16(s[nt], ql[kb], bhK);
                    mma_f16(s[nt], qh[kb], blK);
                }
            }

            bool diag = (jt == qt);
            #pragma unroll
            for (int nt = 0; nt < 8; nt++) {
                int colb = jt * 64 + nt * 8 + cql;
                #pragma unroll
                for (int q = 0; q < 4; q++) {
                    float v = s[nt][q] * 0.125f;
                    if (diag) {
                        int col = colb + (q & 1);
                        int row = r0g + (q >> 1) * 8;
                        if (col > row) v = -1e30f;
                    }
                    s[nt][q] = v;
                }
            }

            float mx0 = -1e30f, mx1 = -1e30f;
            #pragma unroll
            for (int nt = 0; nt < 8; nt++) {
                mx0 = fmaxf(mx0, fmaxf(s[nt][0], s[nt][1]));
                mx1 = fmaxf(mx1, fmaxf(s[nt][2], s[nt][3]));
            }
            mx0 = fmaxf(mx0, __shfl_xor_sync(0xffffffffu, mx0, 1));
            mx0 = fmaxf(mx0, __shfl_xor_sync(0xffffffffu, mx0, 2));
            mx1 = fmaxf(mx1, __shfl_xor_sync(0xffffffffu, mx1, 1));
            mx1 = fmaxf(mx1, __shfl_xor_sync(0xffffffffu, mx1, 2));
            float mn0 = fmaxf(mrow[0], mx0), mn1 = fmaxf(mrow[1], mx1);
            float sum0 = 0.f, sum1 = 0.f;
            #pragma unroll
            for (int nt = 0; nt < 8; nt++) {
                s[nt][0] = __expf(s[nt][0] - mn0);
                s[nt][1] = __expf(s[nt][1] - mn0);
                s[nt][2] = __expf(s[nt][2] - mn1);
                s[nt][3] = __expf(s[nt][3] - mn1);
                sum0 += s[nt][0] + s[nt][1];
                sum1 += s[nt][2] + s[nt][3];
            }
            sum0 += __shfl_xor_sync(0xffffffffu, sum0, 1);
            sum0 += __shfl_xor_sync(0xffffffffu, sum0, 2);
            sum1 += __shfl_xor_sync(0xffffffffu, sum1, 1);
            sum1 += __shfl_xor_sync(0xffffffffu, sum1, 2);
            float a0 = __expf(mrow[0] - mn0), a1 = __expf(mrow[1] - mn1);
            lrow[0] = lrow[0] * a0 + sum0;
            lrow[1] = lrow[1] * a1 + sum1;
            mrow[0] = mn0; mrow[1] = mn1;
            #pragma unroll
            for (int nt = 0; nt < 8; nt++) {
                oacc[nt][0] *= a0; oacc[nt][1] *= a0;
                oacc[nt][2] *= a1; oacc[nt][3] *= a1;
            }

            uint32_t vbase = buf + 2 * ATILE;
            #pragma unroll
            for (int kb = 0; kb < 4; kb++) {
                uint32_t ph[4], pl[4];
                {
                    float h0, l0, h1, l1;
                    split_h(s[2*kb][0], h0, l0); split_h(s[2*kb][1], h1, l1);
                    ph[0] = pack_h2(h0, h1); pl[0] = pack_h2(l0, l1);
                    split_h(s[2*kb][2], h0, l0); split_h(s[2*kb][3], h1, l1);
                    ph[1] = pack_h2(h0, h1); pl[1] = pack_h2(l0, l1);
                    split_h(s[2*kb+1][0], h0, l0); split_h(s[2*kb+1][1], h1, l1);
                    ph[2] = pack_h2(h0, h1); pl[2] = pack_h2(l0, l1);
                    split_h(s[2*kb+1][2], h0, l0); split_h(s[2*kb+1][3], h1, l1);
                    ph[3] = pack_h2(h0, h1); pl[3] = pack_h2(l0, l1);
                }
                uint32_t vrow = (uint32_t)(kb * 16 + (lane & 15)) * APITCH;
                #pragma unroll
                for (int nt = 0; nt < 8; nt++) {
                    uint32_t off = vrow + nt * 16;
                    uint32_t vh0, vh1, vl0, vl1;
                    ldsm_x2t(vbase + off, vh0, vh1);
                    ldsm_x2t(vbase + ATILE + off, vl0, vl1);
                    uint32_t bhV[2] = {vh0, vh1}, blV[2] = {vl0, vl1};
                    mma_f16(oacc[nt], ph, bhV);
                    mma_f16(oacc[nt], pl, bhV);
                    mma_f16(oacc[nt], ph, blV);
                }
            }

            CP_WAIT0();
            __syncthreads();
        }

        float li0 = 1.f / lrow[0], li1 = 1.f / lrow[1];
        size_t orow0 = (size_t)(b * TT + r0g) * DD + h * DHH;
        #pragma unroll
        for (int nt = 0; nt < 8; nt++) {
            int gc = nt * 8 + cql;
            float v0 = oacc[nt][0] * li0, v1 = oacc[nt][1] * li0;
            float v2 = oacc[nt][2] * li1, v3 = oacc[nt][3] * li1;
            float h0, l0, h1, l1;
            split_h(v0, h0, l0); split_h(v1, h1, l1);
            *(uint32_t*)&o_hi[orow0 + gc] = pack_h2(h0, h1);
            *(uint32_t*)&o_lo[orow0 + gc] = pack_h2(l0, l1);
            split_h(v2, h0, l0); split_h(v3, h1, l1);
            *(uint32_t*)&o_hi[orow0 + 8 * DD + gc] = pack_h2(h0, h1);
            *(uint32_t*)&o_lo[orow0 + 8 * DD + gc] = pack_h2(l0, l1);
        }
    }
}

// ---------------- launcher ---------------------------------------------------
extern "C" void kernel_launch(void* const* d_in, const int* in_sizes, int n_in,
                              void* d_out, int out_size)
{
    const int*   ids  = (const int*)  d_in[0];
    const float* tok  = (const float*)d_in[1];
    const float* pos  = (const float*)d_in[2];
    const float* ln1s = (const float*)d_in[3];
    const float* ln1b = (const float*)d_in[4];
    const float* Wqkv = (const float*)d_in[5];
    const float* Wout = (const float*)d_in[6];
    const float* ln2s = (const float*)d_in[7];
    const float* ln2b = (const float*)d_in[8];
    const float* W1   = (const float*)d_in[9];
    const float* W2   = (const float*)d_in[10];
    const float* lnfs = (const float*)d_in[11];
    const float* lnfb = (const float*)d_in[12];
    float* out = (float*)d_out;

    float *x;
    __half *h_hi, *h_lo, *qkv_hi, *qkv_lo, *o_hi, *o_lo, *a_hi, *a_lo;
    __half *wqT, *woT, *w1T, *w2T;
    cudaGetSymbolAddress((void**)&x,      g_x);
    cudaGetSymbolAddress((void**)&h_hi,   g_h_hi);
    cudaGetSymbolAddress((void**)&h_lo,   g_h_lo);
    cudaGetSymbolAddress((void**)&qkv_hi, g_qkv_hi);
    cudaGetSymbolAddress((void**)&qkv_lo, g_qkv_lo);
    cudaGetSymbolAddress((void**)&o_hi,   g_o_hi);
    cudaGetSymbolAddress((void**)&o_lo,   g_o_lo);
    cudaGetSymbolAddress((void**)&a_hi,   g_a_hi);
    cudaGetSymbolAddress((void**)&a_lo,   g_a_lo);
    cudaGetSymbolAddress((void**)&wqT,    g_WqkvT);
    cudaGetSymbolAddress((void**)&woT,    g_WoutT);
    cudaGetSymbolAddress((void**)&w1T,    g_W1T);
    cudaGetSymbolAddress((void**)&w2T,    g_W2T);

    cudaFuncSetAttribute(attn_mma,
                         cudaFuncAttributeMaxDynamicSharedMemorySize, ATTN_SMEM);
    cudaFuncSetAttribute(gemm_mma<1>,
                         cudaFuncAttributeMaxDynamicSharedMemorySize, GSM_TOTAL);
    cudaFuncSetAttribute(gemm_mma<2>,
                         cudaFuncAttributeMaxDynamicSharedMemorySize, GSM_TOTAL);
    cudaFuncSetAttribute(gemm_mma<3>,
                         cudaFuncAttributeMaxDynamicSharedMemorySize, GSM_TOTAL);

    // weight transpose + fp16 convert (4 launches)
    dim3 tb(32, 8);
    twk<<<dim3(D3 / 32, DD / 32, LL), tb>>>(Wqkv, wqT, DD, D3);
    twk<<<dim3(DD / 32, DD / 32, LL), tb>>>(Wout, woT, DD, DD);
    twk<<<dim3(DFFF / 32, DD / 32, LL), tb>>>(W1, w1T, DD, DFFF);
    twk<<<dim3(DD / 32, DFFF / 32, LL), tb>>>(W2, w2T, DFFF, DD);

    // fused embed + layer-0 LN1
    embed_ln_kernel<<<MROWS / 8, 256>>>(ids, tok, pos, ln1s, ln1b, x, h_hi, h_lo);

    for (int l = 0; l < LL; l++) {
        if (l > 0)
            ln_kernel<true><<<MROWS / 8, 256>>>(x, ln1s + (size_t)l * DD,
                                                ln1b + (size_t)l * DD,
                                                nullptr, h_hi, h_lo);
        gemm_mma<3><<<dim3(D3 / 128, MROWS / 128), 256, GSM_TOTAL>>>(
            h_hi, h_lo, wqT + (size_t)l * D3 * DD,
            nullptr, nullptr, qkv_hi, qkv_lo, MROWS, D3, DD);
        attn_mma<<<dim3(TT / 128, BB * HH), 128, ATTN_SMEM>>>(qkv_hi, qkv_lo, o_hi, o_lo);
        gemm_mma<1><<<dim3(DD / 128, MROWS / 128), 256, GSM_TOTAL>>>(
            o_hi, o_lo, woT + (size_t)l * DD * DD,
            x, x, nullptr, nullptr, MROWS, DD, DD);
        ln_kernel<true><<<MROWS / 8, 256>>>(x, ln2s + (size_t)l * DD,
                                            ln2b + (size_t)l * DD,
                                            nullptr, h_hi, h_lo);
        gemm_mma<2><<<dim3(DFFF / 128, MROWS / 128), 256, GSM_TOTAL>>>(
            h_hi, h_lo, w1T + (size_t)l * DFFF * DD,
            nullptr, nullptr, a_hi, a_lo, MROWS, DFFF, DD);
        gemm_mma<1><<<dim3(DD / 128, MROWS / 128), 256, GSM_TOTAL>>>(
            a_hi, a_lo, w2T + (size_t)l * DD * DFFF,
            x, x, nullptr, nullptr, MROWS, DD, DFFF);
    }

    ln_kernel<false><<<MROWS / 8, 256>>>(x, lnfs, lnfb, out, nullptr, nullptr);
}

// round 11
// speedup vs baseline: 1.7154x; 1.0529x over previous
#include <cuda_runtime.h>
#include <cuda_fp16.h>
#include <math.h>
#include <stdint.h>

// Problem constants
#define BB 2
#define TT 1024
#define DD 1024
#define HH 16
#define LL 6
#define DHH 64
#define DFFF 2048
#define MROWS (BB*TT)   // 2048
#define D3 (3*DD)

// ---------------- scratch (device globals) ----------------------------------
__device__ float g_x[MROWS * DD];                              // residual
__device__ __half g_h_hi[MROWS*DD],    g_h_lo[MROWS*DD];       // LN out
__device__ __half g_qkv_hi[MROWS*D3],  g_qkv_lo[MROWS*D3];     // qkv
__device__ __half g_o_hi[MROWS*DD],    g_o_lo[MROWS*DD];       // attn out
__device__ __half g_a_hi[MROWS*DFFF],  g_a_lo[MROWS*DFFF];     // gelu out
// transposed [N,K] fp16 weights
__device__ __half g_WqkvT[LL*D3*DD];
__device__ __half g_WoutT[LL*DD*DD];
__device__ __half g_W1T [LL*DFFF*DD];
__device__ __half g_W2T [LL*DD*DFFF];

// ================= helpers =================
__device__ __forceinline__ uint32_t smem_u32(const void* p){
    uint32_t a;
    asm("{ .reg .u64 t; cvta.to.shared.u64 t, %1; cvt.u32.u64 %0, t; }"
        : "=r"(a) : "l"(p));
    return a;
}
__device__ __forceinline__ void ldsm_x4(uint32_t a, uint32_t& r0, uint32_t& r1,
                                        uint32_t& r2, uint32_t& r3){
    asm volatile("ldmatrix.sync.aligned.m8n8.x4.shared.b16 {%0,%1,%2,%3}, [%4];"
                 : "=r"(r0), "=r"(r1), "=r"(r2), "=r"(r3) : "r"(a));
}
__device__ __forceinline__ void ldsm_x2(uint32_t a, uint32_t& r0, uint32_t& r1){
    asm volatile("ldmatrix.sync.aligned.m8n8.x2.shared.b16 {%0,%1}, [%2];"
                 : "=r"(r0), "=r"(r1) : "r"(a));
}
__device__ __forceinline__ void ldsm_x2t(uint32_t a, uint32_t& r0, uint32_t& r1){
    asm volatile("ldmatrix.sync.aligned.m8n8.x2.trans.shared.b16 {%0,%1}, [%2];"
                 : "=r"(r0), "=r"(r1) : "r"(a));
}
__device__ __forceinline__ void mma_f16(float* c, const uint32_t* a,
                                        const uint32_t* b){
    asm volatile(
        "mma.sync.aligned.m16n8k16.row.col.f32.f16.f16.f32 "
        "{%0,%1,%2,%3}, {%4,%5,%6,%7}, {%8,%9}, {%0,%1,%2,%3};"
        : "+f"(c[0]), "+f"(c[1]), "+f"(c[2]), "+f"(c[3])
        : "r"(a[0]), "r"(a[1]), "r"(a[2]), "r"(a[3]), "r"(b[0]), "r"(b[1]));
}
__device__ __forceinline__ void cp16(uint32_t dst, const void* src){
    asm volatile("cp.async.cg.shared.global [%0], [%1], 16;"
                 :: "r"(dst), "l"(src));
}
#define CP_COMMIT() asm volatile("cp.async.commit_group;" ::: "memory")
#define CP_WAIT1()  asm volatile("cp.async.wait_group 1;" ::: "memory")
#define CP_WAIT0()  asm volatile("cp.async.wait_group 0;" ::: "memory")

__device__ __forceinline__ uint32_t pack_h2(float lo_val, float hi_val){
    __half2 t = __floats2half2_rn(lo_val, hi_val);
    return *(uint32_t*)&t;
}
__device__ __forceinline__ void split_h(float v, float& hi_f, float& lo_f){
    __half h = __float2half_rn(v);
    hi_f = __half2float(h);
    lo_f = v - hi_f;
}

// ---------------- weight transpose + fp16 convert (vectorized) --------------
// tile: 32 k-rows x 128 n-cols; block (32,8)
__global__ void twk(const float* __restrict__ W,
                    __half* __restrict__ out, int K, int N)
{
    __shared__ float t[32][129];
    size_t loff = (size_t)blockIdx.z * K * N;
    const float* Wl = W + loff;
    __half* ol = out + loff;

    int n0 = blockIdx.x * 128, k0 = blockIdx.y * 32;
    int tid = threadIdx.y * 32 + threadIdx.x;

    // load 32x128 floats as 1024 float4, 4 per thread
    #pragma unroll
    for (int i = 0; i < 4; i++) {
        int idx = tid + (i << 8);
        int r = idx >> 5, c4 = idx & 31;
        float4 v = *(const float4*)(Wl + (size_t)(k0 + r) * N + n0 + c4 * 4);
        t[r][c4 * 4 + 0] = v.x;
        t[r][c4 * 4 + 1] = v.y;
        t[r][c4 * 4 + 2] = v.z;
        t[r][c4 * 4 + 3] = v.w;
    }
    __syncthreads();

    // store: 128 n x 4 chunks of 8 halfs (uint4), 2 per thread
    #pragma unroll
    for (int i = 0; i < 2; i++) {
        int idx = tid + (i << 8);
        int n = idx >> 2, kc = idx & 3;
        __half h[8];
        #pragma unroll
        for (int j = 0; j < 8; j++)
            h[j] = __float2half_rn(t[kc * 8 + j][n]);
        *(uint4*)(ol + (size_t)(n0 + n) * K + k0 + kc * 8) = *(uint4*)h;
    }
}

// ---------------- fused embedding + layer-0 LN1 (warp-per-row) --------------
__global__ __launch_bounds__(256) void embed_ln_kernel(
    const int* __restrict__ ids,
    const float* __restrict__ tok,
    const float* __restrict__ pos,
    const float* __restrict__ s,
    const float* __restrict__ b,
    float* __restrict__ x,
    __half* __restrict__ yhi,
    __half* __restrict__ ylo)
{
    int lane = threadIdx.x & 31;
    int row  = (blockIdx.x << 3) + (threadIdx.x >> 5);
    int t    = row & (TT - 1);
    const float4* tok4 = (const float4*)(tok + (size_t)ids[row] * DD);
    const float4* pos4 = (const float4*)(pos + (size_t)t * DD);

    float4 v[8];
    float sum = 0.f, sq = 0.f;
    #pragma unroll
    for (int i = 0; i < 8; i++) {
        float4 a = tok4[i * 32 + lane];
        float4 p = pos4[i * 32 + lane];
        v[i] = make_float4(a.x + p.x, a.y + p.y, a.z + p.z, a.w + p.w);
        sum += v[i].x + v[i].y + v[i].z + v[i].w;
        sq  += v[i].x*v[i].x + v[i].y*v[i].y + v[i].z*v[i].z + v[i].w*v[i].w;
        ((float4*)(x + (size_t)row * DD))[i * 32 + lane] = v[i];
    }
    #pragma unroll
    for (int o = 16; o > 0; o >>= 1) {
        sum += __shfl_xor_sync(0xffffffffu, sum, o);
        sq  += __shfl_xor_sync(0xffffffffu, sq,  o);
    }
    float mean = sum * (1.f / DD);
    float inv  = rsqrtf(sq * (1.f / DD) - mean * mean + 1e-5f);

    #pragma unroll
    for (int i = 0; i < 8; i++) {
        int c4 = i * 32 + lane;
        float4 sv = ((const float4*)s)[c4];
        float4 bv = ((const float4*)b)[c4];
        float o0 = (v[i].x - mean) * inv * sv.x + bv.x;
        float o1 = (v[i].y - mean) * inv * sv.y + bv.y;
        float o2 = (v[i].z - mean) * inv * sv.z + bv.z;
        float o3 = (v[i].w - mean) * inv * sv.w + bv.w;
        size_t base = (size_t)row * DD + c4 * 4;
        float h0, l0, h1, l1;
        split_h(o0, h0, l0); split_h(o1, h1, l1);
        *(uint32_t*)&yhi[base]     = pack_h2(h0, h1);
        *(uint32_t*)&ylo[base]     = pack_h2(l0, l1);
        split_h(o2, h0, l0); split_h(o3, h1, l1);
        *(uint32_t*)&yhi[base + 2] = pack_h2(h0, h1);
        *(uint32_t*)&ylo[base + 2] = pack_h2(l0, l1);
    }
}

// ---------------- layernorm: warp-per-row, no barriers ----------------------
template<bool HF>
__global__ __launch_bounds__(256) void ln_kernel(
    const float* __restrict__ x,
    const float* __restrict__ s,
    const float* __restrict__ b,
    float* __restrict__ y,
    __half* __restrict__ yhi,
    __half* __restrict__ ylo)
{
    int lane = threadIdx.x & 31;
    int row  = (blockIdx.x << 3) + (threadIdx.x >> 5);
    const float* xr = x + (size_t)row * DD;

    float4 v[8];
    float sum = 0.f, sq = 0.f;
    #pragma unroll
    for (int i = 0; i < 8; i++) {
        v[i] = ((const float4*)xr)[i * 32 + lane];
        sum += v[i].x + v[i].y + v[i].z + v[i].w;
        sq  += v[i].x*v[i].x + v[i].y*v[i].y + v[i].z*v[i].z + v[i].w*v[i].w;
    }
    #pragma unroll
    for (int o = 16; o > 0; o >>= 1) {
        sum += __shfl_xor_sync(0xffffffffu, sum, o);
        sq  += __shfl_xor_sync(0xffffffffu, sq,  o);
    }
    float mean = sum * (1.f / DD);
    float inv  = rsqrtf(sq * (1.f / DD) - mean * mean + 1e-5f);

    #pragma unroll
    for (int i = 0; i < 8; i++) {
        int c4 = i * 32 + lane;
        float4 sv = ((const float4*)s)[c4];
        float4 bv = ((const float4*)b)[c4];
        float o0 = (v[i].x - mean) * inv * sv.x + bv.x;
        float o1 = (v[i].y - mean) * inv * sv.y + bv.y;
        float o2 = (v[i].z - mean) * inv * sv.z + bv.z;
        float o3 = (v[i].w - mean) * inv * sv.w + bv.w;
        if (HF) {
            size_t base = (size_t)row * DD + c4 * 4;
            float h0, l0, h1, l1;
            split_h(o0, h0, l0); split_h(o1, h1, l1);
            *(uint32_t*)&yhi[base]     = pack_h2(h0, h1);
            *(uint32_t*)&ylo[base]     = pack_h2(l0, l1);
            split_h(o2, h0, l0); split_h(o3, h1, l1);
            *(uint32_t*)&yhi[base + 2] = pack_h2(h0, h1);
            *(uint32_t*)&ylo[base + 2] = pack_h2(l0, l1);
        } else {
            ((float4*)(y + (size_t)row * DD))[c4] = make_float4(o0, o1, o2, o3);
        }
    }
}

// ================= mma.sync fp16 GEMM (256 threads, 8 warps) =================
// K-step 64, 2-stage double buffer, ONE barrier per stage, 2 CTAs/SM.
#define GP 144
#define GTILE (128 * GP)              // 18432
#define STAGE_B (3 * GTILE)           // 55296 (Ahi, Alo, B)
#define GSM_TOTAL (2 * STAGE_B)       // 110592 -> 2 CTAs/SM

__device__ __forceinline__ void fill_cp(uint32_t dst, const __half* g,
                                        int K, int tid)
{
    // 128 rows x 8 16B-chunks = 1024 chunks, 256 threads -> 4 each
    #pragma unroll
    for (int i = 0; i < 4; i++) {
        int ch = tid + (i << 8);
        int r = ch >> 3, c = ch & 7;
        cp16(dst + r * GP + c * 16,
             (const char*)g + (size_t)r * K * 2 + c * 16);
    }
}

template<int EPI>
__global__ __launch_bounds__(256, 2) void gemm_mma(
    const __half* __restrict__ Ahi, const __half* __restrict__ Alo,
    const __half* __restrict__ B,
    const float* __restrict__ X, float* __restrict__ C,
    __half* __restrict__ Chi, __half* __restrict__ Clo,
    int M, int N, int K)
{
    extern __shared__ char sm[];
    uint32_t sb = smem_u32(sm);
    int tid  = threadIdx.x;
    int lane = tid & 31, w = tid >> 5;
    int wm = (w >> 2) * 64, wn = (w & 3) * 32;
    int m0 = blockIdx.y * 128, n0 = blockIdx.x * 128;

    const __half* pAhi = Ahi + (size_t)m0 * K;
    const __half* pAlo = Alo + (size_t)m0 * K;
    const __half* pB   = B   + (size_t)n0 * K;

    float acc[4][4][4] = {};
    int S = K >> 6;

    // prologue: stage 0
    fill_cp(sb,             pAhi, K, tid);
    fill_cp(sb + GTILE,     pAlo, K, tid);
    fill_cp(sb + 2 * GTILE, pB,   K, tid);
    CP_COMMIT();

    int aRow = wm + (lane & 15);
    int aSel = (lane >> 4);
    int bRow = wn + (lane & 7);
    int bSel = ((lane >> 3) & 1);

    for (int s = 0; s < S; s++) {
        CP_WAIT0();          // own fill(s) complete
        __syncthreads();     // all fills visible; compute(s-1) done everywhere

        // prefetch stage s+1 into the buffer that held stage s-1
        if (s + 1 < S) {
            uint32_t nbuf = sb + ((s + 1) & 1) * STAGE_B;
            int k0 = (s + 1) << 6;
            fill_cp(nbuf,             pAhi + k0, K, tid);
            fill_cp(nbuf + GTILE,     pAlo + k0, K, tid);
            fill_cp(nbuf + 2 * GTILE, pB + k0,   K, tid);
            CP_COMMIT();
        }

        uint32_t buf = sb + (s & 1) * STAGE_B;
        #pragma unroll
        for (int k16 = 0; k16 < 4; k16++) {
            uint32_t ah[4][4], al[4][4];
            #pragma unroll
            for (int mt = 0; mt < 4; mt++) {
                uint32_t off = (uint32_t)(aRow + mt * 16) * GP +
                               (uint32_t)(k16 * 2 + aSel) * 16;
                ldsm_x4(buf + off, ah[mt][0], ah[mt][1], ah[mt][2], ah[mt][3]);
                ldsm_x4(buf + GTILE + off, al[mt][0], al[mt][1], al[mt][2], al[mt][3]);
            }
            uint32_t bh[4][2];
            #pragma unroll
            for (int nt = 0; nt < 4; nt++) {
                uint32_t off = (uint32_t)(bRow + nt * 8) * GP +
                               (uint32_t)(k16 * 2 + bSel) * 16;
                ldsm_x2(buf + 2 * GTILE + off, bh[nt][0], bh[nt][1]);
            }
            #pragma unroll
            for (int mt = 0; mt < 4; mt++)
                #pragma unroll
                for (int nt = 0; nt < 4; nt++) {
                    mma_f16(acc[mt][nt], ah[mt], bh[nt]);
                    mma_f16(acc[mt][nt], al[mt], bh[nt]);
                }
        }
    }

    #pragma unroll
    for (int mt = 0; mt < 4; mt++) {
        #pragma unroll
        for (int nt = 0; nt < 4; nt++) {
            float* cc = acc[mt][nt];
            int gr = m0 + wm + mt * 16 + (lane >> 2);
            int gc = n0 + wn + nt * 8 + (lane & 3) * 2;
            #pragma unroll
            for (int half = 0; half < 2; half++) {
                size_t base = (size_t)(gr + half * 8) * N + gc;
                float v0 = cc[half * 2], v1 = cc[half * 2 + 1];
                if (EPI == 1) {
                    C[base]     = v0 + X[base];
                    C[base + 1] = v1 + X[base + 1];
                } else {
                    if (EPI == 2) {
                        v0 = 0.5f * v0 * (1.f + erff(v0 * 0.70710678118654752f));
                        v1 = 0.5f * v1 * (1.f + erff(v1 * 0.70710678118654752f));
                    }
                    float h0, l0, h1, l1;
                    split_h(v0, h0, l0);
                    split_h(v1, h1, l1);
                    *(uint32_t*)&Chi[base] = pack_h2(h0, h1);
                    *(uint32_t*)&Clo[base] = pack_h2(l0, l1);
                }
            }
        }
    }
}

// ================= tensor-core flash attention ==============================
// QK^T 3-term, PV 2-term (P single fp16, V hi/lo).
// grid (8 pairs, 32 bh), 128 threads; CTA p handles q-tiles p and 15-p
#define APITCH 144
#define ATILE (64 * APITCH)
#define ASTAGE (4 * ATILE)
#define ATTN_SMEM (2 * ATILE + 2 * ASTAGE)  // 92160

__device__ __forceinline__ void attn_fill(uint32_t dst,
                                          const __half* ghi,
                                          const __half* glo, int tid)
{
    #pragma unroll
    for (int i = 0; i < 8; i++) {
        int ch = tid + (i << 7);
        int r = (ch & 511) >> 3, c = ch & 7;
        const __half* src = (ch < 512) ? ghi : glo;
        uint32_t d = dst + ((ch < 512) ? 0 : ATILE) + r * APITCH + c * 16;
        cp16(d, (const char*)src + (size_t)r * D3 * 2 + c * 16);
    }
}

__global__ __launch_bounds__(128) void attn_mma(
    const __half* __restrict__ qkv_hi,
    const __half* __restrict__ qkv_lo,
    __half* __restrict__ o_hi,
    __half* __restrict__ o_lo)
{
    extern __shared__ char sm[];
    uint32_t sb = smem_u32(sm);
    int p = blockIdx.x, bh = blockIdx.y;
    int b = bh >> 4, h = bh & 15;
    int tid = threadIdx.x, lane = tid & 31, w = tid >> 5;

    uint32_t sQ = sb;
    uint32_t sS0 = sb + 2 * ATILE;

    for (int sub = 0; sub < 2; sub++) {
        int qt = sub ? (15 - p) : p;

        size_t qrow = (size_t)(b * TT + qt * 64);
        const __half* gq_hi = qkv_hi + qrow * D3 + h * DHH;
        const __half* gq_lo = qkv_lo + qrow * D3 + h * DHH;

        attn_fill(sQ, gq_hi, gq_lo, tid);
        {
            const __half* gk_hi = qkv_hi + (size_t)(b * TT) * D3 + DD + h * DHH;
            const __half* gk_lo = qkv_lo + (size_t)(b * TT) * D3 + DD + h * DHH;
            attn_fill(sS0,             gk_hi, gk_lo, tid);
            attn_fill(sS0 + 2 * ATILE, gk_hi + DD, gk_lo + DD, tid);
        }
        CP_COMMIT();
        CP_WAIT0();
        __syncthreads();

        uint32_t qh[4][4], ql[4][4];
        {
            uint32_t rowoff = (uint32_t)(w * 16 + (lane & 15)) * APITCH;
            uint32_t coloff = (uint32_t)(lane >> 4) * 16;
            #pragma unroll
            for (int kb = 0; kb < 4; kb++) {
                uint32_t off = rowoff + kb * 32 + coloff;
                ldsm_x4(sQ + off,         qh[kb][0], qh[kb][1], qh[kb][2], qh[kb][3]);
                ldsm_x4(sQ + ATILE + off, ql[kb][0], ql[kb][1], ql[kb][2], ql[kb][3]);
            }
        }

        float oacc[8][4] = {};
        float mrow[2] = {-1e30f, -1e30f};
        float lrow[2] = {0.f, 0.f};

        int r0loc = w * 16 + (lane >> 2);
        int r0g = qt * 64 + r0loc;
        int cql = (lane & 3) * 2;

        for (int jt = 0; jt <= qt; jt++) {
            uint32_t buf = sS0 + (jt & 1) * ASTAGE;
            if (jt + 1 <= qt) {
                uint32_t nbuf = sS0 + ((jt + 1) & 1) * ASTAGE;
                size_t krow = (size_t)(b * TT + (jt + 1) * 64);
                const __half* gk_hi = qkv_hi + krow * D3 + DD + h * DHH;
                const __half* gk_lo = qkv_lo + krow * D3 + DD + h * DHH;
                attn_fill(nbuf,             gk_hi, gk_lo, tid);
                attn_fill(nbuf + 2 * ATILE, gk_hi + DD, gk_lo + DD, tid);
                CP_COMMIT();
            }

            float s[8][4] = {};
            #pragma unroll
            for (int kb = 0; kb < 4; kb++) {
                uint32_t kcol = (uint32_t)(((lane >> 3) & 1) * 8 + kb * 16) * 2;
                #pragma unroll
                for (int nt = 0; nt < 8; nt++) {
                    uint32_t off = (uint32_t)(nt * 8 + (lane & 7)) * APITCH + kcol;
                    uint32_t kh0, kh1, kl0, kl1;
                    ldsm_x2(buf + off, kh0, kh1);
                    ldsm_x2(buf + ATILE + off, kl0, kl1);
                    uint32_t bhK[2] = {kh0, kh1}, blK[2] = {kl0, kl1};
                    mma_f16(s[nt], qh[kb], bhK);
                    mma_f16(s[nt], ql[kb], bhK);
                    mma_f16(s[nt], qh[kb], blK);
                }
            }

            bool diag = (jt == qt);
            #pragma unroll
            for (int nt = 0; nt < 8; nt++) {
                int colb = jt * 64 + nt * 8 + cql;
                #pragma unroll
                for (int q = 0; q < 4; q++) {
                    float v = s[nt][q] * 0.125f;
                    if (diag) {
                        int col = colb + (q & 1);
                        int row = r0g + (q >> 1) * 8;
                        if (col > row) v = -1e30f;
                    }
                    s[nt][q] = v;
                }
            }

            float mx0 = -1e30f, mx1 = -1e30f;
            #pragma unroll
            for (int nt = 0; nt < 8; nt++) {
                mx0 = fmaxf(mx0, fmaxf(s[nt][0], s[nt][1]));
                mx1 = fmaxf(mx1, fmaxf(s[nt][2], s[nt][3]));
            }
            mx0 = fmaxf(mx0, __shfl_xor_sync(0xffffffffu, mx0, 1));
            mx0 = fmaxf(mx0, __shfl_xor_sync(0xffffffffu, mx0, 2));
            mx1 = fmaxf(mx1, __shfl_xor_sync(0xffffffffu, mx1, 1));
            mx1 = fmaxf(mx1, __shfl_xor_sync(0xffffffffu, mx1, 2));
            float mn0 = fmaxf(mrow[0], mx0), mn1 = fmaxf(mrow[1], mx1);
            float sum0 = 0.f, sum1 = 0.f;
            #pragma unroll
            for (int nt = 0; nt < 8; nt++) {
                s[nt][0] = __expf(s[nt][0] - mn0);
                s[nt][1] = __expf(s[nt][1] - mn0);
                s[nt][2] = __expf(s[nt][2] - mn1);
                s[nt][3] = __expf(s[nt][3] - mn1);
                sum0 += s[nt][0] + s[nt][1];
                sum1 += s[nt][2] + s[nt][3];
            }
            sum0 += __shfl_xor_sync(0xffffffffu, sum0, 1);
            sum0 += __shfl_xor_sync(0xffffffffu, sum0, 2);
            sum1 += __shfl_xor_sync(0xffffffffu, sum1, 1);
            sum1 += __shfl_xor_sync(0xffffffffu, sum1, 2);
            float a0 = __expf(mrow[0] - mn0), a1 = __expf(mrow[1] - mn1);
            lrow[0] = lrow[0] * a0 + sum0;
            lrow[1] = lrow[1] * a1 + sum1;
            mrow[0] = mn0; mrow[1] = mn1;
            #pragma unroll
            for (int nt = 0; nt < 8; nt++) {
                oacc[nt][0] *= a0; oacc[nt][1] *= a0;
                oacc[nt][2] *= a1; oacc[nt][3] *= a1;
            }

            // O += P V : P single fp16, V hi/lo (2 MMAs per nt)
            uint32_t vbase = buf + 2 * ATILE;
            #pragma unroll
            for (int kb = 0; kb < 4; kb++) {
                uint32_t ph[4];
                ph[0] = pack_h2(s[2*kb][0],   s[2*kb][1]);
                ph[1] = pack_h2(s[2*kb][2],   s[2*kb][3]);
                ph[2] = pack_h2(s[2*kb+1][0], s[2*kb+1][1]);
                ph[3] = pack_h2(s[2*kb+1][2], s[2*kb+1][3]);
                uint32_t vrow = (uint32_t)(kb * 16 + (lane & 15)) * APITCH;
                #pragma unroll
                for (int nt = 0; nt < 8; nt++) {
                    uint32_t off = vrow + nt * 16;
                    uint32_t vh0, vh1, vl0, vl1;
                    ldsm_x2t(vbase + off, vh0, vh1);
                    ldsm_x2t(vbase + ATILE + off, vl0, vl1);
                    uint32_t bhV[2] = {vh0, vh1}, blV[2] = {vl0, vl1};
                    mma_f16(oacc[nt], ph, bhV);
                    mma_f16(oacc[nt], ph, blV);
                }
            }

            CP_WAIT0();
            __syncthreads();
        }

        float li0 = 1.f / lrow[0], li1 = 1.f / lrow[1];
        size_t orow0 = (size_t)(b * TT + r0g) * DD + h * DHH;
        #pragma unroll
        for (int nt = 0; nt < 8; nt++) {
            int gc = nt * 8 + cql;
            float v0 = oacc[nt][0] * li0, v1 = oacc[nt][1] * li0;
            float v2 = oacc[nt][2] * li1, v3 = oacc[nt][3] * li1;
            float h0, l0, h1, l1;
            split_h(v0, h0, l0); split_h(v1, h1, l1);
            *(uint32_t*)&o_hi[orow0 + gc] = pack_h2(h0, h1);
            *(uint32_t*)&o_lo[orow0 + gc] = pack_h2(l0, l1);
            split_h(v2, h0, l0); split_h(v3, h1, l1);
            *(uint32_t*)&o_hi[orow0 + 8 * DD + gc] = pack_h2(h0, h1);
            *(uint32_t*)&o_lo[orow0 + 8 * DD + gc] = pack_h2(l0, l1);
        }
    }
}

// ---------------- launcher ---------------------------------------------------
extern "C" void kernel_launch(void* const* d_in, const int* in_sizes, int n_in,
                              void* d_out, int out_size)
{
    const int*   ids  = (const int*)  d_in[0];
    const float* tok  = (const float*)d_in[1];
    const float* pos  = (const float*)d_in[2];
    const float* ln1s = (const float*)d_in[3];
    const float* ln1b = (const float*)d_in[4];
    const float* Wqkv = (const float*)d_in[5];
    const float* Wout = (const float*)d_in[6];
    const float* ln2s = (const float*)d_in[7];
    const float* ln2b = (const float*)d_in[8];
    const float* W1   = (const float*)d_in[9];
    const float* W2   = (const float*)d_in[10];
    const float* lnfs = (const float*)d_in[11];
    const float* lnfb = (const float*)d_in[12];
    float* out = (float*)d_out;

    float *x;
    __half *h_hi, *h_lo, *qkv_hi, *qkv_lo, *o_hi, *o_lo, *a_hi, *a_lo;
    __half *wqT, *woT, *w1T, *w2T;
    cudaGetSymbolAddress((void**)&x,      g_x);
    cudaGetSymbolAddress((void**)&h_hi,   g_h_hi);
    cudaGetSymbolAddress((void**)&h_lo,   g_h_lo);
    cudaGetSymbolAddress((void**)&qkv_hi, g_qkv_hi);
    cudaGetSymbolAddress((void**)&qkv_lo, g_qkv_lo);
    cudaGetSymbolAddress((void**)&o_hi,   g_o_hi);
    cudaGetSymbolAddress((void**)&o_lo,   g_o_lo);
    cudaGetSymbolAddress((void**)&a_hi,   g_a_hi);
    cudaGetSymbolAddress((void**)&a_lo,   g_a_lo);
    cudaGetSymbolAddress((void**)&wqT,    g_WqkvT);
    cudaGetSymbolAddress((void**)&woT,    g_WoutT);
    cudaGetSymbolAddress((void**)&w1T,    g_W1T);
    cudaGetSymbolAddress((void**)&w2T,    g_W2T);

    cudaFuncSetAttribute(attn_mma,
                         cudaFuncAttributeMaxDynamicSharedMemorySize, ATTN_SMEM);
    cudaFuncSetAttribute(gemm_mma<1>,
                         cudaFuncAttributeMaxDynamicSharedMemorySize, GSM_TOTAL);
    cudaFuncSetAttribute(gemm_mma<2>,
                         cudaFuncAttributeMaxDynamicSharedMemorySize, GSM_TOTAL);
    cudaFuncSetAttribute(gemm_mma<3>,
                         cudaFuncAttributeMaxDynamicSharedMemorySize, GSM_TOTAL);

    // weight transpose + fp16 convert (4 launches, vectorized)
    dim3 tb(32, 8);
    twk<<<dim3(D3 / 128,   DD / 32,   LL), tb>>>(Wqkv, wqT, DD, D3);
    twk<<<dim3(DD / 128,   DD / 32,   LL), tb>>>(Wout, woT, DD, DD);
    twk<<<dim3(DFFF / 128, DD / 32,   LL), tb>>>(W1, w1T, DD, DFFF);
    twk<<<dim3(DD / 128,   DFFF / 32, LL), tb>>>(W2, w2T, DFFF, DD);

    // fused embed + layer-0 LN1
    embed_ln_kernel<<<MROWS / 8, 256>>>(ids, tok, pos, ln1s, ln1b, x, h_hi, h_lo);

    for (int l = 0; l < LL; l++) {
        if (l > 0)
            ln_kernel<true><<<MROWS / 8, 256>>>(x, ln1s + (size_t)l * DD,
                                                ln1b + (size_t)l * DD,
                                                nullptr, h_hi, h_lo);
        gemm_mma<3><<<dim3(D3 / 128, MROWS / 128), 256, GSM_TOTAL>>>(
            h_hi, h_lo, wqT + (size_t)l * D3 * DD,
            nullptr, nullptr, qkv_hi, qkv_lo, MROWS, D3, DD);
        attn_mma<<<dim3(TT / 128, BB * HH), 128, ATTN_SMEM>>>(qkv_hi, qkv_lo, o_hi, o_lo);
        gemm_mma<1><<<dim3(DD / 128, MROWS / 128), 256, GSM_TOTAL>>>(
            o_hi, o_lo, woT + (size_t)l * DD * DD,
            x, x, nullptr, nullptr, MROWS, DD, DD);
        ln_kernel<true><<<MROWS / 8, 256>>>(x, ln2s + (size_t)l * DD,
                                            ln2b + (size_t)l * DD,
                                            nullptr, h_hi, h_lo);
        gemm_mma<2><<<dim3(DFFF / 128, MROWS / 128), 256, GSM_TOTAL>>>(
            h_hi, h_lo, w1T + (size_t)l * DFFF * DD,
            nullptr, nullptr, a_hi, a_lo, MROWS, DFFF, DD);
        gemm_mma<1><<<dim3(DD / 128, MROWS / 128), 256, GSM_TOTAL>>>(
            a_hi, a_lo, w2T + (size_t)l * DD * DFFF,
            x, x, nullptr, nullptr, MROWS, DD, DFFF);
    }

    ln_kernel<false><<<MROWS / 8, 256>>>(x, lnfs, lnfb, out, nullptr, nullptr);
}

// round 12
// speedup vs baseline: 2.0536x; 1.1972x over previous
#include <cuda_runtime.h>
#include <cuda_fp16.h>
#include <math.h>
#include <stdint.h>

// Problem constants
#define BB 2
#define TT 1024
#define DD 1024
#define HH 16
#define LL 6
#define DHH 64
#define DFFF 2048
#define MROWS (BB*TT)   // 2048
#define D3 (3*DD)

// ---------------- scratch (device globals) ----------------------------------
__device__ float g_x[MROWS * DD];                              // residual
__device__ __half g_h_hi[MROWS*DD],    g_h_lo[MROWS*DD];       // LN out
__device__ __half g_qkv_hi[MROWS*D3],  g_qkv_lo[MROWS*D3];     // qkv
__device__ __half g_o_hi[MROWS*DD],    g_o_lo[MROWS*DD];       // attn out
__device__ __half g_a_hi[MROWS*DFFF];                          // gelu out (hi only)
// transposed [N,K] fp16 weights
__device__ __half g_WqkvT[LL*D3*DD];
__device__ __half g_WoutT[LL*DD*DD];
__device__ __half g_W1T [LL*DFFF*DD];
__device__ __half g_W2T [LL*DD*DFFF];

// ================= helpers =================
__device__ __forceinline__ uint32_t smem_u32(const void* p){
    uint32_t a;
    asm("{ .reg .u64 t; cvta.to.shared.u64 t, %1; cvt.u32.u64 %0, t; }"
        : "=r"(a) : "l"(p));
    return a;
}
__device__ __forceinline__ void ldsm_x4(uint32_t a, uint32_t& r0, uint32_t& r1,
                                        uint32_t& r2, uint32_t& r3){
    asm volatile("ldmatrix.sync.aligned.m8n8.x4.shared.b16 {%0,%1,%2,%3}, [%4];"
                 : "=r"(r0), "=r"(r1), "=r"(r2), "=r"(r3) : "r"(a));
}
__device__ __forceinline__ void ldsm_x2(uint32_t a, uint32_t& r0, uint32_t& r1){
    asm volatile("ldmatrix.sync.aligned.m8n8.x2.shared.b16 {%0,%1}, [%2];"
                 : "=r"(r0), "=r"(r1) : "r"(a));
}
__device__ __forceinline__ void ldsm_x2t(uint32_t a, uint32_t& r0, uint32_t& r1){
    asm volatile("ldmatrix.sync.aligned.m8n8.x2.trans.shared.b16 {%0,%1}, [%2];"
                 : "=r"(r0), "=r"(r1) : "r"(a));
}
__device__ __forceinline__ void mma_f16(float* c, const uint32_t* a,
                                        const uint32_t* b){
    asm volatile(
        "mma.sync.aligned.m16n8k16.row.col.f32.f16.f16.f32 "
        "{%0,%1,%2,%3}, {%4,%5,%6,%7}, {%8,%9}, {%0,%1,%2,%3};"
        : "+f"(c[0]), "+f"(c[1]), "+f"(c[2]), "+f"(c[3])
        : "r"(a[0]), "r"(a[1]), "r"(a[2]), "r"(a[3]), "r"(b[0]), "r"(b[1]));
}
__device__ __forceinline__ void cp16(uint32_t dst, const void* src){
    asm volatile("cp.async.cg.shared.global [%0], [%1], 16;"
                 :: "r"(dst), "l"(src));
}
#define CP_COMMIT() asm volatile("cp.async.commit_group;" ::: "memory")
#define CP_WAIT0()  asm volatile("cp.async.wait_group 0;" ::: "memory")

__device__ __forceinline__ uint32_t pack_h2(float lo_val, float hi_val){
    __half2 t = __floats2half2_rn(lo_val, hi_val);
    return *(uint32_t*)&t;
}
__device__ __forceinline__ void split_h(float v, float& hi_f, float& lo_f){
    __half h = __float2half_rn(v);
    hi_f = __half2float(h);
    lo_f = v - hi_f;
}

// ---------------- weight transpose + fp16 convert (vectorized) --------------
__global__ void twk(const float* __restrict__ W,
                    __half* __restrict__ out, int K, int N)
{
    __shared__ float t[32][129];
    size_t loff = (size_t)blockIdx.z * K * N;
    const float* Wl = W + loff;
    __half* ol = out + loff;

    int n0 = blockIdx.x * 128, k0 = blockIdx.y * 32;
    int tid = threadIdx.y * 32 + threadIdx.x;

    #pragma unroll
    for (int i = 0; i < 4; i++) {
        int idx = tid + (i << 8);
        int r = idx >> 5, c4 = idx & 31;
        float4 v = *(const float4*)(Wl + (size_t)(k0 + r) * N + n0 + c4 * 4);
        t[r][c4 * 4 + 0] = v.x;
        t[r][c4 * 4 + 1] = v.y;
        t[r][c4 * 4 + 2] = v.z;
        t[r][c4 * 4 + 3] = v.w;
    }
    __syncthreads();

    #pragma unroll
    for (int i = 0; i < 2; i++) {
        int idx = tid + (i << 8);
        int n = idx >> 2, kc = idx & 3;
        __half h[8];
        #pragma unroll
        for (int j = 0; j < 8; j++)
            h[j] = __float2half_rn(t[kc * 8 + j][n]);
        *(uint4*)(ol + (size_t)(n0 + n) * K + k0 + kc * 8) = *(uint4*)h;
    }
}

// ---------------- fused embedding + layer-0 LN1 (warp-per-row) --------------
__global__ __launch_bounds__(256) void embed_ln_kernel(
    const int* __restrict__ ids,
    const float* __restrict__ tok,
    const float* __restrict__ pos,
    const float* __restrict__ s,
    const float* __restrict__ b,
    float* __restrict__ x,
    __half* __restrict__ yhi,
    __half* __restrict__ ylo)
{
    int lane = threadIdx.x & 31;
    int row  = (blockIdx.x << 3) + (threadIdx.x >> 5);
    int t    = row & (TT - 1);
    const float4* tok4 = (const float4*)(tok + (size_t)ids[row] * DD);
    const float4* pos4 = (const float4*)(pos + (size_t)t * DD);

    float4 v[8];
    float sum = 0.f, sq = 0.f;
    #pragma unroll
    for (int i = 0; i < 8; i++) {
        float4 a = tok4[i * 32 + lane];
        float4 p = pos4[i * 32 + lane];
        v[i] = make_float4(a.x + p.x, a.y + p.y, a.z + p.z, a.w + p.w);
        sum += v[i].x + v[i].y + v[i].z + v[i].w;
        sq  += v[i].x*v[i].x + v[i].y*v[i].y + v[i].z*v[i].z + v[i].w*v[i].w;
        ((float4*)(x + (size_t)row * DD))[i * 32 + lane] = v[i];
    }
    #pragma unroll
    for (int o = 16; o > 0; o >>= 1) {
        sum += __shfl_xor_sync(0xffffffffu, sum, o);
        sq  += __shfl_xor_sync(0xffffffffu, sq,  o);
    }
    float mean = sum * (1.f / DD);
    float inv  = rsqrtf(sq * (1.f / DD) - mean * mean + 1e-5f);

    #pragma unroll
    for (int i = 0; i < 8; i++) {
        int c4 = i * 32 + lane;
        float4 sv = ((const float4*)s)[c4];
        float4 bv = ((const float4*)b)[c4];
        float o0 = (v[i].x - mean) * inv * sv.x + bv.x;
        float o1 = (v[i].y - mean) * inv * sv.y + bv.y;
        float o2 = (v[i].z - mean) * inv * sv.z + bv.z;
        float o3 = (v[i].w - mean) * inv * sv.w + bv.w;
        size_t base = (size_t)row * DD + c4 * 4;
        float h0, l0, h1, l1;
        split_h(o0, h0, l0); split_h(o1, h1, l1);
        *(uint32_t*)&yhi[base]     = pack_h2(h0, h1);
        *(uint32_t*)&ylo[base]     = pack_h2(l0, l1);
        split_h(o2, h0, l0); split_h(o3, h1, l1);
        *(uint32_t*)&yhi[base + 2] = pack_h2(h0, h1);
        *(uint32_t*)&ylo[base + 2] = pack_h2(l0, l1);
    }
}

// ---------------- layernorm: warp-per-row, no barriers ----------------------
// MODE: 0 = fp32 out, 1 = fp16 hi+lo, 2 = fp16 hi only
template<int MODE>
__global__ __launch_bounds__(256) void ln_kernel(
    const float* __restrict__ x,
    const float* __restrict__ s,
    const float* __restrict__ b,
    float* __restrict__ y,
    __half* __restrict__ yhi,
    __half* __restrict__ ylo)
{
    int lane = threadIdx.x & 31;
    int row  = (blockIdx.x << 3) + (threadIdx.x >> 5);
    const float* xr = x + (size_t)row * DD;

    float4 v[8];
    float sum = 0.f, sq = 0.f;
    #pragma unroll
    for (int i = 0; i < 8; i++) {
        v[i] = ((const float4*)xr)[i * 32 + lane];
        sum += v[i].x + v[i].y + v[i].z + v[i].w;
        sq  += v[i].x*v[i].x + v[i].y*v[i].y + v[i].z*v[i].z + v[i].w*v[i].w;
    }
    #pragma unroll
    for (int o = 16; o > 0; o >>= 1) {
        sum += __shfl_xor_sync(0xffffffffu, sum, o);
        sq  += __shfl_xor_sync(0xffffffffu, sq,  o);
    }
    float mean = sum * (1.f / DD);
    float inv  = rsqrtf(sq * (1.f / DD) - mean * mean + 1e-5f);

    #pragma unroll
    for (int i = 0; i < 8; i++) {
        int c4 = i * 32 + lane;
        float4 sv = ((const float4*)s)[c4];
        float4 bv = ((const float4*)b)[c4];
        float o0 = (v[i].x - mean) * inv * sv.x + bv.x;
        float o1 = (v[i].y - mean) * inv * sv.y + bv.y;
        float o2 = (v[i].z - mean) * inv * sv.z + bv.z;
        float o3 = (v[i].w - mean) * inv * sv.w + bv.w;
        if (MODE == 0) {
            ((float4*)(y + (size_t)row * DD))[c4] = make_float4(o0, o1, o2, o3);
        } else if (MODE == 1) {
            size_t base = (size_t)row * DD + c4 * 4;
            float h0, l0, h1, l1;
            split_h(o0, h0, l0); split_h(o1, h1, l1);
            *(uint32_t*)&yhi[base]     = pack_h2(h0, h1);
            *(uint32_t*)&ylo[base]     = pack_h2(l0, l1);
            split_h(o2, h0, l0); split_h(o3, h1, l1);
            *(uint32_t*)&yhi[base + 2] = pack_h2(h0, h1);
            *(uint32_t*)&ylo[base + 2] = pack_h2(l0, l1);
        } else {
            size_t base = (size_t)row * DD + c4 * 4;
            *(uint32_t*)&yhi[base]     = pack_h2(o0, o1);
            *(uint32_t*)&yhi[base + 2] = pack_h2(o2, o3);
        }
    }
}

// ================= mma.sync fp16 GEMM (256 threads, 8 warps) =================
// K-step 64, 2-stage double buffer, ONE barrier per stage, 2 CTAs/SM.
// ATERMS: 2 = A hi+lo (2 MMAs/k16), 1 = A hi only (1 MMA/k16)
// EPI: 1 = X+acc fp32, 2 = GELU -> fp16 hi only, 3 = fp16 hi/lo
#define GP 144
#define GTILE (128 * GP)              // 18432

__device__ __forceinline__ void fill_cp(uint32_t dst, const __half* g,
                                        int K, int tid)
{
    #pragma unroll
    for (int i = 0; i < 4; i++) {
        int ch = tid + (i << 8);
        int r = ch >> 3, c = ch & 7;
        cp16(dst + r * GP + c * 16,
             (const char*)g + (size_t)r * K * 2 + c * 16);
    }
}

template<int EPI, int ATERMS>
__global__ __launch_bounds__(256, 2) void gemm_mma(
    const __half* __restrict__ Ahi, const __half* __restrict__ Alo,
    const __half* __restrict__ B,
    const float* __restrict__ X, float* __restrict__ C,
    __half* __restrict__ Chi, __half* __restrict__ Clo,
    int M, int N, int K)
{
    constexpr int NT = ATERMS + 1;            // tiles per stage
    constexpr uint32_t STAGE = NT * GTILE;
    constexpr uint32_t BOFF  = ATERMS * GTILE;

    extern __shared__ char sm[];
    uint32_t sb = smem_u32(sm);
    int tid  = threadIdx.x;
    int lane = tid & 31, w = tid >> 5;
    int wm = (w >> 2) * 64, wn = (w & 3) * 32;
    int m0 = blockIdx.y * 128, n0 = blockIdx.x * 128;

    const __half* pAhi = Ahi + (size_t)m0 * K;
    const __half* pAlo = (ATERMS == 2) ? Alo + (size_t)m0 * K : nullptr;
    const __half* pB   = B   + (size_t)n0 * K;

    float acc[4][4][4] = {};
    int S = K >> 6;

    // prologue: stage 0
    fill_cp(sb, pAhi, K, tid);
    if (ATERMS == 2) fill_cp(sb + GTILE, pAlo, K, tid);
    fill_cp(sb + BOFF, pB, K, tid);
    CP_COMMIT();

    int aRow = wm + (lane & 15);
    int aSel = (lane >> 4);
    int bRow = wn + (lane & 7);
    int bSel = ((lane >> 3) & 1);

    for (int s = 0; s < S; s++) {
        CP_WAIT0();
        __syncthreads();

        if (s + 1 < S) {
            uint32_t nbuf = sb + ((s + 1) & 1) * STAGE;
            int k0 = (s + 1) << 6;
            fill_cp(nbuf, pAhi + k0, K, tid);
            if (ATERMS == 2) fill_cp(nbuf + GTILE, pAlo + k0, K, tid);
            fill_cp(nbuf + BOFF, pB + k0, K, tid);
            CP_COMMIT();
        }

        uint32_t buf = sb + (s & 1) * STAGE;
        #pragma unroll
        for (int k16 = 0; k16 < 4; k16++) {
            uint32_t ah[4][4], al[4][4];
            #pragma unroll
            for (int mt = 0; mt < 4; mt++) {
                uint32_t off = (uint32_t)(aRow + mt * 16) * GP +
                               (uint32_t)(k16 * 2 + aSel) * 16;
                ldsm_x4(buf + off, ah[mt][0], ah[mt][1], ah[mt][2], ah[mt][3]);
                if (ATERMS == 2)
                    ldsm_x4(buf + GTILE + off,
                            al[mt][0], al[mt][1], al[mt][2], al[mt][3]);
            }
            uint32_t bh[4][2];
            #pragma unroll
            for (int nt = 0; nt < 4; nt++) {
                uint32_t off = (uint32_t)(bRow + nt * 8) * GP +
                               (uint32_t)(k16 * 2 + bSel) * 16;
                ldsm_x2(buf + BOFF + off, bh[nt][0], bh[nt][1]);
            }
            #pragma unroll
            for (int mt = 0; mt < 4; mt++)
                #pragma unroll
                for (int nt = 0; nt < 4; nt++) {
                    mma_f16(acc[mt][nt], ah[mt], bh[nt]);
                    if (ATERMS == 2) mma_f16(acc[mt][nt], al[mt], bh[nt]);
                }
        }
    }

    #pragma unroll
    for (int mt = 0; mt < 4; mt++) {
        #pragma unroll
        for (int nt = 0; nt < 4; nt++) {
            float* cc = acc[mt][nt];
            int gr = m0 + wm + mt * 16 + (lane >> 2);
            int gc = n0 + wn + nt * 8 + (lane & 3) * 2;
            #pragma unroll
            for (int half = 0; half < 2; half++) {
                size_t base = (size_t)(gr + half * 8) * N + gc;
                float v0 = cc[half * 2], v1 = cc[half * 2 + 1];
                if (EPI == 1) {
                    C[base]     = v0 + X[base];
                    C[base + 1] = v1 + X[base + 1];
                } else if (EPI == 2) {
                    v0 = 0.5f * v0 * (1.f + erff(v0 * 0.70710678118654752f));
                    v1 = 0.5f * v1 * (1.f + erff(v1 * 0.70710678118654752f));
                    *(uint32_t*)&Chi[base] = pack_h2(v0, v1);
                } else {
                    float h0, l0, h1, l1;
                    split_h(v0, h0, l0);
                    split_h(v1, h1, l1);
                    *(uint32_t*)&Chi[base] = pack_h2(h0, h1);
                    *(uint32_t*)&Clo[base] = pack_h2(l0, l1);
                }
            }
        }
    }
}

// ================= tensor-core flash attention ==============================
// QK^T 3-term, PV 2-term (P single fp16, V hi/lo).
#define APITCH 144
#define ATILE (64 * APITCH)
#define ASTAGE (4 * ATILE)
#define ATTN_SMEM (2 * ATILE + 2 * ASTAGE)  // 92160

__device__ __forceinline__ void attn_fill(uint32_t dst,
                                          const __half* ghi,
                                          const __half* glo, int tid)
{
    #pragma unroll
    for (int i = 0; i < 8; i++) {
        int ch = tid + (i << 7);
        int r = (ch & 511) >> 3, c = ch & 7;
        const __half* src = (ch < 512) ? ghi : glo;
        uint32_t d = dst + ((ch < 512) ? 0 : ATILE) + r * APITCH + c * 16;
        cp16(d, (const char*)src + (size_t)r * D3 * 2 + c * 16);
    }
}

__global__ __launch_bounds__(128) void attn_mma(
    const __half* __restrict__ qkv_hi,
    const __half* __restrict__ qkv_lo,
    __half* __restrict__ o_hi,
    __half* __restrict__ o_lo)
{
    extern __shared__ char sm[];
    uint32_t sb = smem_u32(sm);
    int p = blockIdx.x, bh = blockIdx.y;
    int b = bh >> 4, h = bh & 15;
    int tid = threadIdx.x, lane = tid & 31, w = tid >> 5;

    uint32_t sQ = sb;
    uint32_t sS0 = sb + 2 * ATILE;

    for (int sub = 0; sub < 2; sub++) {
        int qt = sub ? (15 - p) : p;

        size_t qrow = (size_t)(b * TT + qt * 64);
        const __half* gq_hi = qkv_hi + qrow * D3 + h * DHH;
        const __half* gq_lo = qkv_lo + qrow * D3 + h * DHH;

        attn_fill(sQ, gq_hi, gq_lo, tid);
        {
            const __half* gk_hi = qkv_hi + (size_t)(b * TT) * D3 + DD + h * DHH;
            const __half* gk_lo = qkv_lo + (size_t)(b * TT) * D3 + DD + h * DHH;
            attn_fill(sS0,             gk_hi, gk_lo, tid);
            attn_fill(sS0 + 2 * ATILE, gk_hi + DD, gk_lo + DD, tid);
        }
        CP_COMMIT();
        CP_WAIT0();
        __syncthreads();

        uint32_t qh[4][4], ql[4][4];
        {
            uint32_t rowoff = (uint32_t)(w * 16 + (lane & 15)) * APITCH;
            uint32_t coloff = (uint32_t)(lane >> 4) * 16;
            #pragma unroll
            for (int kb = 0; kb < 4; kb++) {
                uint32_t off = rowoff + kb * 32 + coloff;
                ldsm_x4(sQ + off,         qh[kb][0], qh[kb][1], qh[kb][2], qh[kb][3]);
                ldsm_x4(sQ + ATILE + off, ql[kb][0], ql[kb][1], ql[kb][2], ql[kb][3]);
            }
        }

        float oacc[8][4] = {};
        float mrow[2] = {-1e30f, -1e30f};
        float lrow[2] = {0.f, 0.f};

        int r0loc = w * 16 + (lane >> 2);
        int r0g = qt * 64 + r0loc;
        int cql = (lane & 3) * 2;

        for (int jt = 0; jt <= qt; jt++) {
            uint32_t buf = sS0 + (jt & 1) * ASTAGE;
            if (jt + 1 <= qt) {
                uint32_t nbuf = sS0 + ((jt + 1) & 1) * ASTAGE;
                size_t krow = (size_t)(b * TT + (jt + 1) * 64);
                const __half* gk_hi = qkv_hi + krow * D3 + DD + h * DHH;
                const __half* gk_lo = qkv_lo + krow * D3 + DD + h * DHH;
                attn_fill(nbuf,             gk_hi, gk_lo, tid);
                attn_fill(nbuf + 2 * ATILE, gk_hi + DD, gk_lo + DD, tid);
                CP_COMMIT();
            }

            float s[8][4] = {};
            #pragma unroll
            for (int kb = 0; kb < 4; kb++) {
                uint32_t kcol = (uint32_t)(((lane >> 3) & 1) * 8 + kb * 16) * 2;
                #pragma unroll
                for (int nt = 0; nt < 8; nt++) {
                    uint32_t off = (uint32_t)(nt * 8 + (lane & 7)) * APITCH + kcol;
                    uint32_t kh0, kh1, kl0, kl1;
                    ldsm_x2(buf + off, kh0, kh1);
                    ldsm_x2(buf + ATILE + off, kl0, kl1);
                    uint32_t bhK[2] = {kh0, kh1}, blK[2] = {kl0, kl1};
                    mma_f16(s[nt], qh[kb], bhK);
                    mma_f16(s[nt], ql[kb], bhK);
                    mma_f16(s[nt], qh[kb], blK);
                }
            }

            bool diag = (jt == qt);
            #pragma unroll
            for (int nt = 0; nt < 8; nt++) {
                int colb = jt * 64 + nt * 8 + cql;
                #pragma unroll
                for (int q = 0; q < 4; q++) {
                    float v = s[nt][q] * 0.125f;
                    if (diag) {
                        int col = colb + (q & 1);
                        int row = r0g + (q >> 1) * 8;
                        if (col > row) v = -1e30f;
                    }
                    s[nt][q] = v;
                }
            }

            float mx0 = -1e30f, mx1 = -1e30f;
            #pragma unroll
            for (int nt = 0; nt < 8; nt++) {
                mx0 = fmaxf(mx0, fmaxf(s[nt][0], s[nt][1]));
                mx1 = fmaxf(mx1, fmaxf(s[nt][2], s[nt][3]));
            }
            mx0 = fmaxf(mx0, __shfl_xor_sync(0xffffffffu, mx0, 1));
            mx0 = fmaxf(mx0, __shfl_xor_sync(0xffffffffu, mx0, 2));
            mx1 = fmaxf(mx1, __shfl_xor_sync(0xffffffffu, mx1, 1));
            mx1 = fmaxf(mx1, __shfl_xor_sync(0xffffffffu, mx1, 2));
            float mn0 = fmaxf(mrow[0], mx0), mn1 = fmaxf(mrow[1], mx1);
            float sum0 = 0.f, sum1 = 0.f;
            #pragma unroll
            for (int nt = 0; nt < 8; nt++) {
                s[nt][0] = __expf(s[nt][0] - mn0);
                s[nt][1] = __expf(s[nt][1] - mn0);
                s[nt][2] = __expf(s[nt][2] - mn1);
                s[nt][3] = __expf(s[nt][3] - mn1);
                sum0 += s[nt][0] + s[nt][1];
                sum1 += s[nt][2] + s[nt][3];
            }
            sum0 += __shfl_xor_sync(0xffffffffu, sum0, 1);
            sum0 += __shfl_xor_sync(0xffffffffu, sum0, 2);
            sum1 += __shfl_xor_sync(0xffffffffu, sum1, 1);
            sum1 += __shfl_xor_sync(0xffffffffu, sum1, 2);
            float a0 = __expf(mrow[0] - mn0), a1 = __expf(mrow[1] - mn1);
            lrow[0] = lrow[0] * a0 + sum0;
            lrow[1] = lrow[1] * a1 + sum1;
            mrow[0] = mn0; mrow[1] = mn1;
            #pragma unroll
            for (int nt = 0; nt < 8; nt++) {
                oacc[nt][0] *= a0; oacc[nt][1] *= a0;
                oacc[nt][2] *= a1; oacc[nt][3] *= a1;
            }

            uint32_t vbase = buf + 2 * ATILE;
            #pragma unroll
            for (int kb = 0; kb < 4; kb++) {
                uint32_t ph[4];
                ph[0] = pack_h2(s[2*kb][0],   s[2*kb][1]);
                ph[1] = pack_h2(s[2*kb][2],   s[2*kb][3]);
                ph[2] = pack_h2(s[2*kb+1][0], s[2*kb+1][1]);
                ph[3] = pack_h2(s[2*kb+1][2], s[2*kb+1][3]);
                uint32_t vrow = (uint32_t)(kb * 16 + (lane & 15)) * APITCH;
                #pragma unroll
                for (int nt = 0; nt < 8; nt++) {
                    uint32_t off = vrow + nt * 16;
                    uint32_t vh0, vh1, vl0, vl1;
                    ldsm_x2t(vbase + off, vh0, vh1);
                    ldsm_x2t(vbase + ATILE + off, vl0, vl1);
                    uint32_t bhV[2] = {vh0, vh1}, blV[2] = {vl0, vl1};
                    mma_f16(oacc[nt], ph, bhV);
                    mma_f16(oacc[nt], ph, blV);
                }
            }

            CP_WAIT0();
            __syncthreads();
        }

        float li0 = 1.f / lrow[0], li1 = 1.f / lrow[1];
        size_t orow0 = (size_t)(b * TT + r0g) * DD + h * DHH;
        #pragma unroll
        for (int nt = 0; nt < 8; nt++) {
            int gc = nt * 8 + cql;
            float v0 = oacc[nt][0] * li0, v1 = oacc[nt][1] * li0;
            float v2 = oacc[nt][2] * li1, v3 = oacc[nt][3] * li1;
            float h0, l0, h1, l1;
            split_h(v0, h0, l0); split_h(v1, h1, l1);
            *(uint32_t*)&o_hi[orow0 + gc] = pack_h2(h0, h1);
            *(uint32_t*)&o_lo[orow0 + gc] = pack_h2(l0, l1);
            split_h(v2, h0, l0); split_h(v3, h1, l1);
            *(uint32_t*)&o_hi[orow0 + 8 * DD + gc] = pack_h2(h0, h1);
            *(uint32_t*)&o_lo[orow0 + 8 * DD + gc] = pack_h2(l0, l1);
        }
    }
}

// ---------------- launcher ---------------------------------------------------
extern "C" void kernel_launch(void* const* d_in, const int* in_sizes, int n_in,
                              void* d_out, int out_size)
{
    const int*   ids  = (const int*)  d_in[0];
    const float* tok  = (const float*)d_in[1];
    const float* pos  = (const float*)d_in[2];
    const float* ln1s = (const float*)d_in[3];
    const float* ln1b = (const float*)d_in[4];
    const float* Wqkv = (const float*)d_in[5];
    const float* Wout = (const float*)d_in[6];
    const float* ln2s = (const float*)d_in[7];
    const float* ln2b = (const float*)d_in[8];
    const float* W1   = (const float*)d_in[9];
    const float* W2   = (const float*)d_in[10];
    const float* lnfs = (const float*)d_in[11];
    const float* lnfb = (const float*)d_in[12];
    float* out = (float*)d_out;

    float *x;
    __half *h_hi, *h_lo, *qkv_hi, *qkv_lo, *o_hi, *o_lo, *a_hi;
    __half *wqT, *woT, *w1T, *w2T;
    cudaGetSymbolAddress((void**)&x,      g_x);
    cudaGetSymbolAddress((void**)&h_hi,   g_h_hi);
    cudaGetSymbolAddress((void**)&h_lo,   g_h_lo);
    cudaGetSymbolAddress((void**)&qkv_hi, g_qkv_hi);
    cudaGetSymbolAddress((void**)&qkv_lo, g_qkv_lo);
    cudaGetSymbolAddress((void**)&o_hi,   g_o_hi);
    cudaGetSymbolAddress((void**)&o_lo,   g_o_lo);
    cudaGetSymbolAddress((void**)&a_hi,   g_a_hi);
    cudaGetSymbolAddress((void**)&wqT,    g_WqkvT);
    cudaGetSymbolAddress((void**)&woT,    g_WoutT);
    cudaGetSymbolAddress((void**)&w1T,    g_W1T);
    cudaGetSymbolAddress((void**)&w2T,    g_W2T);

    const int GSM2 = 2 * 3 * GTILE;   // 110592 (2-term)
    const int GSM1 = 2 * 2 * GTILE;   // 73728  (1-term)

    cudaFuncSetAttribute(attn_mma,
                         cudaFuncAttributeMaxDynamicSharedMemorySize, ATTN_SMEM);
    cudaFuncSetAttribute(gemm_mma<3, 2>,
                         cudaFuncAttributeMaxDynamicSharedMemorySize, GSM2);
    cudaFuncSetAttribute(gemm_mma<1, 2>,
                         cudaFuncAttributeMaxDynamicSharedMemorySize, GSM2);
    cudaFuncSetAttribute(gemm_mma<2, 1>,
                         cudaFuncAttributeMaxDynamicSharedMemorySize, GSM1);
    cudaFuncSetAttribute(gemm_mma<1, 1>,
                         cudaFuncAttributeMaxDynamicSharedMemorySize, GSM1);

    // weight transpose + fp16 convert (4 launches, vectorized)
    dim3 tb(32, 8);
    twk<<<dim3(D3 / 128,   DD / 32,   LL), tb>>>(Wqkv, wqT, DD, D3);
    twk<<<dim3(DD / 128,   DD / 32,   LL), tb>>>(Wout, woT, DD, DD);
    twk<<<dim3(DFFF / 128, DD / 32,   LL), tb>>>(W1, w1T, DD, DFFF);
    twk<<<dim3(DD / 128,   DFFF / 32, LL), tb>>>(W2, w2T, DFFF, DD);

    // fused embed + layer-0 LN1
    embed_ln_kernel<<<MROWS / 8, 256>>>(ids, tok, pos, ln1s, ln1b, x, h_hi, h_lo);

    for (int l = 0; l < LL; l++) {
        if (l > 0)
            ln_kernel<1><<<MROWS / 8, 256>>>(x, ln1s + (size_t)l * DD,
                                             ln1b + (size_t)l * DD,
                                             nullptr, h_hi, h_lo);
        gemm_mma<3, 2><<<dim3(D3 / 128, MROWS / 128), 256, GSM2>>>(
            h_hi, h_lo, wqT + (size_t)l * D3 * DD,
            nullptr, nullptr, qkv_hi, qkv_lo, MROWS, D3, DD);
        attn_mma<<<dim3(TT / 128, BB * HH), 128, ATTN_SMEM>>>(qkv_hi, qkv_lo, o_hi, o_lo);
        gemm_mma<1, 2><<<dim3(DD / 128, MROWS / 128), 256, GSM2>>>(
            o_hi, o_lo, woT + (size_t)l * DD * DD,
            x, x, nullptr, nullptr, MROWS, DD, DD);
        ln_kernel<2><<<MROWS / 8, 256>>>(x, ln2s + (size_t)l * DD,
                                         ln2b + (size_t)l * DD,
                                         nullptr, h_hi, nullptr);
        gemm_mma<2, 1><<<dim3(DFFF / 128, MROWS / 128), 256, GSM1>>>(
            h_hi, nullptr, w1T + (size_t)l * DFFF * DD,
            nullptr, nullptr, a_hi, nullptr, MROWS, DFFF, DD);
        gemm_mma<1, 1><<<dim3(DD / 128, MROWS / 128), 256, GSM1>>>(
            a_hi, nullptr, w2T + (size_t)l * DD * DFFF,
            x, x, nullptr, nullptr, MROWS, DD, DFFF);
    }

    ln_kernel<0><<<MROWS / 8, 256>>>(x, lnfs, lnfb, out, nullptr, nullptr);
}

// round 13
// speedup vs baseline: 2.5008x; 1.2178x over previous
#include <cuda_runtime.h>
#include <cuda_fp16.h>
#include <math.h>
#include <stdint.h>

// Problem constants
#define BB 2
#define TT 1024
#define DD 1024
#define HH 16
#define LL 6
#define DHH 64
#define DFFF 2048
#define MROWS (BB*TT)   // 2048
#define D3 (3*DD)

// ---------------- scratch (device globals) ----------------------------------
__device__ float g_x[MROWS * DD];                              // residual
__device__ __half g_h_hi[MROWS*DD];                            // LN out (hi only)
__device__ __half g_qkv_hi[MROWS*D3],  g_qkv_lo[MROWS*D3];     // qkv hi/lo
__device__ __half g_o_hi[MROWS*DD];                            // attn out (hi only)
__device__ __half g_a_hi[MROWS*DFFF];                          // gelu out (hi only)
// transposed [N,K] fp16 weights
__device__ __half g_WqkvT[LL*D3*DD];
__device__ __half g_WoutT[LL*DD*DD];
__device__ __half g_W1T [LL*DFFF*DD];
__device__ __half g_W2T [LL*DD*DFFF];

// ================= helpers =================
__device__ __forceinline__ uint32_t smem_u32(const void* p){
    uint32_t a;
    asm("{ .reg .u64 t; cvta.to.shared.u64 t, %1; cvt.u32.u64 %0, t; }"
        : "=r"(a) : "l"(p));
    return a;
}
__device__ __forceinline__ void ldsm_x4(uint32_t a, uint32_t& r0, uint32_t& r1,
                                        uint32_t& r2, uint32_t& r3){
    asm volatile("ldmatrix.sync.aligned.m8n8.x4.shared.b16 {%0,%1,%2,%3}, [%4];"
                 : "=r"(r0), "=r"(r1), "=r"(r2), "=r"(r3) : "r"(a));
}
__device__ __forceinline__ void ldsm_x2(uint32_t a, uint32_t& r0, uint32_t& r1){
    asm volatile("ldmatrix.sync.aligned.m8n8.x2.shared.b16 {%0,%1}, [%2];"
                 : "=r"(r0), "=r"(r1) : "r"(a));
}
__device__ __forceinline__ void ldsm_x2t(uint32_t a, uint32_t& r0, uint32_t& r1){
    asm volatile("ldmatrix.sync.aligned.m8n8.x2.trans.shared.b16 {%0,%1}, [%2];"
                 : "=r"(r0), "=r"(r1) : "r"(a));
}
__device__ __forceinline__ void mma_f16(float* c, const uint32_t* a,
                                        const uint32_t* b){
    asm volatile(
        "mma.sync.aligned.m16n8k16.row.col.f32.f16.f16.f32 "
        "{%0,%1,%2,%3}, {%4,%5,%6,%7}, {%8,%9}, {%0,%1,%2,%3};"
        : "+f"(c[0]), "+f"(c[1]), "+f"(c[2]), "+f"(c[3])
        : "r"(a[0]), "r"(a[1]), "r"(a[2]), "r"(a[3]), "r"(b[0]), "r"(b[1]));
}
__device__ __forceinline__ void cp16(uint32_t dst, const void* src){
    asm volatile("cp.async.cg.shared.global [%0], [%1], 16;"
                 :: "r"(dst), "l"(src));
}
#define CP_COMMIT() asm volatile("cp.async.commit_group;" ::: "memory")
#define CP_WAIT0()  asm volatile("cp.async.wait_group 0;" ::: "memory")

__device__ __forceinline__ uint32_t pack_h2(float lo_val, float hi_val){
    __half2 t = __floats2half2_rn(lo_val, hi_val);
    return *(uint32_t*)&t;
}
__device__ __forceinline__ void split_h(float v, float& hi_f, float& lo_f){
    __half h = __float2half_rn(v);
    hi_f = __half2float(h);
    lo_f = v - hi_f;
}

// ---------------- weight transpose + fp16 convert (vectorized) --------------
__global__ void twk(const float* __restrict__ W,
                    __half* __restrict__ out, int K, int N)
{
    __shared__ float t[32][129];
    size_t loff = (size_t)blockIdx.z * K * N;
    const float* Wl = W + loff;
    __half* ol = out + loff;

    int n0 = blockIdx.x * 128, k0 = blockIdx.y * 32;
    int tid = threadIdx.y * 32 + threadIdx.x;

    #pragma unroll
    for (int i = 0; i < 4; i++) {
        int idx = tid + (i << 8);
        int r = idx >> 5, c4 = idx & 31;
        float4 v = *(const float4*)(Wl + (size_t)(k0 + r) * N + n0 + c4 * 4);
        t[r][c4 * 4 + 0] = v.x;
        t[r][c4 * 4 + 1] = v.y;
        t[r][c4 * 4 + 2] = v.z;
        t[r][c4 * 4 + 3] = v.w;
    }
    __syncthreads();

    #pragma unroll
    for (int i = 0; i < 2; i++) {
        int idx = tid + (i << 8);
        int n = idx >> 2, kc = idx & 3;
        __half h[8];
        #pragma unroll
        for (int j = 0; j < 8; j++)
            h[j] = __float2half_rn(t[kc * 8 + j][n]);
        *(uint4*)(ol + (size_t)(n0 + n) * K + k0 + kc * 8) = *(uint4*)h;
    }
}

// ---------------- fused embedding + layer-0 LN1 (warp-per-row, hi only) -----
__global__ __launch_bounds__(256) void embed_ln_kernel(
    const int* __restrict__ ids,
    const float* __restrict__ tok,
    const float* __restrict__ pos,
    const float* __restrict__ s,
    const float* __restrict__ b,
    float* __restrict__ x,
    __half* __restrict__ yhi)
{
    int lane = threadIdx.x & 31;
    int row  = (blockIdx.x << 3) + (threadIdx.x >> 5);
    int t    = row & (TT - 1);
    const float4* tok4 = (const float4*)(tok + (size_t)ids[row] * DD);
    const float4* pos4 = (const float4*)(pos + (size_t)t * DD);

    float4 v[8];
    float sum = 0.f, sq = 0.f;
    #pragma unroll
    for (int i = 0; i < 8; i++) {
        float4 a = tok4[i * 32 + lane];
        float4 p = pos4[i * 32 + lane];
        v[i] = make_float4(a.x + p.x, a.y + p.y, a.z + p.z, a.w + p.w);
        sum += v[i].x + v[i].y + v[i].z + v[i].w;
        sq  += v[i].x*v[i].x + v[i].y*v[i].y + v[i].z*v[i].z + v[i].w*v[i].w;
        ((float4*)(x + (size_t)row * DD))[i * 32 + lane] = v[i];
    }
    #pragma unroll
    for (int o = 16; o > 0; o >>= 1) {
        sum += __shfl_xor_sync(0xffffffffu, sum, o);
        sq  += __shfl_xor_sync(0xffffffffu, sq,  o);
    }
    float mean = sum * (1.f / DD);
    float inv  = rsqrtf(sq * (1.f / DD) - mean * mean + 1e-5f);

    #pragma unroll
    for (int i = 0; i < 8; i++) {
        int c4 = i * 32 + lane;
        float4 sv = ((const float4*)s)[c4];
        float4 bv = ((const float4*)b)[c4];
        float o0 = (v[i].x - mean) * inv * sv.x + bv.x;
        float o1 = (v[i].y - mean) * inv * sv.y + bv.y;
        float o2 = (v[i].z - mean) * inv * sv.z + bv.z;
        float o3 = (v[i].w - mean) * inv * sv.w + bv.w;
        size_t base = (size_t)row * DD + c4 * 4;
        *(uint32_t*)&yhi[base]     = pack_h2(o0, o1);
        *(uint32_t*)&yhi[base + 2] = pack_h2(o2, o3);
    }
}

// ---------------- layernorm: warp-per-row, no barriers ----------------------
// MODE: 0 = fp32 out, 2 = fp16 hi only
template<int MODE>
__global__ __launch_bounds__(256) void ln_kernel(
    const float* __restrict__ x,
    const float* __restrict__ s,
    const float* __restrict__ b,
    float* __restrict__ y,
    __half* __restrict__ yhi)
{
    int lane = threadIdx.x & 31;
    int row  = (blockIdx.x << 3) + (threadIdx.x >> 5);
    const float* xr = x + (size_t)row * DD;

    float4 v[8];
    float sum = 0.f, sq = 0.f;
    #pragma unroll
    for (int i = 0; i < 8; i++) {
        v[i] = ((const float4*)xr)[i * 32 + lane];
        sum += v[i].x + v[i].y + v[i].z + v[i].w;
        sq  += v[i].x*v[i].x + v[i].y*v[i].y + v[i].z*v[i].z + v[i].w*v[i].w;
    }
    #pragma unroll
    for (int o = 16; o > 0; o >>= 1) {
        sum += __shfl_xor_sync(0xffffffffu, sum, o);
        sq  += __shfl_xor_sync(0xffffffffu, sq,  o);
    }
    float mean = sum * (1.f / DD);
    float inv  = rsqrtf(sq * (1.f / DD) - mean * mean + 1e-5f);

    #pragma unroll
    for (int i = 0; i < 8; i++) {
        int c4 = i * 32 + lane;
        float4 sv = ((const float4*)s)[c4];
        float4 bv = ((const float4*)b)[c4];
        float o0 = (v[i].x - mean) * inv * sv.x + bv.x;
        float o1 = (v[i].y - mean) * inv * sv.y + bv.y;
        float o2 = (v[i].z - mean) * inv * sv.z + bv.z;
        float o3 = (v[i].w - mean) * inv * sv.w + bv.w;
        if (MODE == 0) {
            ((float4*)(y + (size_t)row * DD))[c4] = make_float4(o0, o1, o2, o3);
        } else {
            size_t base = (size_t)row * DD + c4 * 4;
            *(uint32_t*)&yhi[base]     = pack_h2(o0, o1);
            *(uint32_t*)&yhi[base + 2] = pack_h2(o2, o3);
        }
    }
}

// ================= mma.sync fp16 GEMM (256 threads, 8 warps) =================
// All GEMMs 1-term: C = epi(A @ B^T), A single fp16, B single fp16.
// K-step 64, 2-stage double buffer, ONE barrier per stage, 2 CTAs/SM.
// EPI: 1 = X+acc fp32, 2 = GELU -> fp16 hi, 3 = fp16 hi/lo split
#define GP 144
#define GTILE (128 * GP)              // 18432
#define GSTAGE (2 * GTILE)            // 36864 (A, B)
#define GSM_TOTAL (2 * GSTAGE)        // 73728 -> 2 CTAs/SM

__device__ __forceinline__ void fill_cp(uint32_t dst, const __half* g,
                                        int K, int tid)
{
    #pragma unroll
    for (int i = 0; i < 4; i++) {
        int ch = tid + (i << 8);
        int r = ch >> 3, c = ch & 7;
        cp16(dst + r * GP + c * 16,
             (const char*)g + (size_t)r * K * 2 + c * 16);
    }
}

template<int EPI>
__global__ __launch_bounds__(256, 2) void gemm_mma(
    const __half* __restrict__ A,
    const __half* __restrict__ B,
    const float* __restrict__ X, float* __restrict__ C,
    __half* __restrict__ Chi, __half* __restrict__ Clo,
    int M, int N, int K)
{
    extern __shared__ char sm[];
    uint32_t sb = smem_u32(sm);
    int tid  = threadIdx.x;
    int lane = tid & 31, w = tid >> 5;
    int wm = (w >> 2) * 64, wn = (w & 3) * 32;
    int m0 = blockIdx.y * 128, n0 = blockIdx.x * 128;

    const __half* pA = A + (size_t)m0 * K;
    const __half* pB = B + (size_t)n0 * K;

    float acc[4][4][4] = {};
    int S = K >> 6;

    fill_cp(sb,         pA, K, tid);
    fill_cp(sb + GTILE, pB, K, tid);
    CP_COMMIT();

    int aRow = wm + (lane & 15);
    int aSel = (lane >> 4);
    int bRow = wn + (lane & 7);
    int bSel = ((lane >> 3) & 1);

    for (int s = 0; s < S; s++) {
        CP_WAIT0();
        __syncthreads();

        if (s + 1 < S) {
            uint32_t nbuf = sb + ((s + 1) & 1) * GSTAGE;
            int k0 = (s + 1) << 6;
            fill_cp(nbuf,         pA + k0, K, tid);
            fill_cp(nbuf + GTILE, pB + k0, K, tid);
            CP_COMMIT();
        }

        uint32_t buf = sb + (s & 1) * GSTAGE;
        #pragma unroll
        for (int k16 = 0; k16 < 4; k16++) {
            uint32_t ah[4][4];
            #pragma unroll
            for (int mt = 0; mt < 4; mt++) {
                uint32_t off = (uint32_t)(aRow + mt * 16) * GP +
                               (uint32_t)(k16 * 2 + aSel) * 16;
                ldsm_x4(buf + off, ah[mt][0], ah[mt][1], ah[mt][2], ah[mt][3]);
            }
            uint32_t bh[4][2];
            #pragma unroll
            for (int nt = 0; nt < 4; nt++) {
                uint32_t off = (uint32_t)(bRow + nt * 8) * GP +
                               (uint32_t)(k16 * 2 + bSel) * 16;
                ldsm_x2(buf + GTILE + off, bh[nt][0], bh[nt][1]);
            }
            #pragma unroll
            for (int mt = 0; mt < 4; mt++)
                #pragma unroll
                for (int nt = 0; nt < 4; nt++)
                    mma_f16(acc[mt][nt], ah[mt], bh[nt]);
        }
    }

    #pragma unroll
    for (int mt = 0; mt < 4; mt++) {
        #pragma unroll
        for (int nt = 0; nt < 4; nt++) {
            float* cc = acc[mt][nt];
            int gr = m0 + wm + mt * 16 + (lane >> 2);
            int gc = n0 + wn + nt * 8 + (lane & 3) * 2;
            #pragma unroll
            for (int half = 0; half < 2; half++) {
                size_t base = (size_t)(gr + half * 8) * N + gc;
                float v0 = cc[half * 2], v1 = cc[half * 2 + 1];
                if (EPI == 1) {
                    C[base]     = v0 + X[base];
                    C[base + 1] = v1 + X[base + 1];
                } else if (EPI == 2) {
                    v0 = 0.5f * v0 * (1.f + erff(v0 * 0.70710678118654752f));
                    v1 = 0.5f * v1 * (1.f + erff(v1 * 0.70710678118654752f));
                    *(uint32_t*)&Chi[base] = pack_h2(v0, v1);
                } else {
                    float h0, l0, h1, l1;
                    split_h(v0, h0, l0);
                    split_h(v1, h1, l1);
                    *(uint32_t*)&Chi[base] = pack_h2(h0, h1);
                    *(uint32_t*)&Clo[base] = pack_h2(l0, l1);
                }
            }
        }
    }
}

// ================= tensor-core flash attention ==============================
// QK^T 3-term, PV 2-term (P single fp16, V hi/lo). Output hi only.
#define APITCH 144
#define ATILE (64 * APITCH)
#define ASTAGE (4 * ATILE)
#define ATTN_SMEM (2 * ATILE + 2 * ASTAGE)  // 92160

__device__ __forceinline__ void attn_fill(uint32_t dst,
                                          const __half* ghi,
                                          const __half* glo, int tid)
{
    #pragma unroll
    for (int i = 0; i < 8; i++) {
        int ch = tid + (i << 7);
        int r = (ch & 511) >> 3, c = ch & 7;
        const __half* src = (ch < 512) ? ghi : glo;
        uint32_t d = dst + ((ch < 512) ? 0 : ATILE) + r * APITCH + c * 16;
        cp16(d, (const char*)src + (size_t)r * D3 * 2 + c * 16);
    }
}

__global__ __launch_bounds__(128) void attn_mma(
    const __half* __restrict__ qkv_hi,
    const __half* __restrict__ qkv_lo,
    __half* __restrict__ o_hi)
{
    extern __shared__ char sm[];
    uint32_t sb = smem_u32(sm);
    int p = blockIdx.x, bh = blockIdx.y;
    int b = bh >> 4, h = bh & 15;
    int tid = threadIdx.x, lane = tid & 31, w = tid >> 5;

    uint32_t sQ = sb;
    uint32_t sS0 = sb + 2 * ATILE;

    for (int sub = 0; sub < 2; sub++) {
        int qt = sub ? (15 - p) : p;

        size_t qrow = (size_t)(b * TT + qt * 64);
        const __half* gq_hi = qkv_hi + qrow * D3 + h * DHH;
        const __half* gq_lo = qkv_lo + qrow * D3 + h * DHH;

        attn_fill(sQ, gq_hi, gq_lo, tid);
        {
            const __half* gk_hi = qkv_hi + (size_t)(b * TT) * D3 + DD + h * DHH;
            const __half* gk_lo = qkv_lo + (size_t)(b * TT) * D3 + DD + h * DHH;
            attn_fill(sS0,             gk_hi, gk_lo, tid);
            attn_fill(sS0 + 2 * ATILE, gk_hi + DD, gk_lo + DD, tid);
        }
        CP_COMMIT();
        CP_WAIT0();
        __syncthreads();

        uint32_t qh[4][4], ql[4][4];
        {
            uint32_t rowoff = (uint32_t)(w * 16 + (lane & 15)) * APITCH;
            uint32_t coloff = (uint32_t)(lane >> 4) * 16;
            #pragma unroll
            for (int kb = 0; kb < 4; kb++) {
                uint32_t off = rowoff + kb * 32 + coloff;
                ldsm_x4(sQ + off,         qh[kb][0], qh[kb][1], qh[kb][2], qh[kb][3]);
                ldsm_x4(sQ + ATILE + off, ql[kb][0], ql[kb][1], ql[kb][2], ql[kb][3]);
            }
        }

        float oacc[8][4] = {};
        float mrow[2] = {-1e30f, -1e30f};
        float lrow[2] = {0.f, 0.f};

        int r0loc = w * 16 + (lane >> 2);
        int r0g = qt * 64 + r0loc;
        int cql = (lane & 3) * 2;

        for (int jt = 0; jt <= qt; jt++) {
            uint32_t buf = sS0 + (jt & 1) * ASTAGE;
            if (jt + 1 <= qt) {
                uint32_t nbuf = sS0 + ((jt + 1) & 1) * ASTAGE;
                size_t krow = (size_t)(b * TT + (jt + 1) * 64);
                const __half* gk_hi = qkv_hi + krow * D3 + DD + h * DHH;
                const __half* gk_lo = qkv_lo + krow * D3 + DD + h * DHH;
                attn_fill(nbuf,             gk_hi, gk_lo, tid);
                attn_fill(nbuf + 2 * ATILE, gk_hi + DD, gk_lo + DD, tid);
                CP_COMMIT();
            }

            float s[8][4] = {};
            #pragma unroll
            for (int kb = 0; kb < 4; kb++) {
                uint32_t kcol = (uint32_t)(((lane >> 3) & 1) * 8 + kb * 16) * 2;
                #pragma unroll
                for (int nt = 0; nt < 8; nt++) {
                    uint32_t off = (uint32_t)(nt * 8 + (lane & 7)) * APITCH + kcol;
                    uint32_t kh0, kh1, kl0, kl1;
                    ldsm_x2(buf + off, kh0, kh1);
                    ldsm_x2(buf + ATILE + off, kl0, kl1);
                    uint32_t bhK[2] = {kh0, kh1}, blK[2] = {kl0, kl1};
                    mma_f16(s[nt], qh[kb], bhK);
                    mma_f16(s[nt], ql[kb], bhK);
                    mma_f16(s[nt], qh[kb], blK);
                }
            }

            bool diag = (jt == qt);
            #pragma unroll
            for (int nt = 0; nt < 8; nt++) {
                int colb = jt * 64 + nt * 8 + cql;
                #pragma unroll
                for (int q = 0; q < 4; q++) {
                    float v = s[nt][q] * 0.125f;
                    if (diag) {
                        int col = colb + (q & 1);
                        int row = r0g + (q >> 1) * 8;
                        if (col > row) v = -1e30f;
                    }
                    s[nt][q] = v;
                }
            }

            float mx0 = -1e30f, mx1 = -1e30f;
            #pragma unroll
            for (int nt = 0; nt < 8; nt++) {
                mx0 = fmaxf(mx0, fmaxf(s[nt][0], s[nt][1]));
                mx1 = fmaxf(mx1, fmaxf(s[nt][2], s[nt][3]));
            }
            mx0 = fmaxf(mx0, __shfl_xor_sync(0xffffffffu, mx0, 1));
            mx0 = fmaxf(mx0, __shfl_xor_sync(0xffffffffu, mx0, 2));
            mx1 = fmaxf(mx1, __shfl_xor_sync(0xffffffffu, mx1, 1));
            mx1 = fmaxf(mx1, __shfl_xor_sync(0xffffffffu, mx1, 2));
            float mn0 = fmaxf(mrow[0], mx0), mn1 = fmaxf(mrow[1], mx1);
            float sum0 = 0.f, sum1 = 0.f;
            #pragma unroll
            for (int nt = 0; nt < 8; nt++) {
                s[nt][0] = __expf(s[nt][0] - mn0);
                s[nt][1] = __expf(s[nt][1] - mn0);
                s[nt][2] = __expf(s[nt][2] - mn1);
                s[nt][3] = __expf(s[nt][3] - mn1);
                sum0 += s[nt][0] + s[nt][1];
                sum1 += s[nt][2] + s[nt][3];
            }
            sum0 += __shfl_xor_sync(0xffffffffu, sum0, 1);
            sum0 += __shfl_xor_sync(0xffffffffu, sum0, 2);
            sum1 += __shfl_xor_sync(0xffffffffu, sum1, 1);
            sum1 += __shfl_xor_sync(0xffffffffu, sum1, 2);
            float a0 = __expf(mrow[0] - mn0), a1 = __expf(mrow[1] - mn1);
            lrow[0] = lrow[0] * a0 + sum0;
            lrow[1] = lrow[1] * a1 + sum1;
            mrow[0] = mn0; mrow[1] = mn1;
            #pragma unroll
            for (int nt = 0; nt < 8; nt++) {
                oacc[nt][0] *= a0; oacc[nt][1] *= a0;
                oacc[nt][2] *= a1; oacc[nt][3] *= a1;
            }

            uint32_t vbase = buf + 2 * ATILE;
            #pragma unroll
            for (int kb = 0; kb < 4; kb++) {
                uint32_t ph[4];
                ph[0] = pack_h2(s[2*kb][0],   s[2*kb][1]);
                ph[1] = pack_h2(s[2*kb][2],   s[2*kb][3]);
                ph[2] = pack_h2(s[2*kb+1][0], s[2*kb+1][1]);
                ph[3] = pack_h2(s[2*kb+1][2], s[2*kb+1][3]);
                uint32_t vrow = (uint32_t)(kb * 16 + (lane & 15)) * APITCH;
                #pragma unroll
                for (int nt = 0; nt < 8; nt++) {
                    uint32_t off = vrow + nt * 16;
                    uint32_t vh0, vh1, vl0, vl1;
                    ldsm_x2t(vbase + off, vh0, vh1);
                    ldsm_x2t(vbase + ATILE + off, vl0, vl1);
                    uint32_t bhV[2] = {vh0, vh1}, blV[2] = {vl0, vl1};
                    mma_f16(oacc[nt], ph, bhV);
                    mma_f16(oacc[nt], ph, blV);
                }
            }

            CP_WAIT0();
            __syncthreads();
        }

        float li0 = 1.f / lrow[0], li1 = 1.f / lrow[1];
        size_t orow0 = (size_t)(b * TT + r0g) * DD + h * DHH;
        #pragma unroll
        for (int nt = 0; nt < 8; nt++) {
            int gc = nt * 8 + cql;
            *(uint32_t*)&o_hi[orow0 + gc] =
                pack_h2(oacc[nt][0] * li0, oacc[nt][1] * li0);
            *(uint32_t*)&o_hi[orow0 + 8 * DD + gc] =
                pack_h2(oacc[nt][2] * li1, oacc[nt][3] * li1);
        }
    }
}

// ---------------- launcher ---------------------------------------------------
extern "C" void kernel_launch(void* const* d_in, const int* in_sizes, int n_in,
                              void* d_out, int out_size)
{
    const int*   ids  = (const int*)  d_in[0];
    const float* tok  = (const float*)d_in[1];
    const float* pos  = (const float*)d_in[2];
    const float* ln1s = (const float*)d_in[3];
    const float* ln1b = (const float*)d_in[4];
    const float* Wqkv = (const float*)d_in[5];
    const float* Wout = (const float*)d_in[6];
    const float* ln2s = (const float*)d_in[7];
    const float* ln2b = (const float*)d_in[8];
    const float* W1   = (const float*)d_in[9];
    const float* W2   = (const float*)d_in[10];
    const float* lnfs = (const float*)d_in[11];
    const float* lnfb = (const float*)d_in[12];
    float* out = (float*)d_out;

    float *x;
    __half *h_hi, *qkv_hi, *qkv_lo, *o_hi, *a_hi;
    __half *wqT, *woT, *w1T, *w2T;
    cudaGetSymbolAddress((void**)&x,      g_x);
    cudaGetSymbolAddress((void**)&h_hi,   g_h_hi);
    cudaGetSymbolAddress((void**)&qkv_hi, g_qkv_hi);
    cudaGetSymbolAddress((void**)&qkv_lo, g_qkv_lo);
    cudaGetSymbolAddress((void**)&o_hi,   g_o_hi);
    cudaGetSymbolAddress((void**)&a_hi,   g_a_hi);
    cudaGetSymbolAddress((void**)&wqT,    g_WqkvT);
    cudaGetSymbolAddress((void**)&woT,    g_WoutT);
    cudaGetSymbolAddress((void**)&w1T,    g_W1T);
    cudaGetSymbolAddress((void**)&w2T,    g_W2T);

    cudaFuncSetAttribute(attn_mma,
                         cudaFuncAttributeMaxDynamicSharedMemorySize, ATTN_SMEM);
    cudaFuncSetAttribute(gemm_mma<1>,
                         cudaFuncAttributeMaxDynamicSharedMemorySize, GSM_TOTAL);
    cudaFuncSetAttribute(gemm_mma<2>,
                         cudaFuncAttributeMaxDynamicSharedMemorySize, GSM_TOTAL);
    cudaFuncSetAttribute(gemm_mma<3>,
                         cudaFuncAttributeMaxDynamicSharedMemorySize, GSM_TOTAL);

    // weight transpose + fp16 convert (4 launches, vectorized)
    dim3 tb(32, 8);
    twk<<<dim3(D3 / 128,   DD / 32,   LL), tb>>>(Wqkv, wqT, DD, D3);
    twk<<<dim3(DD / 128,   DD / 32,   LL), tb>>>(Wout, woT, DD, DD);
    twk<<<dim3(DFFF / 128, DD / 32,   LL), tb>>>(W1, w1T, DD, DFFF);
    twk<<<dim3(DD / 128,   DFFF / 32, LL), tb>>>(W2, w2T, DFFF, DD);

    // fused embed + layer-0 LN1 (hi only)
    embed_ln_kernel<<<MROWS / 8, 256>>>(ids, tok, pos, ln1s, ln1b, x, h_hi);

    for (int l = 0; l < LL; l++) {
        if (l > 0)
            ln_kernel<2><<<MROWS / 8, 256>>>(x, ln1s + (size_t)l * DD,
                                             ln1b + (size_t)l * DD,
                                             nullptr, h_hi);
        gemm_mma<3><<<dim3(D3 / 128, MROWS / 128), 256, GSM_TOTAL>>>(
            h_hi, wqT + (size_t)l * D3 * DD,
            nullptr, nullptr, qkv_hi, qkv_lo, MROWS, D3, DD);
        attn_mma<<<dim3(TT / 128, BB * HH), 128, ATTN_SMEM>>>(qkv_hi, qkv_lo, o_hi);
        gemm_mma<1><<<dim3(DD / 128, MROWS / 128), 256, GSM_TOTAL>>>(
            o_hi, woT + (size_t)l * DD * DD,
            x, x, nullptr, nullptr, MROWS, DD, DD);
        ln_kernel<2><<<MROWS / 8, 256>>>(x, ln2s + (size_t)l * DD,
                                         ln2b + (size_t)l * DD,
                                         nullptr, h_hi);
        gemm_mma<2><<<dim3(DFFF / 128, MROWS / 128), 256, GSM_TOTAL>>>(
            h_hi, w1T + (size_t)l * DFFF * DD,
            nullptr, nullptr, a_hi, nullptr, MROWS, DFFF, DD);
        gemm_mma<1><<<dim3(DD / 128, MROWS / 128), 256, GSM_TOTAL>>>(
            a_hi, w2T + (size_t)l * DD * DFFF,
            x, x, nullptr, nullptr, MROWS, DD, DFFF);
    }

    ln_kernel<0><<<MROWS / 8, 256>>>(x, lnfs, lnfb, out, nullptr);
}

// round 14
// speedup vs baseline: 2.6640x; 1.0653x over previous
#include <cuda_runtime.h>
#include <cuda_fp16.h>
#include <math.h>
#include <stdint.h>

// Problem constants
#define BB 2
#define TT 1024
#define DD 1024
#define HH 16
#define LL 6
#define DHH 64
#define DFFF 2048
#define MROWS (BB*TT)   // 2048
#define D3 (3*DD)

// ---------------- scratch (device globals) ----------------------------------
__device__ float g_x[MROWS * DD];                              // residual
__device__ __half g_h_hi[MROWS*DD];                            // LN out (hi only)
__device__ __half g_qkv_hi[MROWS*D3],  g_qkv_lo[MROWS*D3];     // qkv (lo: V only)
__device__ __half g_o_hi[MROWS*DD];                            // attn out (hi only)
__device__ __half g_a_hi[MROWS*DFFF];                          // gelu out (hi only)
// transposed [N,K] fp16 weights
__device__ __half g_WqkvT[LL*D3*DD];
__device__ __half g_WoutT[LL*DD*DD];
__device__ __half g_W1T [LL*DFFF*DD];
__device__ __half g_W2T [LL*DD*DFFF];

// ================= helpers =================
__device__ __forceinline__ uint32_t smem_u32(const void* p){
    uint32_t a;
    asm("{ .reg .u64 t; cvta.to.shared.u64 t, %1; cvt.u32.u64 %0, t; }"
        : "=r"(a) : "l"(p));
    return a;
}
__device__ __forceinline__ void ldsm_x4(uint32_t a, uint32_t& r0, uint32_t& r1,
                                        uint32_t& r2, uint32_t& r3){
    asm volatile("ldmatrix.sync.aligned.m8n8.x4.shared.b16 {%0,%1,%2,%3}, [%4];"
                 : "=r"(r0), "=r"(r1), "=r"(r2), "=r"(r3) : "r"(a));
}
__device__ __forceinline__ void ldsm_x2(uint32_t a, uint32_t& r0, uint32_t& r1){
    asm volatile("ldmatrix.sync.aligned.m8n8.x2.shared.b16 {%0,%1}, [%2];"
                 : "=r"(r0), "=r"(r1) : "r"(a));
}
__device__ __forceinline__ void ldsm_x2t(uint32_t a, uint32_t& r0, uint32_t& r1){
    asm volatile("ldmatrix.sync.aligned.m8n8.x2.trans.shared.b16 {%0,%1}, [%2];"
                 : "=r"(r0), "=r"(r1) : "r"(a));
}
__device__ __forceinline__ void mma_f16(float* c, const uint32_t* a,
                                        const uint32_t* b){
    asm volatile(
        "mma.sync.aligned.m16n8k16.row.col.f32.f16.f16.f32 "
        "{%0,%1,%2,%3}, {%4,%5,%6,%7}, {%8,%9}, {%0,%1,%2,%3};"
        : "+f"(c[0]), "+f"(c[1]), "+f"(c[2]), "+f"(c[3])
        : "r"(a[0]), "r"(a[1]), "r"(a[2]), "r"(a[3]), "r"(b[0]), "r"(b[1]));
}
__device__ __forceinline__ void cp16(uint32_t dst, const void* src){
    asm volatile("cp.async.cg.shared.global [%0], [%1], 16;"
                 :: "r"(dst), "l"(src));
}
#define CP_COMMIT() asm volatile("cp.async.commit_group;" ::: "memory")
#define CP_WAIT0()  asm volatile("cp.async.wait_group 0;" ::: "memory")

__device__ __forceinline__ uint32_t pack_h2(float lo_val, float hi_val){
    __half2 t = __floats2half2_rn(lo_val, hi_val);
    return *(uint32_t*)&t;
}
__device__ __forceinline__ void split_h(float v, float& hi_f, float& lo_f){
    __half h = __float2half_rn(v);
    hi_f = __half2float(h);
    lo_f = v - hi_f;
}

// ---------------- weight transpose + fp16 convert (vectorized) --------------
__global__ void twk(const float* __restrict__ W,
                    __half* __restrict__ out, int K, int N)
{
    __shared__ float t[32][129];
    size_t loff = (size_t)blockIdx.z * K * N;
    const float* Wl = W + loff;
    __half* ol = out + loff;

    int n0 = blockIdx.x * 128, k0 = blockIdx.y * 32;
    int tid = threadIdx.y * 32 + threadIdx.x;

    #pragma unroll
    for (int i = 0; i < 4; i++) {
        int idx = tid + (i << 8);
        int r = idx >> 5, c4 = idx & 31;
        float4 v = *(const float4*)(Wl + (size_t)(k0 + r) * N + n0 + c4 * 4);
        t[r][c4 * 4 + 0] = v.x;
        t[r][c4 * 4 + 1] = v.y;
        t[r][c4 * 4 + 2] = v.z;
        t[r][c4 * 4 + 3] = v.w;
    }
    __syncthreads();

    #pragma unroll
    for (int i = 0; i < 2; i++) {
        int idx = tid + (i << 8);
        int n = idx >> 2, kc = idx & 3;
        __half h[8];
        #pragma unroll
        for (int j = 0; j < 8; j++)
            h[j] = __float2half_rn(t[kc * 8 + j][n]);
        *(uint4*)(ol + (size_t)(n0 + n) * K + k0 + kc * 8) = *(uint4*)h;
    }
}

// ---------------- fused embedding + layer-0 LN1 (warp-per-row, hi only) -----
__global__ __launch_bounds__(256) void embed_ln_kernel(
    const int* __restrict__ ids,
    const float* __restrict__ tok,
    const float* __restrict__ pos,
    const float* __restrict__ s,
    const float* __restrict__ b,
    float* __restrict__ x,
    __half* __restrict__ yhi)
{
    int lane = threadIdx.x & 31;
    int row  = (blockIdx.x << 3) + (threadIdx.x >> 5);
    int t    = row & (TT - 1);
    const float4* tok4 = (const float4*)(tok + (size_t)ids[row] * DD);
    const float4* pos4 = (const float4*)(pos + (size_t)t * DD);

    float4 v[8];
    float sum = 0.f, sq = 0.f;
    #pragma unroll
    for (int i = 0; i < 8; i++) {
        float4 a = tok4[i * 32 + lane];
        float4 p = pos4[i * 32 + lane];
        v[i] = make_float4(a.x + p.x, a.y + p.y, a.z + p.z, a.w + p.w);
        sum += v[i].x + v[i].y + v[i].z + v[i].w;
        sq  += v[i].x*v[i].x + v[i].y*v[i].y + v[i].z*v[i].z + v[i].w*v[i].w;
        ((float4*)(x + (size_t)row * DD))[i * 32 + lane] = v[i];
    }
    #pragma unroll
    for (int o = 16; o > 0; o >>= 1) {
        sum += __shfl_xor_sync(0xffffffffu, sum, o);
        sq  += __shfl_xor_sync(0xffffffffu, sq,  o);
    }
    float mean = sum * (1.f / DD);
    float inv  = rsqrtf(sq * (1.f / DD) - mean * mean + 1e-5f);

    #pragma unroll
    for (int i = 0; i < 8; i++) {
        int c4 = i * 32 + lane;
        float4 sv = ((const float4*)s)[c4];
        float4 bv = ((const float4*)b)[c4];
        float o0 = (v[i].x - mean) * inv * sv.x + bv.x;
        float o1 = (v[i].y - mean) * inv * sv.y + bv.y;
        float o2 = (v[i].z - mean) * inv * sv.z + bv.z;
        float o3 = (v[i].w - mean) * inv * sv.w + bv.w;
        size_t base = (size_t)row * DD + c4 * 4;
        *(uint32_t*)&yhi[base]     = pack_h2(o0, o1);
        *(uint32_t*)&yhi[base + 2] = pack_h2(o2, o3);
    }
}

// ---------------- layernorm: warp-per-row, no barriers ----------------------
// MODE: 0 = fp32 out, 2 = fp16 hi only
template<int MODE>
__global__ __launch_bounds__(256) void ln_kernel(
    const float* __restrict__ x,
    const float* __restrict__ s,
    const float* __restrict__ b,
    float* __restrict__ y,
    __half* __restrict__ yhi)
{
    int lane = threadIdx.x & 31;
    int row  = (blockIdx.x << 3) + (threadIdx.x >> 5);
    const float* xr = x + (size_t)row * DD;

    float4 v[8];
    float sum = 0.f, sq = 0.f;
    #pragma unroll
    for (int i = 0; i < 8; i++) {
        v[i] = ((const float4*)xr)[i * 32 + lane];
        sum += v[i].x + v[i].y + v[i].z + v[i].w;
        sq  += v[i].x*v[i].x + v[i].y*v[i].y + v[i].z*v[i].z + v[i].w*v[i].w;
    }
    #pragma unroll
    for (int o = 16; o > 0; o >>= 1) {
        sum += __shfl_xor_sync(0xffffffffu, sum, o);
        sq  += __shfl_xor_sync(0xffffffffu, sq,  o);
    }
    float mean = sum * (1.f / DD);
    float inv  = rsqrtf(sq * (1.f / DD) - mean * mean + 1e-5f);

    #pragma unroll
    for (int i = 0; i < 8; i++) {
        int c4 = i * 32 + lane;
        float4 sv = ((const float4*)s)[c4];
        float4 bv = ((const float4*)b)[c4];
        float o0 = (v[i].x - mean) * inv * sv.x + bv.x;
        float o1 = (v[i].y - mean) * inv * sv.y + bv.y;
        float o2 = (v[i].z - mean) * inv * sv.z + bv.z;
        float o3 = (v[i].w - mean) * inv * sv.w + bv.w;
        if (MODE == 0) {
            ((float4*)(y + (size_t)row * DD))[c4] = make_float4(o0, o1, o2, o3);
        } else {
            size_t base = (size_t)row * DD + c4 * 4;
            *(uint32_t*)&yhi[base]     = pack_h2(o0, o1);
            *(uint32_t*)&yhi[base + 2] = pack_h2(o2, o3);
        }
    }
}

// ================= mma.sync fp16 GEMM (256 threads, 8 warps) =================
// 1-term: C = epi(A @ B^T). K-step 64, 2-stage, ONE barrier/stage, 2 CTAs/SM.
// EPI: 1 = X+acc fp32, 2 = GELU -> fp16 hi, 3 = fp16 hi (+lo only for n>=2*DD)
#define GP 144
#define GTILE (128 * GP)              // 18432
#define GSTAGE (2 * GTILE)            // 36864 (A, B)
#define GSM_TOTAL (2 * GSTAGE)        // 73728 -> 2 CTAs/SM

__device__ __forceinline__ void fill_cp(uint32_t dst, const __half* g,
                                        int K, int tid)
{
    #pragma unroll
    for (int i = 0; i < 4; i++) {
        int ch = tid + (i << 8);
        int r = ch >> 3, c = ch & 7;
        cp16(dst + r * GP + c * 16,
             (const char*)g + (size_t)r * K * 2 + c * 16);
    }
}

template<int EPI>
__global__ __launch_bounds__(256, 2) void gemm_mma(
    const __half* __restrict__ A,
    const __half* __restrict__ B,
    const float* __restrict__ X, float* __restrict__ C,
    __half* __restrict__ Chi, __half* __restrict__ Clo,
    int M, int N, int K)
{
    extern __shared__ char sm[];
    uint32_t sb = smem_u32(sm);
    int tid  = threadIdx.x;
    int lane = tid & 31, w = tid >> 5;
    int wm = (w >> 2) * 64, wn = (w & 3) * 32;
    int m0 = blockIdx.y * 128, n0 = blockIdx.x * 128;

    const __half* pA = A + (size_t)m0 * K;
    const __half* pB = B + (size_t)n0 * K;

    float acc[4][4][4] = {};
    int S = K >> 6;

    fill_cp(sb,         pA, K, tid);
    fill_cp(sb + GTILE, pB, K, tid);
    CP_COMMIT();

    int aRow = wm + (lane & 15);
    int aSel = (lane >> 4);
    int bRow = wn + (lane & 7);
    int bSel = ((lane >> 3) & 1);

    for (int s = 0; s < S; s++) {
        CP_WAIT0();
        __syncthreads();

        if (s + 1 < S) {
            uint32_t nbuf = sb + ((s + 1) & 1) * GSTAGE;
            int k0 = (s + 1) << 6;
            fill_cp(nbuf,         pA + k0, K, tid);
            fill_cp(nbuf + GTILE, pB + k0, K, tid);
            CP_COMMIT();
        }

        uint32_t buf = sb + (s & 1) * GSTAGE;
        #pragma unroll
        for (int k16 = 0; k16 < 4; k16++) {
            uint32_t ah[4][4];
            #pragma unroll
            for (int mt = 0; mt < 4; mt++) {
                uint32_t off = (uint32_t)(aRow + mt * 16) * GP +
                               (uint32_t)(k16 * 2 + aSel) * 16;
                ldsm_x4(buf + off, ah[mt][0], ah[mt][1], ah[mt][2], ah[mt][3]);
            }
            uint32_t bh[4][2];
            #pragma unroll
            for (int nt = 0; nt < 4; nt++) {
                uint32_t off = (uint32_t)(bRow + nt * 8) * GP +
                               (uint32_t)(k16 * 2 + bSel) * 16;
                ldsm_x2(buf + GTILE + off, bh[nt][0], bh[nt][1]);
            }
            #pragma unroll
            for (int mt = 0; mt < 4; mt++)
                #pragma unroll
                for (int nt = 0; nt < 4; nt++)
                    mma_f16(acc[mt][nt], ah[mt], bh[nt]);
        }
    }

    bool wantLo = (EPI == 3) && (n0 >= 2 * DD);   // lo needed only for V third
    #pragma unroll
    for (int mt = 0; mt < 4; mt++) {
        #pragma unroll
        for (int nt = 0; nt < 4; nt++) {
            float* cc = acc[mt][nt];
            int gr = m0 + wm + mt * 16 + (lane >> 2);
            int gc = n0 + wn + nt * 8 + (lane & 3) * 2;
            #pragma unroll
            for (int half = 0; half < 2; half++) {
                size_t base = (size_t)(gr + half * 8) * N + gc;
                float v0 = cc[half * 2], v1 = cc[half * 2 + 1];
                if (EPI == 1) {
                    C[base]     = v0 + X[base];
                    C[base + 1] = v1 + X[base + 1];
                } else if (EPI == 2) {
                    v0 = 0.5f * v0 * (1.f + erff(v0 * 0.70710678118654752f));
                    v1 = 0.5f * v1 * (1.f + erff(v1 * 0.70710678118654752f));
                    *(uint32_t*)&Chi[base] = pack_h2(v0, v1);
                } else {
                    float h0, l0, h1, l1;
                    split_h(v0, h0, l0);
                    split_h(v1, h1, l1);
                    *(uint32_t*)&Chi[base] = pack_h2(h0, h1);
                    if (wantLo)
                        *(uint32_t*)&Clo[base] = pack_h2(l0, l1);
                }
            }
        }
    }
}

// ================= tensor-core flash attention ==============================
// QK^T 1-term (Q,K single fp16), PV 2-term (P fp16, V hi/lo). Output hi only.
#define APITCH 144
#define ATILE (64 * APITCH)
#define ASTAGE (3 * ATILE)                  // Khi, Vhi, Vlo
#define ATTN_SMEM (ATILE + 2 * ASTAGE)      // 64512

// fill one 64x128B tile: 512 chunks, 128 threads -> 4 each
__device__ __forceinline__ void attn_fill1(uint32_t dst, const __half* g,
                                           int tid)
{
    #pragma unroll
    for (int i = 0; i < 4; i++) {
        int ch = tid + (i << 7);
        int r = ch >> 3, c = ch & 7;
        cp16(dst + r * APITCH + c * 16,
             (const char*)g + (size_t)r * D3 * 2 + c * 16);
    }
}

__global__ __launch_bounds__(128) void attn_mma(
    const __half* __restrict__ qkv_hi,
    const __half* __restrict__ qkv_lo,
    __half* __restrict__ o_hi)
{
    extern __shared__ char sm[];
    uint32_t sb = smem_u32(sm);
    int p = blockIdx.x, bh = blockIdx.y;
    int b = bh >> 4, h = bh & 15;
    int tid = threadIdx.x, lane = tid & 31, w = tid >> 5;

    uint32_t sQ = sb;
    uint32_t sS0 = sb + ATILE;

    for (int sub = 0; sub < 2; sub++) {
        int qt = sub ? (15 - p) : p;

        size_t qrow = (size_t)(b * TT + qt * 64);
        const __half* gq = qkv_hi + qrow * D3 + h * DHH;

        attn_fill1(sQ, gq, tid);
        {
            size_t krow = (size_t)(b * TT);
            attn_fill1(sS0,             qkv_hi + krow * D3 + DD + h * DHH, tid);
            attn_fill1(sS0 + ATILE,     qkv_hi + krow * D3 + 2 * DD + h * DHH, tid);
            attn_fill1(sS0 + 2 * ATILE, qkv_lo + krow * D3 + 2 * DD + h * DHH, tid);
        }
        CP_COMMIT();
        CP_WAIT0();
        __syncthreads();

        uint32_t qh[4][4];
        {
            uint32_t rowoff = (uint32_t)(w * 16 + (lane & 15)) * APITCH;
            uint32_t coloff = (uint32_t)(lane >> 4) * 16;
            #pragma unroll
            for (int kb = 0; kb < 4; kb++) {
                uint32_t off = rowoff + kb * 32 + coloff;
                ldsm_x4(sQ + off, qh[kb][0], qh[kb][1], qh[kb][2], qh[kb][3]);
            }
        }

        float oacc[8][4] = {};
        float mrow[2] = {-1e30f, -1e30f};
        float lrow[2] = {0.f, 0.f};

        int r0loc = w * 16 + (lane >> 2);
        int r0g = qt * 64 + r0loc;
        int cql = (lane & 3) * 2;

        for (int jt = 0; jt <= qt; jt++) {
            uint32_t buf = sS0 + (jt & 1) * ASTAGE;
            if (jt + 1 <= qt) {
                uint32_t nbuf = sS0 + ((jt + 1) & 1) * ASTAGE;
                size_t krow = (size_t)(b * TT + (jt + 1) * 64);
                attn_fill1(nbuf,             qkv_hi + krow * D3 + DD + h * DHH, tid);
                attn_fill1(nbuf + ATILE,     qkv_hi + krow * D3 + 2 * DD + h * DHH, tid);
                attn_fill1(nbuf + 2 * ATILE, qkv_lo + krow * D3 + 2 * DD + h * DHH, tid);
                CP_COMMIT();
            }

            float s[8][4] = {};
            #pragma unroll
            for (int kb = 0; kb < 4; kb++) {
                uint32_t kcol = (uint32_t)(((lane >> 3) & 1) * 8 + kb * 16) * 2;
                #pragma unroll
                for (int nt = 0; nt < 8; nt++) {
                    uint32_t off = (uint32_t)(nt * 8 + (lane & 7)) * APITCH + kcol;
                    uint32_t kh0, kh1;
                    ldsm_x2(buf + off, kh0, kh1);
                    uint32_t bhK[2] = {kh0, kh1};
                    mma_f16(s[nt], qh[kb], bhK);
                }
            }

            bool diag = (jt == qt);
            #pragma unroll
            for (int nt = 0; nt < 8; nt++) {
                int colb = jt * 64 + nt * 8 + cql;
                #pragma unroll
                for (int q = 0; q < 4; q++) {
                    float v = s[nt][q] * 0.125f;
                    if (diag) {
                        int col = colb + (q & 1);
                        int row = r0g + (q >> 1) * 8;
                        if (col > row) v = -1e30f;
                    }
                    s[nt][q] = v;
                }
            }

            float mx0 = -1e30f, mx1 = -1e30f;
            #pragma unroll
            for (int nt = 0; nt < 8; nt++) {
                mx0 = fmaxf(mx0, fmaxf(s[nt][0], s[nt][1]));
                mx1 = fmaxf(mx1, fmaxf(s[nt][2], s[nt][3]));
            }
            mx0 = fmaxf(mx0, __shfl_xor_sync(0xffffffffu, mx0, 1));
            mx0 = fmaxf(mx0, __shfl_xor_sync(0xffffffffu, mx0, 2));
            mx1 = fmaxf(mx1, __shfl_xor_sync(0xffffffffu, mx1, 1));
            mx1 = fmaxf(mx1, __shfl_xor_sync(0xffffffffu, mx1, 2));
            float mn0 = fmaxf(mrow[0], mx0), mn1 = fmaxf(mrow[1], mx1);
            float sum0 = 0.f, sum1 = 0.f;
            #pragma unroll
            for (int nt = 0; nt < 8; nt++) {
                s[nt][0] = __expf(s[nt][0] - mn0);
                s[nt][1] = __expf(s[nt][1] - mn0);
                s[nt][2] = __expf(s[nt][2] - mn1);
                s[nt][3] = __expf(s[nt][3] - mn1);
                sum0 += s[nt][0] + s[nt][1];
                sum1 += s[nt][2] + s[nt][3];
            }
            sum0 += __shfl_xor_sync(0xffffffffu, sum0, 1);
            sum0 += __shfl_xor_sync(0xffffffffu, sum0, 2);
            sum1 += __shfl_xor_sync(0xffffffffu, sum1, 1);
            sum1 += __shfl_xor_sync(0xffffffffu, sum1, 2);
            float a0 = __expf(mrow[0] - mn0), a1 = __expf(mrow[1] - mn1);
            lrow[0] = lrow[0] * a0 + sum0;
            lrow[1] = lrow[1] * a1 + sum1;
            mrow[0] = mn0; mrow[1] = mn1;
            #pragma unroll
            for (int nt = 0; nt < 8; nt++) {
                oacc[nt][0] *= a0; oacc[nt][1] *= a0;
                oacc[nt][2] *= a1; oacc[nt][3] *= a1;
            }

            uint32_t vbase = buf + ATILE;
            #pragma unroll
            for (int kb = 0; kb < 4; kb++) {
                uint32_t ph[4];
                ph[0] = pack_h2(s[2*kb][0],   s[2*kb][1]);
                ph[1] = pack_h2(s[2*kb][2],   s[2*kb][3]);
                ph[2] = pack_h2(s[2*kb+1][0], s[2*kb+1][1]);
                ph[3] = pack_h2(s[2*kb+1][2], s[2*kb+1][3]);
                uint32_t vrow = (uint32_t)(kb * 16 + (lane & 15)) * APITCH;
                #pragma unroll
                for (int nt = 0; nt < 8; nt++) {
                    uint32_t off = vrow + nt * 16;
                    uint32_t vh0, vh1, vl0, vl1;
                    ldsm_x2t(vbase + off, vh0, vh1);
                    ldsm_x2t(vbase + ATILE + off, vl0, vl1);
                    uint32_t bhV[2] = {vh0, vh1}, blV[2] = {vl0, vl1};
                    mma_f16(oacc[nt], ph, bhV);
                    mma_f16(oacc[nt], ph, blV);
                }
            }

            CP_WAIT0();
            __syncthreads();
        }

        float li0 = 1.f / lrow[0], li1 = 1.f / lrow[1];
        size_t orow0 = (size_t)(b * TT + r0g) * DD + h * DHH;
        #pragma unroll
        for (int nt = 0; nt < 8; nt++) {
            int gc = nt * 8 + cql;
            *(uint32_t*)&o_hi[orow0 + gc] =
                pack_h2(oacc[nt][0] * li0, oacc[nt][1] * li0);
            *(uint32_t*)&o_hi[orow0 + 8 * DD + gc] =
                pack_h2(oacc[nt][2] * li1, oacc[nt][3] * li1);
        }
    }
}

// ---------------- launcher ---------------------------------------------------
extern "C" void kernel_launch(void* const* d_in, const int* in_sizes, int n_in,
                              void* d_out, int out_size)
{
    const int*   ids  = (const int*)  d_in[0];
    const float* tok  = (const float*)d_in[1];
    const float* pos  = (const float*)d_in[2];
    const float* ln1s = (const float*)d_in[3];
    const float* ln1b = (const float*)d_in[4];
    const float* Wqkv = (const float*)d_in[5];
    const float* Wout = (const float*)d_in[6];
    const float* ln2s = (const float*)d_in[7];
    const float* ln2b = (const float*)d_in[8];
    const float* W1   = (const float*)d_in[9];
    const float* W2   = (const float*)d_in[10];
    const float* lnfs = (const float*)d_in[11];
    const float* lnfb = (const float*)d_in[12];
    float* out = (float*)d_out;

    float *x;
    __half *h_hi, *qkv_hi, *qkv_lo, *o_hi, *a_hi;
    __half *wqT, *woT, *w1T, *w2T;
    cudaGetSymbolAddress((void**)&x,      g_x);
    cudaGetSymbolAddress((void**)&h_hi,   g_h_hi);
    cudaGetSymbolAddress((void**)&qkv_hi, g_qkv_hi);
    cudaGetSymbolAddress((void**)&qkv_lo, g_qkv_lo);
    cudaGetSymbolAddress((void**)&o_hi,   g_o_hi);
    cudaGetSymbolAddress((void**)&a_hi,   g_a_hi);
    cudaGetSymbolAddress((void**)&wqT,    g_WqkvT);
    cudaGetSymbolAddress((void**)&woT,    g_WoutT);
    cudaGetSymbolAddress((void**)&w1T,    g_W1T);
    cudaGetSymbolAddress((void**)&w2T,    g_W2T);

    cudaFuncSetAttribute(attn_mma,
                         cudaFuncAttributeMaxDynamicSharedMemorySize, ATTN_SMEM);
    cudaFuncSetAttribute(gemm_mma<1>,
                         cudaFuncAttributeMaxDynamicSharedMemorySize, GSM_TOTAL);
    cudaFuncSetAttribute(gemm_mma<2>,
                         cudaFuncAttributeMaxDynamicSharedMemorySize, GSM_TOTAL);
    cudaFuncSetAttribute(gemm_mma<3>,
                         cudaFuncAttributeMaxDynamicSharedMemorySize, GSM_TOTAL);

    // weight transpose + fp16 convert (4 launches, vectorized)
    dim3 tb(32, 8);
    twk<<<dim3(D3 / 128,   DD / 32,   LL), tb>>>(Wqkv, wqT, DD, D3);
    twk<<<dim3(DD / 128,   DD / 32,   LL), tb>>>(Wout, woT, DD, DD);
    twk<<<dim3(DFFF / 128, DD / 32,   LL), tb>>>(W1, w1T, DD, DFFF);
    twk<<<dim3(DD / 128,   DFFF / 32, LL), tb>>>(W2, w2T, DFFF, DD);

    // fused embed + layer-0 LN1 (hi only)
    embed_ln_kernel<<<MROWS / 8, 256>>>(ids, tok, pos, ln1s, ln1b, x, h_hi);

    for (int l = 0; l < LL; l++) {
        if (l > 0)
            ln_kernel<2><<<MROWS / 8, 256>>>(x, ln1s + (size_t)l * DD,
                                             ln1b + (size_t)l * DD,
                                             nullptr, h_hi);
        gemm_mma<3><<<dim3(D3 / 128, MROWS / 128), 256, GSM_TOTAL>>>(
            h_hi, wqT + (size_t)l * D3 * DD,
            nullptr, nullptr, qkv_hi, qkv_lo, MROWS, D3, DD);
        attn_mma<<<dim3(TT / 128, BB * HH), 128, ATTN_SMEM>>>(qkv_hi, qkv_lo, o_hi);
        gemm_mma<1><<<dim3(DD / 128, MROWS / 128), 256, GSM_TOTAL>>>(
            o_hi, woT + (size_t)l * DD * DD,
            x, x, nullptr, nullptr, MROWS, DD, DD);
        ln_kernel<2><<<MROWS / 8, 256>>>(x, ln2s + (size_t)l * DD,
                                         ln2b + (size_t)l * DD,
                                         nullptr, h_hi);
        gemm_mma<2><<<dim3(DFFF / 128, MROWS / 128), 256, GSM_TOTAL>>>(
            h_hi, w1T + (size_t)l * DFFF * DD,
            nullptr, nullptr, a_hi, nullptr, MROWS, DFFF, DD);
        gemm_mma<1><<<dim3(DD / 128, MROWS / 128), 256, GSM_TOTAL>>>(
            a_hi, w2T + (size_t)l * DD * DFFF,
            x, x, nullptr, nullptr, MROWS, DD, DFFF);
    }

    ln_kernel<0><<<MROWS / 8, 256>>>(x, lnfs, lnfb, out, nullptr);
}